// round 1
// baseline (speedup 1.0000x reference)
#include <cuda_runtime.h>
#include <cstdint>

#define B_ROWS   131072
#define TOT_ROWS 262144

// Scratch (sanctioned __device__ globals; no allocations anywhere).
__device__ float g_bufA[(size_t)TOT_ROWS * 512];
__device__ float g_bufB[(size_t)TOT_ROWS * 512];

// ---------------- helpers ----------------
static __device__ __forceinline__ unsigned long long pack2(float lo, float hi) {
    unsigned long long r;
    asm("mov.b64 %0, {%1,%2};" : "=l"(r) : "f"(lo), "f"(hi));
    return r;
}
static __device__ __forceinline__ void unpack2(unsigned long long v, float& lo, float& hi) {
    asm("mov.b64 {%0,%1}, %2;" : "=f"(lo), "=f"(hi) : "l"(v));
}
static __device__ __forceinline__ unsigned long long fma2(unsigned long long a,
                                                          unsigned long long b,
                                                          unsigned long long c) {
    unsigned long long d;
    asm("fma.rn.f32x2 %0, %1, %2, %3;" : "=l"(d) : "l"(a), "l"(b), "l"(c));
    return d;
}
static __device__ __forceinline__ void cp16(uint32_t dst, const void* src) {
    asm volatile("cp.async.cg.shared.global [%0], [%1], 16;" :: "r"(dst), "l"(src));
}
static __device__ __forceinline__ float gelu_f(float x) {
    // jax.nn.gelu(approximate=True): 0.5x(1+tanh(sqrt(2/pi)(x+0.044715x^3)))
    float u = 0.7978845608028654f * x * (1.0f + 0.044715f * x * x);
    return 0.5f * x * (1.0f + tanhf(u));
}

// ---------------- fused GEMM + bias (+gelu+LayerNorm) layer ----------------
// CTA: 32 rows x 512 cols, 256 threads, per-thread 8x8 microtile via f32x2.
// smem: W_s [32][512] (64KB) + A_d [32][68] duplicated-pair transposed A tile.
#define AD_STRIDE 68
#define SM_FLOATS (32*512 + 32*AD_STRIDE)

template<int K, bool ACT>
__global__ __launch_bounds__(256, 2)
void layer_kernel(const float* __restrict__ inA, const float* __restrict__ inB,
                  const float* __restrict__ W, const float* __restrict__ bias,
                  const float* __restrict__ lns, const float* __restrict__ lnb,
                  float* __restrict__ out)
{
    extern __shared__ float smem[];
    float* W_s = smem;             // [32][512]
    float* A_d = smem + 32 * 512;  // [32][AD_STRIDE], each a stored duplicated (a,a)

    const int t    = threadIdx.x;
    const int tcol = t & 63;       // 64 column groups
    const int trow = t >> 6;       // 4 row groups (8 rows each)
    const int row0 = blockIdx.x * 32;

    unsigned long long acc[8][4];
#pragma unroll
    for (int i = 0; i < 8; i++)
#pragma unroll
        for (int p = 0; p < 4; p++) acc[i][p] = 0ULL;

    // A-tile load assignment: thread -> (row ar, 4 consecutive k at ak)
    const int ar = t >> 3;
    const int ak = (t & 7) * 4;
    const int grow = row0 + ar;
    const float* asrc = (inB != nullptr && grow >= B_ROWS)
                        ? (inB + (size_t)(grow - B_ROWS) * K)
                        : (inA + (size_t)grow * K);

    uint32_t ws_base = (uint32_t)__cvta_generic_to_shared(W_s);

#pragma unroll 1
    for (int kc = 0; kc < K / 32; kc++) {
        // -- load W chunk [32][512] via cp.async (no register staging) --
#pragma unroll
        for (int i = 0; i < 16; i++) {
            int lin = i * 256 + t;
            int wr  = lin >> 7;
            int wc  = (lin & 127) * 4;
            cp16(ws_base + (uint32_t)(wr * 512 + wc) * 4u,
                 W + (size_t)(kc * 32 + wr) * 512 + wc);
        }
        asm volatile("cp.async.commit_group;");

        // -- load A chunk, store transposed + duplicated pairs --
        float4 av = *(const float4*)(asrc + kc * 32 + ak);
        *(unsigned long long*)&A_d[(ak + 0) * AD_STRIDE + 2 * ar] = pack2(av.x, av.x);
        *(unsigned long long*)&A_d[(ak + 1) * AD_STRIDE + 2 * ar] = pack2(av.y, av.y);
        *(unsigned long long*)&A_d[(ak + 2) * AD_STRIDE + 2 * ar] = pack2(av.z, av.z);
        *(unsigned long long*)&A_d[(ak + 3) * AD_STRIDE + 2 * ar] = pack2(av.w, av.w);

        asm volatile("cp.async.wait_group 0;");
        __syncthreads();

        // -- compute --
#pragma unroll 8
        for (int kk = 0; kk < 32; kk++) {
            const float* arow = &A_d[kk * AD_STRIDE + trow * 16];
            ulonglong2 aa0 = *(const ulonglong2*)(arow + 0);
            ulonglong2 aa1 = *(const ulonglong2*)(arow + 4);
            ulonglong2 aa2 = *(const ulonglong2*)(arow + 8);
            ulonglong2 aa3 = *(const ulonglong2*)(arow + 12);
            unsigned long long a2[8] = {aa0.x, aa0.y, aa1.x, aa1.y,
                                        aa2.x, aa2.y, aa3.x, aa3.y};
            float4 w0 = *(const float4*)&W_s[kk * 512 + tcol * 4];
            float4 w1 = *(const float4*)&W_s[kk * 512 + 256 + tcol * 4];
            unsigned long long wp[4];
            wp[0] = pack2(w0.x, w0.y); wp[1] = pack2(w0.z, w0.w);
            wp[2] = pack2(w1.x, w1.y); wp[3] = pack2(w1.z, w1.w);
#pragma unroll
            for (int i = 0; i < 8; i++)
#pragma unroll
                for (int p = 0; p < 4; p++)
                    acc[i][p] = fma2(a2[i], wp[p], acc[i][p]);
        }
        __syncthreads();
    }

    // ---------------- epilogue ----------------
    const int c0 = tcol * 4, c1 = 256 + tcol * 4;
    float4 bv0 = *(const float4*)&bias[c0];
    float4 bv1 = *(const float4*)&bias[c1];
    float bj[8] = {bv0.x, bv0.y, bv0.z, bv0.w, bv1.x, bv1.y, bv1.z, bv1.w};

    if constexpr (ACT) {
        float* E = smem;  // [32][520] gelu staging (smem free after final sync)
#pragma unroll
        for (int i = 0; i < 8; i++) {
            int r = trow * 8 + i;
            float v[8];
#pragma unroll
            for (int p = 0; p < 4; p++) {
                float lo, hi; unpack2(acc[i][p], lo, hi);
                v[p * 2] = lo; v[p * 2 + 1] = hi;
            }
#pragma unroll
            for (int j = 0; j < 8; j++) {
                int c = (j < 4) ? (c0 + j) : (c1 + j - 4);
                E[r * 520 + c] = gelu_f(v[j] + bj[j]);
            }
        }
        __syncthreads();

        // per-row LayerNorm: warp w handles rows 4w..4w+3
        const int wid = t >> 5, lane = t & 31;
#pragma unroll 1
        for (int rr = 0; rr < 4; rr++) {
            int r = wid * 4 + rr;
            float4 u[4];
            float s = 0.f, sq = 0.f;
#pragma unroll
            for (int q = 0; q < 4; q++) {
                u[q] = *(const float4*)&E[r * 520 + q * 128 + lane * 4];
                s  += (u[q].x + u[q].y) + (u[q].z + u[q].w);
                sq += u[q].x * u[q].x + u[q].y * u[q].y
                    + u[q].z * u[q].z + u[q].w * u[q].w;
            }
#pragma unroll
            for (int off = 16; off; off >>= 1) {
                s  += __shfl_xor_sync(0xffffffffu, s,  off);
                sq += __shfl_xor_sync(0xffffffffu, sq, off);
            }
            float m   = s * (1.0f / 512.0f);
            float var = fmaxf(sq * (1.0f / 512.0f) - m * m, 0.0f);
            float inv = rsqrtf(var + 1e-6f);
#pragma unroll
            for (int q = 0; q < 4; q++) {
                int c = q * 128 + lane * 4;
                float4 sc = *(const float4*)&lns[c];
                float4 bb = *(const float4*)&lnb[c];
                float4 o;
                o.x = (u[q].x - m) * inv * sc.x + bb.x;
                o.y = (u[q].y - m) * inv * sc.y + bb.y;
                o.z = (u[q].z - m) * inv * sc.z + bb.z;
                o.w = (u[q].w - m) * inv * sc.w + bb.w;
                *(float4*)&out[(size_t)(row0 + r) * 512 + c] = o;
            }
        }
    } else {
#pragma unroll
        for (int i = 0; i < 8; i++) {
            size_t r = (size_t)(row0 + trow * 8 + i);
            float4 o;
            unpack2(acc[i][0], o.x, o.y); unpack2(acc[i][1], o.z, o.w);
            o.x += bj[0]; o.y += bj[1]; o.z += bj[2]; o.w += bj[3];
            *(float4*)&out[r * 512 + c0] = o;
            unpack2(acc[i][2], o.x, o.y); unpack2(acc[i][3], o.z, o.w);
            o.x += bj[4]; o.y += bj[5]; o.z += bj[6]; o.w += bj[7];
            *(float4*)&out[r * 512 + c1] = o;
        }
    }
}

// ---------------- IQE head ----------------
// IQE component == length of union of intervals [x_i, y_i] with x_i < y_i.
// Invalid intervals -> degenerate points (x_i, x_i) (zero measure).
// Sort X asc and Y asc separately (same open-counter => same union), then
// union = sum_j Y[j] - max(X[j], Y[j-1]).  Payload-free FMNMX bitonic sorts.
template<int KK, int J>
static __device__ __forceinline__ void bstep(float (&v)[32]) {
#pragma unroll
    for (int i = 0; i < 32; i++) {
        int l = i ^ J;
        if (l > i) {
            bool up = ((i & KK) == 0);
            float a = v[i], b = v[l];
            float lo = fminf(a, b), hi = fmaxf(a, b);
            v[i] = up ? lo : hi;
            v[l] = up ? hi : lo;
        }
    }
}
static __device__ __forceinline__ void sort32(float (&v)[32]) {
    bstep<2, 1>(v);
    bstep<4, 2>(v);  bstep<4, 1>(v);
    bstep<8, 4>(v);  bstep<8, 2>(v);  bstep<8, 1>(v);
    bstep<16, 8>(v); bstep<16, 4>(v); bstep<16, 2>(v); bstep<16, 1>(v);
    bstep<32, 16>(v); bstep<32, 8>(v); bstep<32, 4>(v); bstep<32, 2>(v); bstep<32, 1>(v);
}

__global__ __launch_bounds__(256)
void iqe_kernel(const float* __restrict__ phi, const float* __restrict__ alpha_p,
                float* __restrict__ out)
{
    int gid  = blockIdx.x * 256 + threadIdx.x;   // one thread = one (row, component)
    int row  = gid >> 4;
    int comp = gid & 15;
    const float* xp = phi + (size_t)row * 512 + comp * 32;
    const float* yp = xp + (size_t)B_ROWS * 512;

    float X[32], Y[32];
#pragma unroll
    for (int q = 0; q < 8; q++) {
        float4 xv = *(const float4*)(xp + q * 4);
        float4 yv = *(const float4*)(yp + q * 4);
        X[q*4+0] = xv.x; Y[q*4+0] = fmaxf(xv.x, yv.x);
        X[q*4+1] = xv.y; Y[q*4+1] = fmaxf(xv.y, yv.y);
        X[q*4+2] = xv.z; Y[q*4+2] = fmaxf(xv.z, yv.z);
        X[q*4+3] = xv.w; Y[q*4+3] = fmaxf(xv.w, yv.w);
    }
    sort32(X);
    sort32(Y);

    float s = Y[0] - X[0];
    float prev = Y[0];
#pragma unroll
    for (int j = 1; j < 32; j++) {
        s += Y[j] - fmaxf(X[j], prev);
        prev = Y[j];
    }

    // reduce 16 components of this row (lanes [0..15] / [16..31] per row)
    float ssum = s, smax = s;
#pragma unroll
    for (int off = 8; off; off >>= 1) {
        ssum += __shfl_xor_sync(0xffffffffu, ssum, off);
        smax  = fmaxf(smax, __shfl_xor_sync(0xffffffffu, smax, off));
    }
    if (comp == 0) {
        float a = 1.0f / (1.0f + expf(-alpha_p[0]));
        out[row] = a * (ssum * (1.0f / 16.0f)) + (1.0f - a) * smax;
    }
}

// ---------------- launch ----------------
extern "C" void kernel_launch(void* const* d_in, const int* in_sizes, int n_in,
                              void* d_out, int out_size)
{
    const float* obs   = (const float*)d_in[0];
    const float* gls   = (const float*)d_in[1];
    const float* W0    = (const float*)d_in[2];
    const float* b0    = (const float*)d_in[3];
    const float* l0s   = (const float*)d_in[4];
    const float* l0b   = (const float*)d_in[5];
    const float* W1    = (const float*)d_in[6];
    const float* b1    = (const float*)d_in[7];
    const float* l1s   = (const float*)d_in[8];
    const float* l1b   = (const float*)d_in[9];
    const float* W2    = (const float*)d_in[10];
    const float* b2    = (const float*)d_in[11];
    const float* l2s   = (const float*)d_in[12];
    const float* l2b   = (const float*)d_in[13];
    const float* W3    = (const float*)d_in[14];
    const float* b3    = (const float*)d_in[15];
    const float* alpha = (const float*)d_in[16];

    float *bufA = nullptr, *bufB = nullptr;
    cudaGetSymbolAddress((void**)&bufA, g_bufA);
    cudaGetSymbolAddress((void**)&bufB, g_bufB);

    const size_t smem = SM_FLOATS * sizeof(float);  // ~72.5 KB
    cudaFuncSetAttribute(layer_kernel<64,  true >, cudaFuncAttributeMaxDynamicSharedMemorySize, (int)smem);
    cudaFuncSetAttribute(layer_kernel<512, true >, cudaFuncAttributeMaxDynamicSharedMemorySize, (int)smem);
    cudaFuncSetAttribute(layer_kernel<512, false>, cudaFuncAttributeMaxDynamicSharedMemorySize, (int)smem);

    dim3 grid(TOT_ROWS / 32), blk(256);
    layer_kernel<64,  true ><<<grid, blk, smem>>>(obs,  gls,     W0, b0, l0s, l0b, bufA);
    layer_kernel<512, true ><<<grid, blk, smem>>>(bufA, nullptr, W1, b1, l1s, l1b, bufB);
    layer_kernel<512, true ><<<grid, blk, smem>>>(bufB, nullptr, W2, b2, l2s, l2b, bufA);
    layer_kernel<512, false><<<grid, blk, smem>>>(bufA, nullptr, W3, b3, nullptr, nullptr, bufB);

    iqe_kernel<<<(B_ROWS * 16) / 256, 256>>>(bufB, alpha, (float*)d_out);
}

// round 3
// speedup vs baseline: 2.2475x; 2.2475x over previous
#include <cuda_runtime.h>
#include <cuda_bf16.h>
#include <cstdint>

#define B_ROWS   131072
#define TOT_ROWS 262144

// ---------------- scratch (device globals; no allocations) ----------------
__device__ __nv_bfloat16 g_a0hi[(size_t)TOT_ROWS * 64];
__device__ __nv_bfloat16 g_a0lo[(size_t)TOT_ROWS * 64];
__device__ __nv_bfloat16 g_hiA[(size_t)TOT_ROWS * 512];
__device__ __nv_bfloat16 g_loA[(size_t)TOT_ROWS * 512];
__device__ __nv_bfloat16 g_hiB[(size_t)TOT_ROWS * 512];
__device__ __nv_bfloat16 g_loB[(size_t)TOT_ROWS * 512];
__device__ float         g_f32[(size_t)TOT_ROWS * 512];
__device__ __nv_bfloat16 g_wthi[512 * 512];
__device__ __nv_bfloat16 g_wtlo[512 * 512];

// ---------------- PTX helpers ----------------
static __device__ __forceinline__ uint32_t smem_u32(const void* p) {
    uint32_t a;
    asm("{ .reg .u64 t; cvta.to.shared.u64 t, %1; cvt.u32.u64 %0, t; }" : "=r"(a) : "l"(p));
    return a;
}
static __device__ __forceinline__ void cp16(uint32_t dst, const void* src) {
    asm volatile("cp.async.cg.shared.global [%0], [%1], 16;" :: "r"(dst), "l"(src));
}
static __device__ __forceinline__ void ldm_x4(uint32_t (&r)[4], uint32_t addr) {
    asm volatile("ldmatrix.sync.aligned.m8n8.x4.shared.b16 {%0,%1,%2,%3}, [%4];"
                 : "=r"(r[0]), "=r"(r[1]), "=r"(r[2]), "=r"(r[3]) : "r"(addr));
}
static __device__ __forceinline__ void mma_bf16(float (&d)[4], const uint32_t (&a)[4],
                                                uint32_t b0, uint32_t b1) {
    asm volatile("mma.sync.aligned.m16n8k16.row.col.f32.bf16.bf16.f32 "
                 "{%0,%1,%2,%3}, {%4,%5,%6,%7}, {%8,%9}, {%0,%1,%2,%3};"
                 : "+f"(d[0]), "+f"(d[1]), "+f"(d[2]), "+f"(d[3])
                 : "r"(a[0]), "r"(a[1]), "r"(a[2]), "r"(a[3]), "r"(b0), "r"(b1));
}
static __device__ __forceinline__ float gelu_f(float x) {
    float u = 0.7978845608028654f * x * (1.0f + 0.044715f * x * x);
    return 0.5f * x * (1.0f + tanhf(u));
}
// conflict-free swizzled byte offset within a [rows][32 bf16 = 64B] tile
static __device__ __forceinline__ uint32_t swz(int row, int seg) {
    return (uint32_t)(row * 64 + ((seg ^ ((row >> 1) & 3)) << 4));
}

// ---------------- smem layout (double-buffered stages) ----------------
// stage st: A_hi @ st*73728, A_lo @ +4096, W_hi @ +8192, W_lo @ +40960
#define STAGE_BYTES 73728
#define SMEM_BYTES  (2 * STAGE_BYTES + 128)
static __device__ __forceinline__ uint32_t A_OFF(int st, int half) {
    return (uint32_t)(st * STAGE_BYTES + half * 4096);
}
static __device__ __forceinline__ uint32_t W_OFF(int st, int half) {
    return (uint32_t)(st * STAGE_BYTES + 8192 + half * 32768);
}

template<int KDIM>
static __device__ __forceinline__ void load_stage(
    int s, int row0, uint32_t sb, int tid,
    const __nv_bfloat16* __restrict__ Ahi, const __nv_bfloat16* __restrict__ Alo,
    const __nv_bfloat16* __restrict__ Whi, const __nv_bfloat16* __restrict__ Wlo)
{
    const int buf = s & 1;
    // W: 512 n-rows x 4 segs x 2 halves = 4096 chunks of 16B
#pragma unroll
    for (int i = 0; i < 16; i++) {
        int idx  = i * 256 + tid;
        int half = idx >> 11;
        int rem  = idx & 2047;
        int n    = rem >> 2;
        int sg   = rem & 3;
        const __nv_bfloat16* src = (half ? Wlo : Whi) + (size_t)n * KDIM + s * 32 + sg * 8;
        cp16(sb + W_OFF(buf, half) + swz(n, sg), src);
    }
    // A: 64 rows x 4 segs x 2 halves = 512 chunks
#pragma unroll
    for (int i = 0; i < 2; i++) {
        int idx  = i * 256 + tid;
        int half = idx >> 8;
        int rem  = idx & 255;
        int r    = rem >> 2;
        int sg   = rem & 3;
        const __nv_bfloat16* src = (half ? Alo : Ahi) + (size_t)(row0 + r) * KDIM + s * 32 + sg * 8;
        cp16(sb + A_OFF(buf, half) + swz(r, sg), src);
    }
    asm volatile("cp.async.commit_group;");
}

// ---------------- fused bf16x3 mma.sync GEMM layer ----------------
// CTA: 64 rows x 512 cols, 256 threads, warp grid 2(m) x 4(n), warp tile 32x128.
#define E_STRIDE 520

template<int KDIM, bool ACT>
__global__ __launch_bounds__(256, 1)
void gemm_kernel(const __nv_bfloat16* __restrict__ Ahi, const __nv_bfloat16* __restrict__ Alo,
                 const __nv_bfloat16* __restrict__ Whi, const __nv_bfloat16* __restrict__ Wlo,
                 const float* __restrict__ bias,
                 const float* __restrict__ lns, const float* __restrict__ lnb,
                 __nv_bfloat16* __restrict__ Ohi, __nv_bfloat16* __restrict__ Olo,
                 float* __restrict__ Of32)
{
    extern __shared__ char smraw[];
    char* smal = (char*)(((uintptr_t)smraw + 127) & ~(uintptr_t)127);
    const uint32_t sb = smem_u32(smal);
    float* E = (float*)smal;

    const int tid  = threadIdx.x;
    const int wid  = tid >> 5;
    const int lane = tid & 31;
    const int wm   = wid >> 2;       // 0..1
    const int wn   = wid & 3;        // 0..3
    const int row0 = blockIdx.x * 64;

    constexpr int NS = KDIM / 32;

    float acc[2][16][4];
#pragma unroll
    for (int mt = 0; mt < 2; mt++)
#pragma unroll
        for (int nt = 0; nt < 16; nt++)
#pragma unroll
            for (int j = 0; j < 4; j++) acc[mt][nt][j] = 0.f;

    load_stage<KDIM>(0, row0, sb, tid, Ahi, Alo, Whi, Wlo);
    if (NS > 1) load_stage<KDIM>(1, row0, sb, tid, Ahi, Alo, Whi, Wlo);

    const int arow_l = wm * 32 + (lane & 15);
    const int aseg_l = lane >> 4;
    const int brow_l = wn * 128 + (lane & 7) + ((lane >> 4) << 3);
    const int bseg_l = (lane >> 3) & 1;

#pragma unroll 1
    for (int s = 0; s < NS; s++) {
        if (s == NS - 1) asm volatile("cp.async.wait_group 0;");
        else             asm volatile("cp.async.wait_group 1;");
        __syncthreads();

        const int buf = s & 1;
        const uint32_t aBh = sb + A_OFF(buf, 0), aBl = sb + A_OFF(buf, 1);
        const uint32_t wBh = sb + W_OFF(buf, 0), wBl = sb + W_OFF(buf, 1);

#pragma unroll
        for (int h = 0; h < 2; h++) {
            uint32_t ah[2][4], al[2][4];
#pragma unroll
            for (int mt = 0; mt < 2; mt++) {
                int r  = arow_l + mt * 16;
                uint32_t off = swz(r, 2 * h + aseg_l);
                ldm_x4(ah[mt], aBh + off);
                ldm_x4(al[mt], aBl + off);
            }
#pragma unroll
            for (int p = 0; p < 8; p++) {
                int r = brow_l + p * 16;
                uint32_t off = swz(r, 2 * h + bseg_l);
                uint32_t bh[4], bl[4];
                ldm_x4(bh, wBh + off);
                ldm_x4(bl, wBl + off);
#pragma unroll
                for (int mt = 0; mt < 2; mt++) {
#pragma unroll
                    for (int q = 0; q < 2; q++) {
                        const int nt = 2 * p + q;
                        mma_bf16(acc[mt][nt], ah[mt], bh[2 * q], bh[2 * q + 1]);
                        mma_bf16(acc[mt][nt], ah[mt], bl[2 * q], bl[2 * q + 1]);
                        mma_bf16(acc[mt][nt], al[mt], bh[2 * q], bh[2 * q + 1]);
                    }
                }
            }
        }
        __syncthreads();
        if (s + 2 < NS) load_stage<KDIM>(s + 2, row0, sb, tid, Ahi, Alo, Whi, Wlo);
    }

    // ---------------- epilogue: stage to smem (bias [+gelu]) ----------------
    float2 bias2[16];
#pragma unroll
    for (int nt = 0; nt < 16; nt++)
        bias2[nt] = *(const float2*)(bias + wn * 128 + nt * 8 + 2 * (lane & 3));

#pragma unroll
    for (int mt = 0; mt < 2; mt++) {
#pragma unroll
        for (int dp = 0; dp < 2; dp++) {
            int row = wm * 32 + mt * 16 + dp * 8 + (lane >> 2);
#pragma unroll
            for (int nt = 0; nt < 16; nt++) {
                int col = wn * 128 + nt * 8 + 2 * (lane & 3);
                float v0 = acc[mt][nt][2 * dp + 0] + bias2[nt].x;
                float v1 = acc[mt][nt][2 * dp + 1] + bias2[nt].y;
                if (ACT) { v0 = gelu_f(v0); v1 = gelu_f(v1); }
                *(float2*)&E[row * E_STRIDE + col] = make_float2(v0, v1);
            }
        }
    }
    __syncthreads();

    if constexpr (ACT) {
        // per-row LayerNorm: warp w handles rows w*8 .. w*8+7
#pragma unroll 1
        for (int rr = 0; rr < 8; rr++) {
            int row = wid * 8 + rr;
            float4 u[4];
            float s = 0.f, sq = 0.f;
#pragma unroll
            for (int q = 0; q < 4; q++) {
                u[q] = *(const float4*)&E[row * E_STRIDE + q * 128 + lane * 4];
                s  += (u[q].x + u[q].y) + (u[q].z + u[q].w);
                sq += u[q].x * u[q].x + u[q].y * u[q].y
                    + u[q].z * u[q].z + u[q].w * u[q].w;
            }
#pragma unroll
            for (int off = 16; off; off >>= 1) {
                s  += __shfl_xor_sync(0xffffffffu, s,  off);
                sq += __shfl_xor_sync(0xffffffffu, sq, off);
            }
            float m   = s * (1.0f / 512.0f);
            float var = fmaxf(sq * (1.0f / 512.0f) - m * m, 0.0f);
            float inv = rsqrtf(var + 1e-6f);
            size_t gbase = (size_t)(row0 + row) * 512;
#pragma unroll
            for (int q = 0; q < 4; q++) {
                int c = q * 128 + lane * 4;
                float4 sc = *(const float4*)&lns[c];
                float4 bb = *(const float4*)&lnb[c];
                float o[4];
                o[0] = (u[q].x - m) * inv * sc.x + bb.x;
                o[1] = (u[q].y - m) * inv * sc.y + bb.y;
                o[2] = (u[q].z - m) * inv * sc.z + bb.z;
                o[3] = (u[q].w - m) * inv * sc.w + bb.w;
                __nv_bfloat16 hb[4], lb[4];
#pragma unroll
                for (int j = 0; j < 4; j++) {
                    __nv_bfloat16 hh = __float2bfloat16(o[j]);
                    hb[j] = hh;
                    lb[j] = __float2bfloat16(o[j] - __bfloat162float(hh));
                }
                *(uint2*)&Ohi[gbase + c] = *(const uint2*)hb;
                *(uint2*)&Olo[gbase + c] = *(const uint2*)lb;
            }
        }
    } else {
#pragma unroll 1
        for (int rr = 0; rr < 8; rr++) {
            int row = wid * 8 + rr;
            size_t gbase = (size_t)(row0 + row) * 512;
#pragma unroll
            for (int q = 0; q < 4; q++) {
                int c = q * 128 + lane * 4;
                *(float4*)&Of32[gbase + c] = *(const float4*)&E[row * E_STRIDE + c];
            }
        }
    }
}

// ---------------- input conversion / weight prep ----------------
__global__ void conv_in(const float* __restrict__ obs, const float* __restrict__ gls,
                        __nv_bfloat16* __restrict__ hi, __nv_bfloat16* __restrict__ lo)
{
    size_t i = (size_t)blockIdx.x * blockDim.x + threadIdx.x;
    size_t n = (size_t)TOT_ROWS * 64;
    if (i >= n) return;
    float v = (i < (size_t)B_ROWS * 64) ? obs[i] : gls[i - (size_t)B_ROWS * 64];
    __nv_bfloat16 h = __float2bfloat16(v);
    hi[i] = h;
    lo[i] = __float2bfloat16(v - __bfloat162float(h));
}

__global__ void wprep(const float* __restrict__ W, int K,
                      __nv_bfloat16* __restrict__ wthi, __nv_bfloat16* __restrict__ wtlo)
{
    int i = blockIdx.x * blockDim.x + threadIdx.x;   // over 512*K, Wt[n][k]
    if (i >= 512 * K) return;
    int n = i / K, k = i % K;
    float v = W[(size_t)k * 512 + n];
    __nv_bfloat16 h = __float2bfloat16(v);
    wthi[i] = h;
    wtlo[i] = __float2bfloat16(v - __bfloat162float(h));
}

// ---------------- IQE head (union-of-intervals formulation) ----------------
template<int KK, int J>
static __device__ __forceinline__ void bstep(float (&v)[32]) {
#pragma unroll
    for (int i = 0; i < 32; i++) {
        int l = i ^ J;
        if (l > i) {
            bool up = ((i & KK) == 0);
            float a = v[i], b = v[l];
            float lo = fminf(a, b), hi = fmaxf(a, b);
            v[i] = up ? lo : hi;
            v[l] = up ? hi : lo;
        }
    }
}
static __device__ __forceinline__ void sort32(float (&v)[32]) {
    bstep<2, 1>(v);
    bstep<4, 2>(v);  bstep<4, 1>(v);
    bstep<8, 4>(v);  bstep<8, 2>(v);  bstep<8, 1>(v);
    bstep<16, 8>(v); bstep<16, 4>(v); bstep<16, 2>(v); bstep<16, 1>(v);
    bstep<32, 16>(v); bstep<32, 8>(v); bstep<32, 4>(v); bstep<32, 2>(v); bstep<32, 1>(v);
}

__global__ __launch_bounds__(256)
void iqe_kernel(const float* __restrict__ phi, const float* __restrict__ alpha_p,
                float* __restrict__ out)
{
    int gid  = blockIdx.x * 256 + threadIdx.x;   // one thread = one (row, component)
    int row  = gid >> 4;
    int comp = gid & 15;
    const float* xp = phi + (size_t)row * 512 + comp * 32;
    const float* yp = xp + (size_t)B_ROWS * 512;

    float X[32], Y[32];
#pragma unroll
    for (int q = 0; q < 8; q++) {
        float4 xv = *(const float4*)(xp + q * 4);
        float4 yv = *(const float4*)(yp + q * 4);
        X[q*4+0] = xv.x; Y[q*4+0] = fmaxf(xv.x, yv.x);
        X[q*4+1] = xv.y; Y[q*4+1] = fmaxf(xv.y, yv.y);
        X[q*4+2] = xv.z; Y[q*4+2] = fmaxf(xv.z, yv.z);
        X[q*4+3] = xv.w; Y[q*4+3] = fmaxf(xv.w, yv.w);
    }
    sort32(X);
    sort32(Y);

    float s = Y[0] - X[0];
    float prev = Y[0];
#pragma unroll
    for (int j = 1; j < 32; j++) {
        s += Y[j] - fmaxf(X[j], prev);
        prev = Y[j];
    }
    float ssum = s, smax = s;
#pragma unroll
    for (int off = 8; off; off >>= 1) {
        ssum += __shfl_xor_sync(0xffffffffu, ssum, off);
        smax  = fmaxf(smax, __shfl_xor_sync(0xffffffffu, smax, off));
    }
    if (comp == 0) {
        float a = 1.0f / (1.0f + expf(-alpha_p[0]));
        out[row] = a * (ssum * (1.0f / 16.0f)) + (1.0f - a) * smax;
    }
}

// ---------------- launch ----------------
extern "C" void kernel_launch(void* const* d_in, const int* in_sizes, int n_in,
                              void* d_out, int out_size)
{
    const float* obs   = (const float*)d_in[0];
    const float* gls   = (const float*)d_in[1];
    const float* W0    = (const float*)d_in[2];
    const float* b0    = (const float*)d_in[3];
    const float* l0s   = (const float*)d_in[4];
    const float* l0b   = (const float*)d_in[5];
    const float* W1    = (const float*)d_in[6];
    const float* b1    = (const float*)d_in[7];
    const float* l1s   = (const float*)d_in[8];
    const float* l1b   = (const float*)d_in[9];
    const float* W2    = (const float*)d_in[10];
    const float* b2    = (const float*)d_in[11];
    const float* l2s   = (const float*)d_in[12];
    const float* l2b   = (const float*)d_in[13];
    const float* W3    = (const float*)d_in[14];
    const float* b3    = (const float*)d_in[15];
    const float* alpha = (const float*)d_in[16];

    __nv_bfloat16 *a0hi, *a0lo, *hiA, *loA, *hiB, *loB, *wthi, *wtlo;
    float *f32;
    cudaGetSymbolAddress((void**)&a0hi, g_a0hi);
    cudaGetSymbolAddress((void**)&a0lo, g_a0lo);
    cudaGetSymbolAddress((void**)&hiA,  g_hiA);
    cudaGetSymbolAddress((void**)&loA,  g_loA);
    cudaGetSymbolAddress((void**)&hiB,  g_hiB);
    cudaGetSymbolAddress((void**)&loB,  g_loB);
    cudaGetSymbolAddress((void**)&wthi, g_wthi);
    cudaGetSymbolAddress((void**)&wtlo, g_wtlo);
    cudaGetSymbolAddress((void**)&f32,  g_f32);

    cudaFuncSetAttribute(gemm_kernel<64,  true >, cudaFuncAttributeMaxDynamicSharedMemorySize, SMEM_BYTES);
    cudaFuncSetAttribute(gemm_kernel<512, true >, cudaFuncAttributeMaxDynamicSharedMemorySize, SMEM_BYTES);
    cudaFuncSetAttribute(gemm_kernel<512, false>, cudaFuncAttributeMaxDynamicSharedMemorySize, SMEM_BYTES);

    dim3 blk(256);
    dim3 grid(TOT_ROWS / 64);

    conv_in<<<(TOT_ROWS * 64 + 255) / 256, 256>>>(obs, gls, a0hi, a0lo);

    wprep<<<(512 * 64 + 255) / 256, 256>>>(W0, 64, wthi, wtlo);
    gemm_kernel<64,  true ><<<grid, blk, SMEM_BYTES>>>(a0hi, a0lo, wthi, wtlo, b0, l0s, l0b, hiA, loA, nullptr);

    wprep<<<(512 * 512 + 255) / 256, 256>>>(W1, 512, wthi, wtlo);
    gemm_kernel<512, true ><<<grid, blk, SMEM_BYTES>>>(hiA, loA, wthi, wtlo, b1, l1s, l1b, hiB, loB, nullptr);

    wprep<<<(512 * 512 + 255) / 256, 256>>>(W2, 512, wthi, wtlo);
    gemm_kernel<512, true ><<<grid, blk, SMEM_BYTES>>>(hiB, loB, wthi, wtlo, b2, l2s, l2b, hiA, loA, nullptr);

    wprep<<<(512 * 512 + 255) / 256, 256>>>(W3, 512, wthi, wtlo);
    gemm_kernel<512, false><<<grid, blk, SMEM_BYTES>>>(hiA, loA, wthi, wtlo, b3, nullptr, nullptr, nullptr, nullptr, f32);

    iqe_kernel<<<(B_ROWS * 16) / 256, 256>>>(f32, alpha, (float*)d_out);
}

// round 4
// speedup vs baseline: 2.3582x; 1.0492x over previous
#include <cuda_runtime.h>
#include <cuda_bf16.h>
#include <cstdint>

#define B_ROWS   131072
#define TOT_ROWS 262144

// ---------------- scratch (device globals; no allocations) ----------------
__device__ __nv_bfloat16 g_a0hi[(size_t)TOT_ROWS * 64];
__device__ __nv_bfloat16 g_a0lo[(size_t)TOT_ROWS * 64];
__device__ __nv_bfloat16 g_hiA[(size_t)TOT_ROWS * 512];
__device__ __nv_bfloat16 g_loA[(size_t)TOT_ROWS * 512];
__device__ __nv_bfloat16 g_hiB[(size_t)TOT_ROWS * 512];
__device__ __nv_bfloat16 g_loB[(size_t)TOT_ROWS * 512];
__device__ float         g_f32[(size_t)TOT_ROWS * 512];
__device__ __nv_bfloat16 g_wthi[512 * 512];
__device__ __nv_bfloat16 g_wtlo[512 * 512];
__device__ float4        g_statA[(size_t)TOT_ROWS * 4];   // 8 float2 partials per row
__device__ float4        g_statB[(size_t)TOT_ROWS * 4];
__device__ float         g_uvec[512];
__device__ float         g_cvec[512];

// ---------------- PTX helpers ----------------
static __device__ __forceinline__ uint32_t smem_u32(const void* p) {
    uint32_t a;
    asm("{ .reg .u64 t; cvta.to.shared.u64 t, %1; cvt.u32.u64 %0, t; }" : "=r"(a) : "l"(p));
    return a;
}
static __device__ __forceinline__ void cp16(uint32_t dst, const void* src) {
    asm volatile("cp.async.cg.shared.global [%0], [%1], 16;" :: "r"(dst), "l"(src));
}
static __device__ __forceinline__ void ldm_x4(uint32_t (&r)[4], uint32_t addr) {
    asm volatile("ldmatrix.sync.aligned.m8n8.x4.shared.b16 {%0,%1,%2,%3}, [%4];"
                 : "=r"(r[0]), "=r"(r[1]), "=r"(r[2]), "=r"(r[3]) : "r"(addr));
}
static __device__ __forceinline__ void mma_bf16(float (&d)[4], const uint32_t (&a)[4],
                                                uint32_t b0, uint32_t b1) {
    asm volatile("mma.sync.aligned.m16n8k16.row.col.f32.bf16.bf16.f32 "
                 "{%0,%1,%2,%3}, {%4,%5,%6,%7}, {%8,%9}, {%0,%1,%2,%3};"
                 : "+f"(d[0]), "+f"(d[1]), "+f"(d[2]), "+f"(d[3])
                 : "r"(a[0]), "r"(a[1]), "r"(a[2]), "r"(a[3]), "r"(b0), "r"(b1));
}
// gelu(x) = x * sigmoid(2 * sqrt(2/pi) * (x + 0.044715 x^3))   (tanh form)
static __device__ __forceinline__ float gelu_f(float x) {
    float u = 0.7978845608028654f * x * (1.0f + 0.044715f * x * x);
    return x / (1.0f + __expf(-2.0f * u));
}
static __device__ __forceinline__ uint32_t pk(__nv_bfloat16 a, __nv_bfloat16 b) {
    uint16_t ax = *(uint16_t*)&a, bx = *(uint16_t*)&b;
    return (uint32_t)ax | ((uint32_t)bx << 16);
}
// swizzled byte offset within a [rows][32 bf16 = 64B] tile (conflict-free ldmatrix)
static __device__ __forceinline__ uint32_t swz(int row, int seg) {
    return (uint32_t)(row * 64 + ((seg ^ ((row >> 1) & 3)) << 4));
}

// ---------------- smem layout: 4-stage ring ----------------
// stage st (48KB): A_hi @ st*49152 (16KB), A_lo @+16384, W_hi @+32768 (8KB), W_lo @+40960
#define STAGE_BYTES 49152
#define SMEM_BYTES  (4 * STAGE_BYTES + 128)

template<int KDIM>
static __device__ __forceinline__ void load_stage(
    int s, int row0, int col0, uint32_t sb, int tid,
    const __nv_bfloat16* __restrict__ Ahi, const __nv_bfloat16* __restrict__ Alo,
    const __nv_bfloat16* __restrict__ Whi, const __nv_bfloat16* __restrict__ Wlo)
{
    const uint32_t stb = sb + (uint32_t)(s & 3) * STAGE_BYTES;
    // A: 256 rows x 4 segs x 2 halves = 2048 chunks of 16B
#pragma unroll
    for (int i = 0; i < 8; i++) {
        int idx  = i * 256 + tid;
        int half = idx >> 10;
        int rem  = idx & 1023;
        int r    = rem >> 2;
        int sg   = rem & 3;
        const __nv_bfloat16* src = (half ? Alo : Ahi) + (size_t)(row0 + r) * KDIM + s * 32 + sg * 8;
        cp16(stb + (uint32_t)half * 16384u + swz(r, sg), src);
    }
    // W: 128 n-rows x 4 segs x 2 halves = 1024 chunks
#pragma unroll
    for (int i = 0; i < 4; i++) {
        int idx  = i * 256 + tid;
        int half = idx >> 9;
        int rem  = idx & 511;
        int n    = rem >> 2;
        int sg   = rem & 3;
        const __nv_bfloat16* src = (half ? Wlo : Whi) + (size_t)(col0 + n) * KDIM + s * 32 + sg * 8;
        cp16(stb + 32768u + (uint32_t)half * 8192u + swz(n, sg), src);
    }
    asm volatile("cp.async.commit_group;");
}

// ---------------- bf16x3 mma.sync GEMM with folded LayerNorm ----------------
// CTA: 256 rows x 128 cols, 256 threads, warp grid 4(m) x 2(n), warp tile 64x64.
// FOLD: input activation was raw gelu g; output = inv*(g@W'') - (m*inv)*u + c.
// ACT:  apply gelu, emit hi/lo bf16 + per-row partial (sum, sumsq) stats.
template<int KDIM, bool ACT, bool FOLD>
__global__ __launch_bounds__(256, 1)
void gemm_kernel(const __nv_bfloat16* __restrict__ Ahi, const __nv_bfloat16* __restrict__ Alo,
                 const __nv_bfloat16* __restrict__ Whi, const __nv_bfloat16* __restrict__ Wlo,
                 const float* __restrict__ uvec, const float* __restrict__ cvec,
                 const float4* __restrict__ statsIn, float2* __restrict__ statsOut,
                 __nv_bfloat16* __restrict__ Ohi, __nv_bfloat16* __restrict__ Olo,
                 float* __restrict__ Of32)
{
    extern __shared__ char smraw[];
    char* smal = (char*)(((uintptr_t)smraw + 127) & ~(uintptr_t)127);
    const uint32_t sb = smem_u32(smal);

    const int tid  = threadIdx.x;
    const int lane = tid & 31;
    const int wid  = tid >> 5;
    const int wm   = wid >> 1;                 // 0..3 -> rows wm*64
    const int wn   = wid & 1;                  // 0..1 -> cols wn*64
    const int rowTile = blockIdx.x >> 2;
    const int colcta  = blockIdx.x & 3;
    const int row0 = rowTile * 256;
    const int col0 = colcta * 128;

    constexpr int NS = KDIM / 32;
    constexpr int PF = NS < 3 ? NS : 3;

    float acc[4][8][4];
#pragma unroll
    for (int mt = 0; mt < 4; mt++)
#pragma unroll
        for (int nt = 0; nt < 8; nt++)
#pragma unroll
            for (int j = 0; j < 4; j++) acc[mt][nt][j] = 0.f;

#pragma unroll
    for (int s = 0; s < PF; s++)
        load_stage<KDIM>(s, row0, col0, sb, tid, Ahi, Alo, Whi, Wlo);

    const int ar   = lane & 15;
    const int aseg = lane >> 4;
    const int br   = (lane & 7) + ((lane >> 4) << 3);
    const int bseg = (lane >> 3) & 1;

#pragma unroll 1
    for (int s = 0; s < NS; s++) {
        if constexpr (PF - 1 == 2) asm volatile("cp.async.wait_group 2;");
        else                       asm volatile("cp.async.wait_group 1;");
        __syncthreads();

        // issue next loads first (targets buffer of stage s-1: all warps passed its compute)
        if (s + PF < NS) load_stage<KDIM>(s + PF, row0, col0, sb, tid, Ahi, Alo, Whi, Wlo);
        else             asm volatile("cp.async.commit_group;");

        const uint32_t stb = sb + (uint32_t)(s & 3) * STAGE_BYTES;
#pragma unroll
        for (int h = 0; h < 2; h++) {
            uint32_t ah[4][4], al[4][4];
#pragma unroll
            for (int mt = 0; mt < 4; mt++) {
                uint32_t off = swz(wm * 64 + mt * 16 + ar, 2 * h + aseg);
                ldm_x4(ah[mt], stb + off);
                ldm_x4(al[mt], stb + 16384u + off);
            }
#pragma unroll
            for (int p = 0; p < 4; p++) {
                uint32_t offb = swz(wn * 64 + p * 16 + br, 2 * h + bseg);
                uint32_t bh[4], bl[4];
                ldm_x4(bh, stb + 32768u + offb);
                ldm_x4(bl, stb + 40960u + offb);
#pragma unroll
                for (int mt = 0; mt < 4; mt++) {
#pragma unroll
                    for (int q = 0; q < 2; q++) {
                        const int nt = 2 * p + q;
                        mma_bf16(acc[mt][nt], ah[mt], bh[2 * q], bh[2 * q + 1]);
                        mma_bf16(acc[mt][nt], ah[mt], bl[2 * q], bl[2 * q + 1]);
                        mma_bf16(acc[mt][nt], al[mt], bh[2 * q], bh[2 * q + 1]);
                    }
                }
            }
        }
    }
    __syncthreads();   // release stage smem for epilogue arrays

    // ---------------- epilogue ----------------
    float* sInv = (float*)smal;        // [256]
    float* sMi  = sInv + 256;          // [256]
    float* sU   = sMi + 256;           // [128]
    float* sC   = sU + 128;            // [128]

    if constexpr (FOLD) {
        // combine 8 float2 partials of previous layer's gelu row
        const float4* sp = statsIn + (size_t)(row0 + tid) * 4;
        float4 v0 = sp[0], v1 = sp[1], v2 = sp[2], v3 = sp[3];
        float ss = (v0.x + v0.z) + (v1.x + v1.z) + (v2.x + v2.z) + (v3.x + v3.z);
        float sq = (v0.y + v0.w) + (v1.y + v1.w) + (v2.y + v2.w) + (v3.y + v3.w);
        float m   = ss * (1.0f / 512.0f);
        float var = fmaxf(sq * (1.0f / 512.0f) - m * m, 0.0f);
        float inv = rsqrtf(var + 1e-6f);
        sInv[tid] = inv;
        sMi[tid]  = m * inv;
    }
    if (tid < 128) {
        sU[tid] = FOLD ? uvec[col0 + tid] : 0.0f;
        sC[tid] = cvec[col0 + tid];
    }
    __syncthreads();

#pragma unroll
    for (int mt = 0; mt < 4; mt++) {
#pragma unroll
        for (int dp = 0; dp < 2; dp++) {
            const int rl   = wm * 64 + mt * 16 + dp * 8 + (lane >> 2);
            const size_t grow = (size_t)(row0 + rl);
            const float inv = FOLD ? sInv[rl] : 1.0f;
            const float mi  = FOLD ? sMi[rl]  : 0.0f;
            float gs = 0.f, gq = 0.f;
#pragma unroll
            for (int nt = 0; nt < 8; nt++) {
                const int cl = wn * 64 + nt * 8 + 2 * (lane & 3);
                float z0 = inv * acc[mt][nt][2 * dp + 0] - mi * sU[cl]     + sC[cl];
                float z1 = inv * acc[mt][nt][2 * dp + 1] - mi * sU[cl + 1] + sC[cl + 1];
                if constexpr (ACT) {
                    float g0 = gelu_f(z0), g1 = gelu_f(z1);
                    gs += g0 + g1;
                    gq += g0 * g0 + g1 * g1;
                    __nv_bfloat16 h0 = __float2bfloat16(g0);
                    __nv_bfloat16 h1 = __float2bfloat16(g1);
                    __nv_bfloat16 l0 = __float2bfloat16(g0 - __bfloat162float(h0));
                    __nv_bfloat16 l1 = __float2bfloat16(g1 - __bfloat162float(h1));
                    size_t doff = grow * 512 + col0 + cl;
                    *(uint32_t*)(Ohi + doff) = pk(h0, h1);
                    *(uint32_t*)(Olo + doff) = pk(l0, l1);
                } else {
                    *(float2*)(Of32 + grow * 512 + col0 + cl) = make_float2(z0, z1);
                }
            }
            if constexpr (ACT) {
                gs += __shfl_xor_sync(0xffffffffu, gs, 1);
                gs += __shfl_xor_sync(0xffffffffu, gs, 2);
                gq += __shfl_xor_sync(0xffffffffu, gq, 1);
                gq += __shfl_xor_sync(0xffffffffu, gq, 2);
                if ((lane & 3) == 0)
                    statsOut[grow * 8 + (size_t)(colcta * 2 + wn)] = make_float2(gs, gq);
            }
        }
    }
}

// ---------------- input conversion / weight & fold-vector prep ----------------
__global__ void conv_in(const float* __restrict__ obs, const float* __restrict__ gls,
                        __nv_bfloat16* __restrict__ hi, __nv_bfloat16* __restrict__ lo)
{
    size_t i = (size_t)blockIdx.x * blockDim.x + threadIdx.x;
    size_t n = (size_t)TOT_ROWS * 64;
    if (i >= n) return;
    float v = (i < (size_t)B_ROWS * 64) ? obs[i] : gls[i - (size_t)B_ROWS * 64];
    __nv_bfloat16 h = __float2bfloat16(v);
    hi[i] = h;
    lo[i] = __float2bfloat16(v - __bfloat162float(h));
}

// Wt''[n][k] = s[k] * W[k][n]  (s optional), split into hi/lo bf16
__global__ void wprep(const float* __restrict__ W, int K, const float* __restrict__ s,
                      __nv_bfloat16* __restrict__ wthi, __nv_bfloat16* __restrict__ wtlo)
{
    int i = blockIdx.x * blockDim.x + threadIdx.x;
    if (i >= 512 * K) return;
    int n = i / K, k = i % K;
    float v = W[(size_t)k * 512 + n];
    if (s) v *= s[k];
    __nv_bfloat16 h = __float2bfloat16(v);
    wthi[i] = h;
    wtlo[i] = __float2bfloat16(v - __bfloat162float(h));
}

// u[n] = sum_k s[k]*W[k][n];  c[n] = sum_k t[k]*W[k][n] + beta[n]
__global__ void ucprep(const float* __restrict__ W, const float* __restrict__ s,
                       const float* __restrict__ t, const float* __restrict__ beta,
                       float* __restrict__ u, float* __restrict__ c)
{
    __shared__ float ru[128], rc[128];
    int n = blockIdx.x;
    float us = 0.f, cs = 0.f;
    for (int k = threadIdx.x; k < 512; k += 128) {
        float w = W[(size_t)k * 512 + n];
        us += s[k] * w;
        cs += t[k] * w;
    }
    ru[threadIdx.x] = us; rc[threadIdx.x] = cs;
    __syncthreads();
    for (int off = 64; off; off >>= 1) {
        if (threadIdx.x < off) {
            ru[threadIdx.x] += ru[threadIdx.x + off];
            rc[threadIdx.x] += rc[threadIdx.x + off];
        }
        __syncthreads();
    }
    if (threadIdx.x == 0) { u[n] = ru[0]; c[n] = rc[0] + beta[n]; }
}

// ---------------- IQE head (union-of-intervals formulation) ----------------
template<int KK, int J>
static __device__ __forceinline__ void bstep(float (&v)[32]) {
#pragma unroll
    for (int i = 0; i < 32; i++) {
        int l = i ^ J;
        if (l > i) {
            bool up = ((i & KK) == 0);
            float a = v[i], b = v[l];
            float lo = fminf(a, b), hi = fmaxf(a, b);
            v[i] = up ? lo : hi;
            v[l] = up ? hi : lo;
        }
    }
}
static __device__ __forceinline__ void sort32(float (&v)[32]) {
    bstep<2, 1>(v);
    bstep<4, 2>(v);  bstep<4, 1>(v);
    bstep<8, 4>(v);  bstep<8, 2>(v);  bstep<8, 1>(v);
    bstep<16, 8>(v); bstep<16, 4>(v); bstep<16, 2>(v); bstep<16, 1>(v);
    bstep<32, 16>(v); bstep<32, 8>(v); bstep<32, 4>(v); bstep<32, 2>(v); bstep<32, 1>(v);
}

__global__ __launch_bounds__(256)
void iqe_kernel(const float* __restrict__ phi, const float* __restrict__ alpha_p,
                float* __restrict__ out)
{
    int gid  = blockIdx.x * 256 + threadIdx.x;   // one thread = one (row, component)
    int row  = gid >> 4;
    int comp = gid & 15;
    const float* xp = phi + (size_t)row * 512 + comp * 32;
    const float* yp = xp + (size_t)B_ROWS * 512;

    float X[32], Y[32];
#pragma unroll
    for (int q = 0; q < 8; q++) {
        float4 xv = *(const float4*)(xp + q * 4);
        float4 yv = *(const float4*)(yp + q * 4);
        X[q*4+0] = xv.x; Y[q*4+0] = fmaxf(xv.x, yv.x);
        X[q*4+1] = xv.y; Y[q*4+1] = fmaxf(xv.y, yv.y);
        X[q*4+2] = xv.z; Y[q*4+2] = fmaxf(xv.z, yv.z);
        X[q*4+3] = xv.w; Y[q*4+3] = fmaxf(xv.w, yv.w);
    }
    sort32(X);
    sort32(Y);

    float s = Y[0] - X[0];
    float prev = Y[0];
#pragma unroll
    for (int j = 1; j < 32; j++) {
        s += Y[j] - fmaxf(X[j], prev);
        prev = Y[j];
    }
    float ssum = s, smax = s;
#pragma unroll
    for (int off = 8; off; off >>= 1) {
        ssum += __shfl_xor_sync(0xffffffffu, ssum, off);
        smax  = fmaxf(smax, __shfl_xor_sync(0xffffffffu, smax, off));
    }
    if (comp == 0) {
        float a = 1.0f / (1.0f + expf(-alpha_p[0]));
        out[row] = a * (ssum * (1.0f / 16.0f)) + (1.0f - a) * smax;
    }
}

// ---------------- launch ----------------
extern "C" void kernel_launch(void* const* d_in, const int* in_sizes, int n_in,
                              void* d_out, int out_size)
{
    const float* obs   = (const float*)d_in[0];
    const float* gls   = (const float*)d_in[1];
    const float* W0    = (const float*)d_in[2];
    const float* b0    = (const float*)d_in[3];
    const float* l0s   = (const float*)d_in[4];
    const float* l0b   = (const float*)d_in[5];
    const float* W1    = (const float*)d_in[6];
    const float* b1    = (const float*)d_in[7];
    const float* l1s   = (const float*)d_in[8];
    const float* l1b   = (const float*)d_in[9];
    const float* W2    = (const float*)d_in[10];
    const float* b2    = (const float*)d_in[11];
    const float* l2s   = (const float*)d_in[12];
    const float* l2b   = (const float*)d_in[13];
    const float* W3    = (const float*)d_in[14];
    const float* b3    = (const float*)d_in[15];
    const float* alpha = (const float*)d_in[16];

    __nv_bfloat16 *a0hi, *a0lo, *hiA, *loA, *hiB, *loB, *wthi, *wtlo;
    float *f32, *uvec, *cvec;
    float4 *stA, *stB;
    cudaGetSymbolAddress((void**)&a0hi, g_a0hi);
    cudaGetSymbolAddress((void**)&a0lo, g_a0lo);
    cudaGetSymbolAddress((void**)&hiA,  g_hiA);
    cudaGetSymbolAddress((void**)&loA,  g_loA);
    cudaGetSymbolAddress((void**)&hiB,  g_hiB);
    cudaGetSymbolAddress((void**)&loB,  g_loB);
    cudaGetSymbolAddress((void**)&wthi, g_wthi);
    cudaGetSymbolAddress((void**)&wtlo, g_wtlo);
    cudaGetSymbolAddress((void**)&f32,  g_f32);
    cudaGetSymbolAddress((void**)&uvec, g_uvec);
    cudaGetSymbolAddress((void**)&cvec, g_cvec);
    cudaGetSymbolAddress((void**)&stA,  g_statA);
    cudaGetSymbolAddress((void**)&stB,  g_statB);

    cudaFuncSetAttribute(gemm_kernel<64,  true,  false>, cudaFuncAttributeMaxDynamicSharedMemorySize, SMEM_BYTES);
    cudaFuncSetAttribute(gemm_kernel<512, true,  true >, cudaFuncAttributeMaxDynamicSharedMemorySize, SMEM_BYTES);
    cudaFuncSetAttribute(gemm_kernel<512, false, true >, cudaFuncAttributeMaxDynamicSharedMemorySize, SMEM_BYTES);

    dim3 blk(256);
    dim3 grid((TOT_ROWS / 256) * 4);

    conv_in<<<(TOT_ROWS * 64 + 255) / 256, 256>>>(obs, gls, a0hi, a0lo);

    // L0: y = x@W0 + b0 (no fold), gelu + stats -> statA
    wprep<<<(512 * 64 + 255) / 256, 256>>>(W0, 64, nullptr, wthi, wtlo);
    gemm_kernel<64, true, false><<<grid, blk, SMEM_BYTES>>>(
        a0hi, a0lo, wthi, wtlo, nullptr, b0, nullptr, (float2*)stA, hiA, loA, nullptr);

    // L1: fold ln0 into W1
    wprep<<<(512 * 512 + 255) / 256, 256>>>(W1, 512, l0s, wthi, wtlo);
    ucprep<<<512, 128>>>(W1, l0s, l0b, b1, uvec, cvec);
    gemm_kernel<512, true, true><<<grid, blk, SMEM_BYTES>>>(
        hiA, loA, wthi, wtlo, uvec, cvec, stA, (float2*)stB, hiB, loB, nullptr);

    // L2: fold ln1 into W2
    wprep<<<(512 * 512 + 255) / 256, 256>>>(W2, 512, l1s, wthi, wtlo);
    ucprep<<<512, 128>>>(W2, l1s, l1b, b2, uvec, cvec);
    gemm_kernel<512, true, true><<<grid, blk, SMEM_BYTES>>>(
        hiB, loB, wthi, wtlo, uvec, cvec, stB, (float2*)stA, hiA, loA, nullptr);

    // L3: fold ln2 into W3, no activation, f32 out
    wprep<<<(512 * 512 + 255) / 256, 256>>>(W3, 512, l2s, wthi, wtlo);
    ucprep<<<512, 128>>>(W3, l2s, l2b, b3, uvec, cvec);
    gemm_kernel<512, false, true><<<grid, blk, SMEM_BYTES>>>(
        hiA, loA, wthi, wtlo, uvec, cvec, stA, nullptr, nullptr, nullptr, f32);

    iqe_kernel<<<(B_ROWS * 16) / 256, 256>>>(f32, alpha, (float*)d_out);
}

// round 5
// speedup vs baseline: 3.0546x; 1.2953x over previous
#include <cuda_runtime.h>
#include <cuda_fp16.h>
#include <cuda_bf16.h>
#include <cstdint>

#define B_ROWS   131072
#define TOT_ROWS 262144

// ---------------- scratch (device globals; no allocations) ----------------
__device__ __half  g_a0[(size_t)TOT_ROWS * 64];
__device__ __half  g_actA[(size_t)TOT_ROWS * 512];
__device__ __half  g_actB[(size_t)TOT_ROWS * 512];
__device__ float   g_f32[(size_t)TOT_ROWS * 512];
__device__ __half  g_wthi[512 * 512];
__device__ __half  g_wtlo[512 * 512];
__device__ float4  g_statA[(size_t)TOT_ROWS * 4];   // 8 float2 partials per row
__device__ float4  g_statB[(size_t)TOT_ROWS * 4];
__device__ float   g_uvec[512];
__device__ float   g_cvec[512];

// ---------------- PTX helpers ----------------
static __device__ __forceinline__ uint32_t smem_u32(const void* p) {
    uint32_t a;
    asm("{ .reg .u64 t; cvta.to.shared.u64 t, %1; cvt.u32.u64 %0, t; }" : "=r"(a) : "l"(p));
    return a;
}
static __device__ __forceinline__ void cp16(uint32_t dst, const void* src) {
    asm volatile("cp.async.cg.shared.global [%0], [%1], 16;" :: "r"(dst), "l"(src));
}
static __device__ __forceinline__ void ldm_x4(uint32_t (&r)[4], uint32_t addr) {
    asm volatile("ldmatrix.sync.aligned.m8n8.x4.shared.b16 {%0,%1,%2,%3}, [%4];"
                 : "=r"(r[0]), "=r"(r[1]), "=r"(r[2]), "=r"(r[3]) : "r"(addr));
}
static __device__ __forceinline__ void mma_f16(float (&d)[4], const uint32_t (&a)[4],
                                               uint32_t b0, uint32_t b1) {
    asm volatile("mma.sync.aligned.m16n8k16.row.col.f32.f16.f16.f32 "
                 "{%0,%1,%2,%3}, {%4,%5,%6,%7}, {%8,%9}, {%0,%1,%2,%3};"
                 : "+f"(d[0]), "+f"(d[1]), "+f"(d[2]), "+f"(d[3])
                 : "r"(a[0]), "r"(a[1]), "r"(a[2]), "r"(a[3]), "r"(b0), "r"(b1));
}
// gelu(x) = x * sigmoid(2 * sqrt(2/pi) * (x + 0.044715 x^3))   (tanh form)
static __device__ __forceinline__ float gelu_f(float x) {
    float u = 0.7978845608028654f * x * (1.0f + 0.044715f * x * x);
    return x / (1.0f + __expf(-2.0f * u));
}
// swizzled byte offset within a [rows][32 f16 = 64B] tile (conflict-free ldmatrix)
static __device__ __forceinline__ uint32_t swz(int row, int seg) {
    return (uint32_t)(row * 64 + ((seg ^ ((row >> 1) & 3)) << 4));
}

// ---------------- smem layout: 4-stage ring ----------------
// stage st (32KB): A @ st*32768 (16KB), W_hi @ +16384 (8KB), W_lo @ +24576 (8KB)
#define STAGE_BYTES 32768
#define SMEM_BYTES  (4 * STAGE_BYTES + 128)

template<int KDIM>
static __device__ __forceinline__ void load_stage(
    int s, int row0, int col0, uint32_t sb, int tid,
    const __half* __restrict__ Aact,
    const __half* __restrict__ Whi, const __half* __restrict__ Wlo)
{
    const uint32_t stb = sb + (uint32_t)(s & 3) * STAGE_BYTES;
    // A: 256 rows x 4 segs = 1024 chunks of 16B
#pragma unroll
    for (int i = 0; i < 4; i++) {
        int idx = i * 256 + tid;
        int r   = idx >> 2;
        int sg  = idx & 3;
        cp16(stb + swz(r, sg), Aact + (size_t)(row0 + r) * KDIM + s * 32 + sg * 8);
    }
    // W: 128 n-rows x 4 segs x 2 halves = 1024 chunks
#pragma unroll
    for (int i = 0; i < 4; i++) {
        int idx  = i * 256 + tid;
        int half = idx >> 9;
        int rem  = idx & 511;
        int n    = rem >> 2;
        int sg   = rem & 3;
        const __half* src = (half ? Wlo : Whi) + (size_t)(col0 + n) * KDIM + s * 32 + sg * 8;
        cp16(stb + 16384u + (uint32_t)half * 8192u + swz(n, sg), src);
    }
    asm volatile("cp.async.commit_group;");
}

// ---------------- fp16 2-MMA GEMM with folded LayerNorm ----------------
// CTA: 256 rows x 128 cols, 256 threads, warp grid 4(m) x 2(n), warp tile 64x64.
// Weights pre-split hi/lo fp16 (exact to 2^-22); activations single fp16.
// FOLD: input activation was raw gelu g; output = inv*(g@W'') - (m*inv)*u + c.
// ACT:  apply gelu, emit fp16 activation + per-row partial (sum, sumsq) stats.
template<int KDIM, bool ACT, bool FOLD>
__global__ __launch_bounds__(256, 1)
void gemm_kernel(const __half* __restrict__ Aact,
                 const __half* __restrict__ Whi, const __half* __restrict__ Wlo,
                 const float* __restrict__ uvec, const float* __restrict__ cvec,
                 const float4* __restrict__ statsIn, float2* __restrict__ statsOut,
                 __half* __restrict__ Oact, float* __restrict__ Of32)
{
    extern __shared__ char smraw[];
    char* smal = (char*)(((uintptr_t)smraw + 127) & ~(uintptr_t)127);
    const uint32_t sb = smem_u32(smal);

    const int tid  = threadIdx.x;
    const int lane = tid & 31;
    const int wid  = tid >> 5;
    const int wm   = wid >> 1;                 // 0..3 -> rows wm*64
    const int wn   = wid & 1;                  // 0..1 -> cols wn*64
    const int rowTile = blockIdx.x >> 2;
    const int colcta  = blockIdx.x & 3;
    const int row0 = rowTile * 256;
    const int col0 = colcta * 128;

    constexpr int NS = KDIM / 32;
    constexpr int PF = NS < 3 ? NS : 3;

    float acc[4][8][4];
#pragma unroll
    for (int mt = 0; mt < 4; mt++)
#pragma unroll
        for (int nt = 0; nt < 8; nt++)
#pragma unroll
            for (int j = 0; j < 4; j++) acc[mt][nt][j] = 0.f;

#pragma unroll
    for (int s = 0; s < PF; s++)
        load_stage<KDIM>(s, row0, col0, sb, tid, Aact, Whi, Wlo);

    const int ar   = lane & 15;
    const int aseg = lane >> 4;
    const int br   = (lane & 7) + ((lane >> 4) << 3);
    const int bseg = (lane >> 3) & 1;

#pragma unroll 1
    for (int s = 0; s < NS; s++) {
        if constexpr (PF - 1 == 2) asm volatile("cp.async.wait_group 2;");
        else                       asm volatile("cp.async.wait_group 1;");
        __syncthreads();

        // issue next loads first (targets buffer of stage s-1: all warps passed its compute)
        if (s + PF < NS) load_stage<KDIM>(s + PF, row0, col0, sb, tid, Aact, Whi, Wlo);
        else             asm volatile("cp.async.commit_group;");

        const uint32_t stb = sb + (uint32_t)(s & 3) * STAGE_BYTES;
#pragma unroll
        for (int h = 0; h < 2; h++) {
            uint32_t a[4][4];
#pragma unroll
            for (int mt = 0; mt < 4; mt++)
                ldm_x4(a[mt], stb + swz(wm * 64 + mt * 16 + ar, 2 * h + aseg));
#pragma unroll
            for (int p = 0; p < 4; p++) {
                uint32_t offb = swz(wn * 64 + p * 16 + br, 2 * h + bseg);
                uint32_t bh[4], bl[4];
                ldm_x4(bh, stb + 16384u + offb);
                ldm_x4(bl, stb + 24576u + offb);
                // term-major order: 8 independent MMAs between same-acc pairs
#pragma unroll
                for (int t = 0; t < 2; t++) {
#pragma unroll
                    for (int q = 0; q < 2; q++) {
#pragma unroll
                        for (int mt = 0; mt < 4; mt++) {
                            const uint32_t* b = t ? bl : bh;
                            mma_f16(acc[mt][2 * p + q], a[mt], b[2 * q], b[2 * q + 1]);
                        }
                    }
                }
            }
        }
    }
    __syncthreads();   // release stage smem for epilogue arrays

    // ---------------- epilogue ----------------
    float* sInv = (float*)smal;        // [256]
    float* sMi  = sInv + 256;          // [256]
    float* sU   = sMi + 256;           // [128]
    float* sC   = sU + 128;            // [128]

    if constexpr (FOLD) {
        // combine 8 float2 partials of previous layer's gelu row
        const float4* sp = statsIn + (size_t)(row0 + tid) * 4;
        float4 v0 = sp[0], v1 = sp[1], v2 = sp[2], v3 = sp[3];
        float ss = (v0.x + v0.z) + (v1.x + v1.z) + (v2.x + v2.z) + (v3.x + v3.z);
        float sq = (v0.y + v0.w) + (v1.y + v1.w) + (v2.y + v2.w) + (v3.y + v3.w);
        float m   = ss * (1.0f / 512.0f);
        float var = fmaxf(sq * (1.0f / 512.0f) - m * m, 0.0f);
        float inv = rsqrtf(var + 1e-6f);
        sInv[tid] = inv;
        sMi[tid]  = m * inv;
    }
    if (tid < 128) {
        sU[tid] = FOLD ? uvec[col0 + tid] : 0.0f;
        sC[tid] = cvec[col0 + tid];
    }
    __syncthreads();

#pragma unroll
    for (int mt = 0; mt < 4; mt++) {
#pragma unroll
        for (int dp = 0; dp < 2; dp++) {
            const int rl   = wm * 64 + mt * 16 + dp * 8 + (lane >> 2);
            const size_t grow = (size_t)(row0 + rl);
            const float inv = FOLD ? sInv[rl] : 1.0f;
            const float mi  = FOLD ? sMi[rl]  : 0.0f;
            float gs = 0.f, gq = 0.f;
#pragma unroll
            for (int nt = 0; nt < 8; nt++) {
                const int cl = wn * 64 + nt * 8 + 2 * (lane & 3);
                float z0 = inv * acc[mt][nt][2 * dp + 0] - mi * sU[cl]     + sC[cl];
                float z1 = inv * acc[mt][nt][2 * dp + 1] - mi * sU[cl + 1] + sC[cl + 1];
                if constexpr (ACT) {
                    float g0 = gelu_f(z0), g1 = gelu_f(z1);
                    gs += g0 + g1;
                    gq += g0 * g0 + g1 * g1;
                    __half2 hv = __floats2half2_rn(g0, g1);
                    *(__half2*)(Oact + grow * 512 + col0 + cl) = hv;
                } else {
                    *(float2*)(Of32 + grow * 512 + col0 + cl) = make_float2(z0, z1);
                }
            }
            if constexpr (ACT) {
                gs += __shfl_xor_sync(0xffffffffu, gs, 1);
                gs += __shfl_xor_sync(0xffffffffu, gs, 2);
                gq += __shfl_xor_sync(0xffffffffu, gq, 1);
                gq += __shfl_xor_sync(0xffffffffu, gq, 2);
                if ((lane & 3) == 0)
                    statsOut[grow * 8 + (size_t)(colcta * 2 + wn)] = make_float2(gs, gq);
            }
        }
    }
}

// ---------------- input conversion / weight & fold-vector prep ----------------
__global__ void conv_in(const float* __restrict__ obs, const float* __restrict__ gls,
                        __half* __restrict__ out)
{
    size_t i = (size_t)blockIdx.x * blockDim.x + threadIdx.x;
    size_t n = (size_t)TOT_ROWS * 64;
    if (i >= n) return;
    float v = (i < (size_t)B_ROWS * 64) ? obs[i] : gls[i - (size_t)B_ROWS * 64];
    out[i] = __float2half_rn(v);
}

// Wt''[n][k] = s[k] * W[k][n]  (s optional), split into hi/lo fp16
__global__ void wprep(const float* __restrict__ W, int K, const float* __restrict__ s,
                      __half* __restrict__ wthi, __half* __restrict__ wtlo)
{
    int i = blockIdx.x * blockDim.x + threadIdx.x;
    if (i >= 512 * K) return;
    int n = i / K, k = i % K;
    float v = W[(size_t)k * 512 + n];
    if (s) v *= s[k];
    __half h = __float2half_rn(v);
    wthi[i] = h;
    wtlo[i] = __float2half_rn(v - __half2float(h));
}

// u[n] = sum_k s[k]*W[k][n];  c[n] = sum_k t[k]*W[k][n] + beta[n]
__global__ void ucprep(const float* __restrict__ W, const float* __restrict__ s,
                       const float* __restrict__ t, const float* __restrict__ beta,
                       float* __restrict__ u, float* __restrict__ c)
{
    __shared__ float ru[128], rc[128];
    int n = blockIdx.x;
    float us = 0.f, cs = 0.f;
    for (int k = threadIdx.x; k < 512; k += 128) {
        float w = W[(size_t)k * 512 + n];
        us += s[k] * w;
        cs += t[k] * w;
    }
    ru[threadIdx.x] = us; rc[threadIdx.x] = cs;
    __syncthreads();
    for (int off = 64; off; off >>= 1) {
        if (threadIdx.x < off) {
            ru[threadIdx.x] += ru[threadIdx.x + off];
            rc[threadIdx.x] += rc[threadIdx.x + off];
        }
        __syncthreads();
    }
    if (threadIdx.x == 0) { u[n] = ru[0]; c[n] = rc[0] + beta[n]; }
}

// ---------------- IQE head (union-of-intervals formulation) ----------------
template<int KK, int J>
static __device__ __forceinline__ void bstep(float (&v)[32]) {
#pragma unroll
    for (int i = 0; i < 32; i++) {
        int l = i ^ J;
        if (l > i) {
            bool up = ((i & KK) == 0);
            float a = v[i], b = v[l];
            float lo = fminf(a, b), hi = fmaxf(a, b);
            v[i] = up ? lo : hi;
            v[l] = up ? hi : lo;
        }
    }
}
static __device__ __forceinline__ void sort32(float (&v)[32]) {
    bstep<2, 1>(v);
    bstep<4, 2>(v);  bstep<4, 1>(v);
    bstep<8, 4>(v);  bstep<8, 2>(v);  bstep<8, 1>(v);
    bstep<16, 8>(v); bstep<16, 4>(v); bstep<16, 2>(v); bstep<16, 1>(v);
    bstep<32, 16>(v); bstep<32, 8>(v); bstep<32, 4>(v); bstep<32, 2>(v); bstep<32, 1>(v);
}

__global__ __launch_bounds__(256)
void iqe_kernel(const float* __restrict__ phi, const float* __restrict__ alpha_p,
                float* __restrict__ out)
{
    int gid  = blockIdx.x * 256 + threadIdx.x;   // one thread = one (row, component)
    int row  = gid >> 4;
    int comp = gid & 15;
    const float* xp = phi + (size_t)row * 512 + comp * 32;
    const float* yp = xp + (size_t)B_ROWS * 512;

    float X[32], Y[32];
#pragma unroll
    for (int q = 0; q < 8; q++) {
        float4 xv = *(const float4*)(xp + q * 4);
        float4 yv = *(const float4*)(yp + q * 4);
        X[q*4+0] = xv.x; Y[q*4+0] = fmaxf(xv.x, yv.x);
        X[q*4+1] = xv.y; Y[q*4+1] = fmaxf(xv.y, yv.y);
        X[q*4+2] = xv.z; Y[q*4+2] = fmaxf(xv.z, yv.z);
        X[q*4+3] = xv.w; Y[q*4+3] = fmaxf(xv.w, yv.w);
    }
    sort32(X);
    sort32(Y);

    float s = Y[0] - X[0];
    float prev = Y[0];
#pragma unroll
    for (int j = 1; j < 32; j++) {
        s += Y[j] - fmaxf(X[j], prev);
        prev = Y[j];
    }
    float ssum = s, smax = s;
#pragma unroll
    for (int off = 8; off; off >>= 1) {
        ssum += __shfl_xor_sync(0xffffffffu, ssum, off);
        smax  = fmaxf(smax, __shfl_xor_sync(0xffffffffu, smax, off));
    }
    if (comp == 0) {
        float a = 1.0f / (1.0f + expf(-alpha_p[0]));
        out[row] = a * (ssum * (1.0f / 16.0f)) + (1.0f - a) * smax;
    }
}

// ---------------- launch ----------------
extern "C" void kernel_launch(void* const* d_in, const int* in_sizes, int n_in,
                              void* d_out, int out_size)
{
    const float* obs   = (const float*)d_in[0];
    const float* gls   = (const float*)d_in[1];
    const float* W0    = (const float*)d_in[2];
    const float* b0    = (const float*)d_in[3];
    const float* l0s   = (const float*)d_in[4];
    const float* l0b   = (const float*)d_in[5];
    const float* W1    = (const float*)d_in[6];
    const float* b1    = (const float*)d_in[7];
    const float* l1s   = (const float*)d_in[8];
    const float* l1b   = (const float*)d_in[9];
    const float* W2    = (const float*)d_in[10];
    const float* b2    = (const float*)d_in[11];
    const float* l2s   = (const float*)d_in[12];
    const float* l2b   = (const float*)d_in[13];
    const float* W3    = (const float*)d_in[14];
    const float* b3    = (const float*)d_in[15];
    const float* alpha = (const float*)d_in[16];

    __half *a0, *actA, *actB, *wthi, *wtlo;
    float *f32, *uvec, *cvec;
    float4 *stA, *stB;
    cudaGetSymbolAddress((void**)&a0,   g_a0);
    cudaGetSymbolAddress((void**)&actA, g_actA);
    cudaGetSymbolAddress((void**)&actB, g_actB);
    cudaGetSymbolAddress((void**)&wthi, g_wthi);
    cudaGetSymbolAddress((void**)&wtlo, g_wtlo);
    cudaGetSymbolAddress((void**)&f32,  g_f32);
    cudaGetSymbolAddress((void**)&uvec, g_uvec);
    cudaGetSymbolAddress((void**)&cvec, g_cvec);
    cudaGetSymbolAddress((void**)&stA,  g_statA);
    cudaGetSymbolAddress((void**)&stB,  g_statB);

    cudaFuncSetAttribute(gemm_kernel<64,  true,  false>, cudaFuncAttributeMaxDynamicSharedMemorySize, SMEM_BYTES);
    cudaFuncSetAttribute(gemm_kernel<512, true,  true >, cudaFuncAttributeMaxDynamicSharedMemorySize, SMEM_BYTES);
    cudaFuncSetAttribute(gemm_kernel<512, false, true >, cudaFuncAttributeMaxDynamicSharedMemorySize, SMEM_BYTES);

    dim3 blk(256);
    dim3 grid((TOT_ROWS / 256) * 4);

    conv_in<<<(TOT_ROWS * 64 + 255) / 256, 256>>>(obs, gls, a0);

    // L0: y = x@W0 + b0 (no fold), gelu + stats -> statA
    wprep<<<(512 * 64 + 255) / 256, 256>>>(W0, 64, nullptr, wthi, wtlo);
    gemm_kernel<64, true, false><<<grid, blk, SMEM_BYTES>>>(
        a0, wthi, wtlo, nullptr, b0, nullptr, (float2*)stA, actA, nullptr);

    // L1: fold ln0 into W1
    wprep<<<(512 * 512 + 255) / 256, 256>>>(W1, 512, l0s, wthi, wtlo);
    ucprep<<<512, 128>>>(W1, l0s, l0b, b1, uvec, cvec);
    gemm_kernel<512, true, true><<<grid, blk, SMEM_BYTES>>>(
        actA, wthi, wtlo, uvec, cvec, stA, (float2*)stB, actB, nullptr);

    // L2: fold ln1 into W2
    wprep<<<(512 * 512 + 255) / 256, 256>>>(W2, 512, l1s, wthi, wtlo);
    ucprep<<<512, 128>>>(W2, l1s, l1b, b2, uvec, cvec);
    gemm_kernel<512, true, true><<<grid, blk, SMEM_BYTES>>>(
        actB, wthi, wtlo, uvec, cvec, stB, (float2*)stA, actA, nullptr);

    // L3: fold ln2 into W3, no activation, f32 out
    wprep<<<(512 * 512 + 255) / 256, 256>>>(W3, 512, l2s, wthi, wtlo);
    ucprep<<<512, 128>>>(W3, l2s, l2b, b3, uvec, cvec);
    gemm_kernel<512, false, true><<<grid, blk, SMEM_BYTES>>>(
        actA, wthi, wtlo, uvec, cvec, stA, nullptr, nullptr, f32);

    iqe_kernel<<<(B_ROWS * 16) / 256, 256>>>(f32, alpha, (float*)d_out);
}

// round 6
// speedup vs baseline: 4.0551x; 1.3276x over previous
#include <cuda_runtime.h>
#include <cuda_fp16.h>
#include <cstdint>

#define B_ROWS   131072
#define TOT_ROWS 262144

// ---------------- scratch (device globals; no allocations) ----------------
__device__ __half  g_a0[(size_t)TOT_ROWS * 64];
__device__ __half  g_actA[(size_t)TOT_ROWS * 512];
__device__ __half  g_actB[(size_t)TOT_ROWS * 512];
__device__ float   g_f32[(size_t)TOT_ROWS * 512];
__device__ __half  g_wt[512 * 512];
__device__ float4  g_statA[(size_t)TOT_ROWS * 4];   // 8 float2 partials per row
__device__ float4  g_statB[(size_t)TOT_ROWS * 4];
__device__ float   g_uvec[512];
__device__ float   g_cvec[512];

// ---------------- PTX helpers ----------------
static __device__ __forceinline__ uint32_t smem_u32(const void* p) {
    uint32_t a;
    asm("{ .reg .u64 t; cvta.to.shared.u64 t, %1; cvt.u32.u64 %0, t; }" : "=r"(a) : "l"(p));
    return a;
}
static __device__ __forceinline__ void cp16(uint32_t dst, const void* src) {
    asm volatile("cp.async.cg.shared.global [%0], [%1], 16;" :: "r"(dst), "l"(src));
}
static __device__ __forceinline__ void ldm_x4(uint32_t (&r)[4], uint32_t addr) {
    asm volatile("ldmatrix.sync.aligned.m8n8.x4.shared.b16 {%0,%1,%2,%3}, [%4];"
                 : "=r"(r[0]), "=r"(r[1]), "=r"(r[2]), "=r"(r[3]) : "r"(addr));
}
static __device__ __forceinline__ void mma_f16(float (&d)[4], const uint32_t (&a)[4],
                                               uint32_t b0, uint32_t b1) {
    asm volatile("mma.sync.aligned.m16n8k16.row.col.f32.f16.f16.f32 "
                 "{%0,%1,%2,%3}, {%4,%5,%6,%7}, {%8,%9}, {%0,%1,%2,%3};"
                 : "+f"(d[0]), "+f"(d[1]), "+f"(d[2]), "+f"(d[3])
                 : "r"(a[0]), "r"(a[1]), "r"(a[2]), "r"(a[3]), "r"(b0), "r"(b1));
}
// gelu(x) = x * sigmoid(2 * sqrt(2/pi) * (x + 0.044715 x^3))   (tanh form)
static __device__ __forceinline__ float gelu_f(float x) {
    float u = 0.7978845608028654f * x * (1.0f + 0.044715f * x * x);
    return x / (1.0f + __expf(-2.0f * u));
}
// swizzled byte offset within a [rows][32 f16 = 64B] tile (conflict-free ldmatrix)
static __device__ __forceinline__ uint32_t swz(int row, int seg) {
    return (uint32_t)(row * 64 + ((seg ^ ((row >> 1) & 3)) << 4));
}

// ---------------- smem layout: 4-stage ring ----------------
// stage st (24KB): A @ st*24576 (16KB), W @ +16384 (8KB)
#define STAGE_BYTES 24576
#define SMEM_BYTES  (4 * STAGE_BYTES + 128)

template<int KDIM>
static __device__ __forceinline__ void load_stage(
    int s, int row0, int col0, uint32_t sb, int tid,
    const __half* __restrict__ Aact, const __half* __restrict__ Wt)
{
    const uint32_t stb = sb + (uint32_t)(s & 3) * STAGE_BYTES;
    // A: 256 rows x 4 segs = 1024 chunks of 16B
#pragma unroll
    for (int i = 0; i < 4; i++) {
        int idx = i * 256 + tid;
        int r   = idx >> 2;
        int sg  = idx & 3;
        cp16(stb + swz(r, sg), Aact + (size_t)(row0 + r) * KDIM + s * 32 + sg * 8);
    }
    // W: 128 n-rows x 4 segs = 512 chunks
#pragma unroll
    for (int i = 0; i < 2; i++) {
        int idx = i * 256 + tid;
        int n   = idx >> 2;
        int sg  = idx & 3;
        cp16(stb + 16384u + swz(n, sg), Wt + (size_t)(col0 + n) * KDIM + s * 32 + sg * 8);
    }
    asm volatile("cp.async.commit_group;");
}

// ---------------- fp16 single-MMA GEMM with folded LayerNorm ----------------
// CTA: 256 rows x 128 cols, 256 threads, warp grid 4(m) x 2(n), warp tile 64x64.
// Weights and activations in fp16 (rel quantization ~2^-11 each; end-to-end
// error budget measured 9e-5 with exact weights -> ~2e-4 expected here).
// FOLD: input activation was raw gelu g; output = inv*(g@W'') - (m*inv)*u + c.
// ACT:  apply gelu, emit fp16 activation + per-row partial (sum, sumsq) stats.
template<int KDIM, bool ACT, bool FOLD>
__global__ __launch_bounds__(256, 1)
void gemm_kernel(const __half* __restrict__ Aact, const __half* __restrict__ Wt,
                 const float* __restrict__ uvec, const float* __restrict__ cvec,
                 const float4* __restrict__ statsIn, float2* __restrict__ statsOut,
                 __half* __restrict__ Oact, float* __restrict__ Of32)
{
    extern __shared__ char smraw[];
    char* smal = (char*)(((uintptr_t)smraw + 127) & ~(uintptr_t)127);
    const uint32_t sb = smem_u32(smal);

    const int tid  = threadIdx.x;
    const int lane = tid & 31;
    const int wid  = tid >> 5;
    const int wm   = wid >> 1;                 // 0..3 -> rows wm*64
    const int wn   = wid & 1;                  // 0..1 -> cols wn*64
    const int rowTile = blockIdx.x >> 2;
    const int colcta  = blockIdx.x & 3;
    const int row0 = rowTile * 256;
    const int col0 = colcta * 128;

    constexpr int NS = KDIM / 32;
    constexpr int PF = NS < 3 ? NS : 3;

    float acc[4][8][4];
#pragma unroll
    for (int mt = 0; mt < 4; mt++)
#pragma unroll
        for (int nt = 0; nt < 8; nt++)
#pragma unroll
            for (int j = 0; j < 4; j++) acc[mt][nt][j] = 0.f;

#pragma unroll
    for (int s = 0; s < PF; s++)
        load_stage<KDIM>(s, row0, col0, sb, tid, Aact, Wt);

    const int ar   = lane & 15;
    const int aseg = lane >> 4;
    const int br   = (lane & 7) + ((lane >> 4) << 3);
    const int bseg = (lane >> 3) & 1;

#pragma unroll 1
    for (int s = 0; s < NS; s++) {
        if constexpr (PF - 1 == 2) asm volatile("cp.async.wait_group 2;");
        else                       asm volatile("cp.async.wait_group 1;");
        __syncthreads();

        // issue next loads first (targets buffer of stage s-1: all warps passed its compute)
        if (s + PF < NS) load_stage<KDIM>(s + PF, row0, col0, sb, tid, Aact, Wt);
        else             asm volatile("cp.async.commit_group;");

        const uint32_t stb = sb + (uint32_t)(s & 3) * STAGE_BYTES;
#pragma unroll
        for (int h = 0; h < 2; h++) {
            uint32_t a[4][4];
#pragma unroll
            for (int mt = 0; mt < 4; mt++)
                ldm_x4(a[mt], stb + swz(wm * 64 + mt * 16 + ar, 2 * h + aseg));
#pragma unroll
            for (int p = 0; p < 4; p++) {
                uint32_t bh[4];
                ldm_x4(bh, stb + 16384u + swz(wn * 64 + p * 16 + br, 2 * h + bseg));
                // 8 independent accumulators back-to-back
#pragma unroll
                for (int q = 0; q < 2; q++) {
#pragma unroll
                    for (int mt = 0; mt < 4; mt++)
                        mma_f16(acc[mt][2 * p + q], a[mt], bh[2 * q], bh[2 * q + 1]);
                }
            }
        }
    }
    __syncthreads();   // release stage smem for epilogue arrays

    // ---------------- epilogue ----------------
    float* sInv = (float*)smal;        // [256]
    float* sMi  = sInv + 256;          // [256]
    float* sU   = sMi + 256;           // [128]
    float* sC   = sU + 128;            // [128]

    if constexpr (FOLD) {
        // combine 8 float2 partials of previous layer's gelu row
        const float4* sp = statsIn + (size_t)(row0 + tid) * 4;
        float4 v0 = sp[0], v1 = sp[1], v2 = sp[2], v3 = sp[3];
        float ss = (v0.x + v0.z) + (v1.x + v1.z) + (v2.x + v2.z) + (v3.x + v3.z);
        float sq = (v0.y + v0.w) + (v1.y + v1.w) + (v2.y + v2.w) + (v3.y + v3.w);
        float m   = ss * (1.0f / 512.0f);
        float var = fmaxf(sq * (1.0f / 512.0f) - m * m, 0.0f);
        float inv = rsqrtf(var + 1e-6f);
        sInv[tid] = inv;
        sMi[tid]  = m * inv;
    }
    if (tid < 128) {
        sU[tid] = FOLD ? uvec[col0 + tid] : 0.0f;
        sC[tid] = cvec[col0 + tid];
    }
    __syncthreads();

#pragma unroll
    for (int mt = 0; mt < 4; mt++) {
#pragma unroll
        for (int dp = 0; dp < 2; dp++) {
            const int rl   = wm * 64 + mt * 16 + dp * 8 + (lane >> 2);
            const size_t grow = (size_t)(row0 + rl);
            const float inv = FOLD ? sInv[rl] : 1.0f;
            const float mi  = FOLD ? sMi[rl]  : 0.0f;
            float gs = 0.f, gq = 0.f;
#pragma unroll
            for (int nt = 0; nt < 8; nt++) {
                const int cl = wn * 64 + nt * 8 + 2 * (lane & 3);
                float z0 = inv * acc[mt][nt][2 * dp + 0] - mi * sU[cl]     + sC[cl];
                float z1 = inv * acc[mt][nt][2 * dp + 1] - mi * sU[cl + 1] + sC[cl + 1];
                if constexpr (ACT) {
                    float g0 = gelu_f(z0), g1 = gelu_f(z1);
                    gs += g0 + g1;
                    gq += g0 * g0 + g1 * g1;
                    __half2 hv = __floats2half2_rn(g0, g1);
                    *(__half2*)(Oact + grow * 512 + col0 + cl) = hv;
                } else {
                    *(float2*)(Of32 + grow * 512 + col0 + cl) = make_float2(z0, z1);
                }
            }
            if constexpr (ACT) {
                gs += __shfl_xor_sync(0xffffffffu, gs, 1);
                gs += __shfl_xor_sync(0xffffffffu, gs, 2);
                gq += __shfl_xor_sync(0xffffffffu, gq, 1);
                gq += __shfl_xor_sync(0xffffffffu, gq, 2);
                if ((lane & 3) == 0)
                    statsOut[grow * 8 + (size_t)(colcta * 2 + wn)] = make_float2(gs, gq);
            }
        }
    }
}

// ---------------- input conversion / weight & fold-vector prep ----------------
__global__ void conv_in(const float* __restrict__ obs, const float* __restrict__ gls,
                        __half* __restrict__ out)
{
    size_t i = (size_t)blockIdx.x * blockDim.x + threadIdx.x;
    size_t n = (size_t)TOT_ROWS * 64;
    if (i >= n) return;
    float v = (i < (size_t)B_ROWS * 64) ? obs[i] : gls[i - (size_t)B_ROWS * 64];
    out[i] = __float2half_rn(v);
}

// Wt''[n][k] = s[k] * W[k][n]  (s optional), fp16
__global__ void wprep(const float* __restrict__ W, int K, const float* __restrict__ s,
                      __half* __restrict__ wt)
{
    int i = blockIdx.x * blockDim.x + threadIdx.x;
    if (i >= 512 * K) return;
    int n = i / K, k = i % K;
    float v = W[(size_t)k * 512 + n];
    if (s) v *= s[k];
    wt[i] = __float2half_rn(v);
}

// u[n] = sum_k s[k]*W[k][n];  c[n] = sum_k t[k]*W[k][n] + beta[n]
__global__ void ucprep(const float* __restrict__ W, const float* __restrict__ s,
                       const float* __restrict__ t, const float* __restrict__ beta,
                       float* __restrict__ u, float* __restrict__ c)
{
    __shared__ float ru[128], rc[128];
    int n = blockIdx.x;
    float us = 0.f, cs = 0.f;
    for (int k = threadIdx.x; k < 512; k += 128) {
        float w = W[(size_t)k * 512 + n];
        us += s[k] * w;
        cs += t[k] * w;
    }
    ru[threadIdx.x] = us; rc[threadIdx.x] = cs;
    __syncthreads();
    for (int off = 64; off; off >>= 1) {
        if (threadIdx.x < off) {
            ru[threadIdx.x] += ru[threadIdx.x + off];
            rc[threadIdx.x] += rc[threadIdx.x + off];
        }
        __syncthreads();
    }
    if (threadIdx.x == 0) { u[n] = ru[0]; c[n] = rc[0] + beta[n]; }
}

// ---------------- IQE head (union-of-intervals formulation) ----------------
template<int KK, int J>
static __device__ __forceinline__ void bstep(float (&v)[32]) {
#pragma unroll
    for (int i = 0; i < 32; i++) {
        int l = i ^ J;
        if (l > i) {
            bool up = ((i & KK) == 0);
            float a = v[i], b = v[l];
            float lo = fminf(a, b), hi = fmaxf(a, b);
            v[i] = up ? lo : hi;
            v[l] = up ? hi : lo;
        }
    }
}
static __device__ __forceinline__ void sort32(float (&v)[32]) {
    bstep<2, 1>(v);
    bstep<4, 2>(v);  bstep<4, 1>(v);
    bstep<8, 4>(v);  bstep<8, 2>(v);  bstep<8, 1>(v);
    bstep<16, 8>(v); bstep<16, 4>(v); bstep<16, 2>(v); bstep<16, 1>(v);
    bstep<32, 16>(v); bstep<32, 8>(v); bstep<32, 4>(v); bstep<32, 2>(v); bstep<32, 1>(v);
}

__global__ __launch_bounds__(256)
void iqe_kernel(const float* __restrict__ phi, const float* __restrict__ alpha_p,
                float* __restrict__ out)
{
    int gid  = blockIdx.x * 256 + threadIdx.x;   // one thread = one (row, component)
    int row  = gid >> 4;
    int comp = gid & 15;
    const float* xp = phi + (size_t)row * 512 + comp * 32;
    const float* yp = xp + (size_t)B_ROWS * 512;

    float X[32], Y[32];
#pragma unroll
    for (int q = 0; q < 8; q++) {
        float4 xv = *(const float4*)(xp + q * 4);
        float4 yv = *(const float4*)(yp + q * 4);
        X[q*4+0] = xv.x; Y[q*4+0] = fmaxf(xv.x, yv.x);
        X[q*4+1] = xv.y; Y[q*4+1] = fmaxf(xv.y, yv.y);
        X[q*4+2] = xv.z; Y[q*4+2] = fmaxf(xv.z, yv.z);
        X[q*4+3] = xv.w; Y[q*4+3] = fmaxf(xv.w, yv.w);
    }
    sort32(X);
    sort32(Y);

    float s = Y[0] - X[0];
    float prev = Y[0];
#pragma unroll
    for (int j = 1; j < 32; j++) {
        s += Y[j] - fmaxf(X[j], prev);
        prev = Y[j];
    }
    float ssum = s, smax = s;
#pragma unroll
    for (int off = 8; off; off >>= 1) {
        ssum += __shfl_xor_sync(0xffffffffu, ssum, off);
        smax  = fmaxf(smax, __shfl_xor_sync(0xffffffffu, smax, off));
    }
    if (comp == 0) {
        float a = 1.0f / (1.0f + expf(-alpha_p[0]));
        out[row] = a * (ssum * (1.0f / 16.0f)) + (1.0f - a) * smax;
    }
}

// ---------------- launch ----------------
extern "C" void kernel_launch(void* const* d_in, const int* in_sizes, int n_in,
                              void* d_out, int out_size)
{
    const float* obs   = (const float*)d_in[0];
    const float* gls   = (const float*)d_in[1];
    const float* W0    = (const float*)d_in[2];
    const float* b0    = (const float*)d_in[3];
    const float* l0s   = (const float*)d_in[4];
    const float* l0b   = (const float*)d_in[5];
    const float* W1    = (const float*)d_in[6];
    const float* b1    = (const float*)d_in[7];
    const float* l1s   = (const float*)d_in[8];
    const float* l1b   = (const float*)d_in[9];
    const float* W2    = (const float*)d_in[10];
    const float* b2    = (const float*)d_in[11];
    const float* l2s   = (const float*)d_in[12];
    const float* l2b   = (const float*)d_in[13];
    const float* W3    = (const float*)d_in[14];
    const float* b3    = (const float*)d_in[15];
    const float* alpha = (const float*)d_in[16];

    __half *a0, *actA, *actB, *wt;
    float *f32, *uvec, *cvec;
    float4 *stA, *stB;
    cudaGetSymbolAddress((void**)&a0,   g_a0);
    cudaGetSymbolAddress((void**)&actA, g_actA);
    cudaGetSymbolAddress((void**)&actB, g_actB);
    cudaGetSymbolAddress((void**)&wt,   g_wt);
    cudaGetSymbolAddress((void**)&f32,  g_f32);
    cudaGetSymbolAddress((void**)&uvec, g_uvec);
    cudaGetSymbolAddress((void**)&cvec, g_cvec);
    cudaGetSymbolAddress((void**)&stA,  g_statA);
    cudaGetSymbolAddress((void**)&stB,  g_statB);

    cudaFuncSetAttribute(gemm_kernel<64,  true,  false>, cudaFuncAttributeMaxDynamicSharedMemorySize, SMEM_BYTES);
    cudaFuncSetAttribute(gemm_kernel<512, true,  true >, cudaFuncAttributeMaxDynamicSharedMemorySize, SMEM_BYTES);
    cudaFuncSetAttribute(gemm_kernel<512, false, true >, cudaFuncAttributeMaxDynamicSharedMemorySize, SMEM_BYTES);

    dim3 blk(256);
    dim3 grid((TOT_ROWS / 256) * 4);

    conv_in<<<(TOT_ROWS * 64 + 255) / 256, 256>>>(obs, gls, a0);

    // L0: y = x@W0 + b0 (no fold), gelu + stats -> statA
    wprep<<<(512 * 64 + 255) / 256, 256>>>(W0, 64, nullptr, wt);
    gemm_kernel<64, true, false><<<grid, blk, SMEM_BYTES>>>(
        a0, wt, nullptr, b0, nullptr, (float2*)stA, actA, nullptr);

    // L1: fold ln0 into W1
    ucprep<<<512, 128>>>(W1, l0s, l0b, b1, uvec, cvec);
    wprep<<<(512 * 512 + 255) / 256, 256>>>(W1, 512, l0s, wt);
    gemm_kernel<512, true, true><<<grid, blk, SMEM_BYTES>>>(
        actA, wt, uvec, cvec, stA, (float2*)stB, actB, nullptr);

    // L2: fold ln1 into W2
    ucprep<<<512, 128>>>(W2, l1s, l1b, b2, uvec, cvec);
    wprep<<<(512 * 512 + 255) / 256, 256>>>(W2, 512, l1s, wt);
    gemm_kernel<512, true, true><<<grid, blk, SMEM_BYTES>>>(
        actB, wt, uvec, cvec, stB, (float2*)stA, actA, nullptr);

    // L3: fold ln2 into W3, no activation, f32 out
    ucprep<<<512, 128>>>(W3, l2s, l2b, b3, uvec, cvec);
    wprep<<<(512 * 512 + 255) / 256, 256>>>(W3, 512, l2s, wt);
    gemm_kernel<512, false, true><<<grid, blk, SMEM_BYTES>>>(
        actA, wt, uvec, cvec, stA, nullptr, nullptr, f32);

    iqe_kernel<<<(B_ROWS * 16) / 256, 256>>>(f32, alpha, (float*)d_out);
}

// round 7
// speedup vs baseline: 5.0200x; 1.2380x over previous
#include <cuda_runtime.h>
#include <cuda_fp16.h>
#include <cstdint>

#define B_ROWS   131072
#define TOT_ROWS 262144

// ---------------- scratch (device globals; no allocations) ----------------
__device__ __half  g_a0[(size_t)TOT_ROWS * 64];
__device__ __half  g_actA[(size_t)TOT_ROWS * 512];
__device__ __half  g_actB[(size_t)TOT_ROWS * 512];
__device__ float   g_f32[(size_t)TOT_ROWS * 512];
__device__ __half  g_wt[512 * 512];
__device__ float4  g_statA[(size_t)TOT_ROWS * 8];   // 16 float2 partials per row
__device__ float4  g_statB[(size_t)TOT_ROWS * 8];
__device__ float   g_uvec[512];
__device__ float   g_cvec[512];

// ---------------- PTX helpers ----------------
static __device__ __forceinline__ uint32_t smem_u32(const void* p) {
    uint32_t a;
    asm("{ .reg .u64 t; cvta.to.shared.u64 t, %1; cvt.u32.u64 %0, t; }" : "=r"(a) : "l"(p));
    return a;
}
static __device__ __forceinline__ void cp16(uint32_t dst, const void* src) {
    asm volatile("cp.async.cg.shared.global [%0], [%1], 16;" :: "r"(dst), "l"(src));
}
static __device__ __forceinline__ void ldm_x4(uint32_t (&r)[4], uint32_t addr) {
    asm volatile("ldmatrix.sync.aligned.m8n8.x4.shared.b16 {%0,%1,%2,%3}, [%4];"
                 : "=r"(r[0]), "=r"(r[1]), "=r"(r[2]), "=r"(r[3]) : "r"(addr));
}
static __device__ __forceinline__ void mma_f16(float (&d)[4], const uint32_t (&a)[4],
                                               uint32_t b0, uint32_t b1) {
    asm volatile("mma.sync.aligned.m16n8k16.row.col.f32.f16.f16.f32 "
                 "{%0,%1,%2,%3}, {%4,%5,%6,%7}, {%8,%9}, {%0,%1,%2,%3};"
                 : "+f"(d[0]), "+f"(d[1]), "+f"(d[2]), "+f"(d[3])
                 : "r"(a[0]), "r"(a[1]), "r"(a[2]), "r"(a[3]), "r"(b0), "r"(b1));
}
// gelu(x) = x * sigmoid(2 * sqrt(2/pi) * (x + 0.044715 x^3))   (tanh form)
static __device__ __forceinline__ float gelu_f(float x) {
    float u = 0.7978845608028654f * x * (1.0f + 0.044715f * x * x);
    return x / (1.0f + __expf(-2.0f * u));
}
// swizzled byte offset within a [rows][32 f16 = 64B] tile (conflict-free ldmatrix)
static __device__ __forceinline__ uint32_t swz(int row, int seg) {
    return (uint32_t)(row * 64 + ((seg ^ ((row >> 1) & 3)) << 4));
}

// ---------------- smem layout: 4-stage ring ----------------
// stage st (16KB): A @ st*16384 (8KB: 128 rows x 64B), W @ +8192 (8KB)
#define STAGE_BYTES 16384
#define SMEM_BYTES  (4 * STAGE_BYTES + 128)

template<int KDIM>
static __device__ __forceinline__ void load_stage(
    int s, int row0, int col0, uint32_t sb, int tid,
    const __half* __restrict__ Aact, const __half* __restrict__ Wt)
{
    const uint32_t stb = sb + (uint32_t)(s & 3) * STAGE_BYTES;
    // A: 128 rows x 4 segs = 512 chunks of 16B
#pragma unroll
    for (int i = 0; i < 2; i++) {
        int idx = i * 256 + tid;
        int r   = idx >> 2;
        int sg  = idx & 3;
        cp16(stb + swz(r, sg), Aact + (size_t)(row0 + r) * KDIM + s * 32 + sg * 8);
    }
    // W: 128 n-rows x 4 segs = 512 chunks
#pragma unroll
    for (int i = 0; i < 2; i++) {
        int idx = i * 256 + tid;
        int n   = idx >> 2;
        int sg  = idx & 3;
        cp16(stb + 8192u + swz(n, sg), Wt + (size_t)(col0 + n) * KDIM + s * 32 + sg * 8);
    }
    asm volatile("cp.async.commit_group;");
}

// ---------------- fp16 single-MMA GEMM with folded LayerNorm ----------------
// CTA: 128 rows x 128 cols, 256 threads, warp grid 2(m) x 4(n), warp tile 64x32.
// 2 CTAs/SM (occ 2): one CTA's epilogue/barriers overlap the other's MMA stream.
// FOLD: input activation was raw gelu g; output = inv*(g@W'') - (m*inv)*u + c.
// ACT:  apply gelu, emit fp16 activation + per-row partial (sum, sumsq) stats.
template<int KDIM, bool ACT, bool FOLD>
__global__ __launch_bounds__(256, 2)
void gemm_kernel(const __half* __restrict__ Aact, const __half* __restrict__ Wt,
                 const float* __restrict__ uvec, const float* __restrict__ cvec,
                 const float4* __restrict__ statsIn, float2* __restrict__ statsOut,
                 __half* __restrict__ Oact, float* __restrict__ Of32)
{
    extern __shared__ char smraw[];
    char* smal = (char*)(((uintptr_t)smraw + 127) & ~(uintptr_t)127);
    const uint32_t sb = smem_u32(smal);

    const int tid  = threadIdx.x;
    const int lane = tid & 31;
    const int wid  = tid >> 5;
    const int wm   = wid >> 2;                 // 0..1 -> rows wm*64
    const int wn   = wid & 3;                  // 0..3 -> cols wn*32
    const int rowTile = blockIdx.x >> 2;
    const int colcta  = blockIdx.x & 3;
    const int row0 = rowTile * 128;
    const int col0 = colcta * 128;

    constexpr int NS = KDIM / 32;
    constexpr int PF = NS < 3 ? NS : 3;

    float acc[4][4][4];
#pragma unroll
    for (int mt = 0; mt < 4; mt++)
#pragma unroll
        for (int nt = 0; nt < 4; nt++)
#pragma unroll
            for (int j = 0; j < 4; j++) acc[mt][nt][j] = 0.f;

#pragma unroll
    for (int s = 0; s < PF; s++)
        load_stage<KDIM>(s, row0, col0, sb, tid, Aact, Wt);

    const int ar   = lane & 15;
    const int aseg = lane >> 4;
    const int br   = (lane & 7) + ((lane >> 4) << 3);
    const int bseg = (lane >> 3) & 1;

#pragma unroll 1
    for (int s = 0; s < NS; s++) {
        if constexpr (PF - 1 == 2) asm volatile("cp.async.wait_group 2;");
        else                       asm volatile("cp.async.wait_group 1;");
        __syncthreads();

        // issue next loads first (targets buffer of stage s-1: all warps passed its compute)
        if (s + PF < NS) load_stage<KDIM>(s + PF, row0, col0, sb, tid, Aact, Wt);
        else             asm volatile("cp.async.commit_group;");

        const uint32_t stb = sb + (uint32_t)(s & 3) * STAGE_BYTES;
#pragma unroll
        for (int h = 0; h < 2; h++) {
            uint32_t a[4][4];
#pragma unroll
            for (int mt = 0; mt < 4; mt++)
                ldm_x4(a[mt], stb + swz(wm * 64 + mt * 16 + ar, 2 * h + aseg));
#pragma unroll
            for (int p = 0; p < 2; p++) {
                uint32_t bh[4];
                ldm_x4(bh, stb + 8192u + swz(wn * 32 + p * 16 + br, 2 * h + bseg));
                // 8 independent accumulators back-to-back
#pragma unroll
                for (int q = 0; q < 2; q++) {
#pragma unroll
                    for (int mt = 0; mt < 4; mt++)
                        mma_f16(acc[mt][2 * p + q], a[mt], bh[2 * q], bh[2 * q + 1]);
                }
            }
        }
    }
    __syncthreads();   // release stage smem for epilogue arrays

    // ---------------- epilogue ----------------
    float* sInv = (float*)smal;        // [128]
    float* sMi  = sInv + 128;          // [128]
    float* sU   = sMi + 128;           // [128]
    float* sC   = sU + 128;            // [128]

    if constexpr (FOLD) {
        // combine 16 float2 partials of previous layer's gelu row
        if (tid < 128) {
            const float4* sp = statsIn + (size_t)(row0 + tid) * 8;
            float ss = 0.f, sq = 0.f;
#pragma unroll
            for (int i = 0; i < 8; i++) {
                float4 v = sp[i];
                ss += v.x + v.z;
                sq += v.y + v.w;
            }
            float m   = ss * (1.0f / 512.0f);
            float var = fmaxf(sq * (1.0f / 512.0f) - m * m, 0.0f);
            float inv = rsqrtf(var + 1e-6f);
            sInv[tid] = inv;
            sMi[tid]  = m * inv;
        }
    }
    if (tid >= 128) {
        sU[tid - 128] = FOLD ? uvec[col0 + tid - 128] : 0.0f;
        sC[tid - 128] = cvec[col0 + tid - 128];
    }
    __syncthreads();

#pragma unroll
    for (int mt = 0; mt < 4; mt++) {
#pragma unroll
        for (int dp = 0; dp < 2; dp++) {
            const int rl   = wm * 64 + mt * 16 + dp * 8 + (lane >> 2);
            const size_t grow = (size_t)(row0 + rl);
            const float inv = FOLD ? sInv[rl] : 1.0f;
            const float mi  = FOLD ? sMi[rl]  : 0.0f;
            float gs = 0.f, gq = 0.f;
#pragma unroll
            for (int nt = 0; nt < 4; nt++) {
                const int cl = wn * 32 + nt * 8 + 2 * (lane & 3);
                float z0 = inv * acc[mt][nt][2 * dp + 0] - mi * sU[cl]     + sC[cl];
                float z1 = inv * acc[mt][nt][2 * dp + 1] - mi * sU[cl + 1] + sC[cl + 1];
                if constexpr (ACT) {
                    float g0 = gelu_f(z0), g1 = gelu_f(z1);
                    gs += g0 + g1;
                    gq += g0 * g0 + g1 * g1;
                    __half2 hv = __floats2half2_rn(g0, g1);
                    *(__half2*)(Oact + grow * 512 + col0 + cl) = hv;
                } else {
                    *(float2*)(Of32 + grow * 512 + col0 + cl) = make_float2(z0, z1);
                }
            }
            if constexpr (ACT) {
                gs += __shfl_xor_sync(0xffffffffu, gs, 1);
                gs += __shfl_xor_sync(0xffffffffu, gs, 2);
                gq += __shfl_xor_sync(0xffffffffu, gq, 1);
                gq += __shfl_xor_sync(0xffffffffu, gq, 2);
                if ((lane & 3) == 0)
                    statsOut[grow * 16 + (size_t)(colcta * 4 + wn)] = make_float2(gs, gq);
            }
        }
    }
}

// ---------------- input conversion / weight & fold-vector prep ----------------
__global__ void conv_in(const float* __restrict__ obs, const float* __restrict__ gls,
                        __half* __restrict__ out)
{
    size_t i = (size_t)blockIdx.x * blockDim.x + threadIdx.x;
    size_t n = (size_t)TOT_ROWS * 64;
    if (i >= n) return;
    float v = (i < (size_t)B_ROWS * 64) ? obs[i] : gls[i - (size_t)B_ROWS * 64];
    out[i] = __float2half_rn(v);
}

// Wt''[n][k] = s[k] * W[k][n]  (s optional), fp16
__global__ void wprep(const float* __restrict__ W, int K, const float* __restrict__ s,
                      __half* __restrict__ wt)
{
    int i = blockIdx.x * blockDim.x + threadIdx.x;
    if (i >= 512 * K) return;
    int n = i / K, k = i % K;
    float v = W[(size_t)k * 512 + n];
    if (s) v *= s[k];
    wt[i] = __float2half_rn(v);
}

// u[n] = sum_k s[k]*W[k][n];  c[n] = sum_k t[k]*W[k][n] + beta[n]
__global__ void ucprep(const float* __restrict__ W, const float* __restrict__ s,
                       const float* __restrict__ t, const float* __restrict__ beta,
                       float* __restrict__ u, float* __restrict__ c)
{
    __shared__ float ru[128], rc[128];
    int n = blockIdx.x;
    float us = 0.f, cs = 0.f;
    for (int k = threadIdx.x; k < 512; k += 128) {
        float w = W[(size_t)k * 512 + n];
        us += s[k] * w;
        cs += t[k] * w;
    }
    ru[threadIdx.x] = us; rc[threadIdx.x] = cs;
    __syncthreads();
    for (int off = 64; off; off >>= 1) {
        if (threadIdx.x < off) {
            ru[threadIdx.x] += ru[threadIdx.x + off];
            rc[threadIdx.x] += rc[threadIdx.x + off];
        }
        __syncthreads();
    }
    if (threadIdx.x == 0) { u[n] = ru[0]; c[n] = rc[0] + beta[n]; }
}

// ---------------- IQE head (union-of-intervals formulation) ----------------
template<int KK, int J>
static __device__ __forceinline__ void bstep(float (&v)[32]) {
#pragma unroll
    for (int i = 0; i < 32; i++) {
        int l = i ^ J;
        if (l > i) {
            bool up = ((i & KK) == 0);
            float a = v[i], b = v[l];
            float lo = fminf(a, b), hi = fmaxf(a, b);
            v[i] = up ? lo : hi;
            v[l] = up ? hi : lo;
        }
    }
}
static __device__ __forceinline__ void sort32(float (&v)[32]) {
    bstep<2, 1>(v);
    bstep<4, 2>(v);  bstep<4, 1>(v);
    bstep<8, 4>(v);  bstep<8, 2>(v);  bstep<8, 1>(v);
    bstep<16, 8>(v); bstep<16, 4>(v); bstep<16, 2>(v); bstep<16, 1>(v);
    bstep<32, 16>(v); bstep<32, 8>(v); bstep<32, 4>(v); bstep<32, 2>(v); bstep<32, 1>(v);
}

__global__ __launch_bounds__(256)
void iqe_kernel(const float* __restrict__ phi, const float* __restrict__ alpha_p,
                float* __restrict__ out)
{
    int gid  = blockIdx.x * 256 + threadIdx.x;   // one thread = one (row, component)
    int row  = gid >> 4;
    int comp = gid & 15;
    const float* xp = phi + (size_t)row * 512 + comp * 32;
    const float* yp = xp + (size_t)B_ROWS * 512;

    float X[32], Y[32];
#pragma unroll
    for (int q = 0; q < 8; q++) {
        float4 xv = *(const float4*)(xp + q * 4);
        float4 yv = *(const float4*)(yp + q * 4);
        X[q*4+0] = xv.x; Y[q*4+0] = fmaxf(xv.x, yv.x);
        X[q*4+1] = xv.y; Y[q*4+1] = fmaxf(xv.y, yv.y);
        X[q*4+2] = xv.z; Y[q*4+2] = fmaxf(xv.z, yv.z);
        X[q*4+3] = xv.w; Y[q*4+3] = fmaxf(xv.w, yv.w);
    }
    sort32(X);
    sort32(Y);

    float s = Y[0] - X[0];
    float prev = Y[0];
#pragma unroll
    for (int j = 1; j < 32; j++) {
        s += Y[j] - fmaxf(X[j], prev);
        prev = Y[j];
    }
    float ssum = s, smax = s;
#pragma unroll
    for (int off = 8; off; off >>= 1) {
        ssum += __shfl_xor_sync(0xffffffffu, ssum, off);
        smax  = fmaxf(smax, __shfl_xor_sync(0xffffffffu, smax, off));
    }
    if (comp == 0) {
        float a = 1.0f / (1.0f + expf(-alpha_p[0]));
        out[row] = a * (ssum * (1.0f / 16.0f)) + (1.0f - a) * smax;
    }
}

// ---------------- launch ----------------
extern "C" void kernel_launch(void* const* d_in, const int* in_sizes, int n_in,
                              void* d_out, int out_size)
{
    const float* obs   = (const float*)d_in[0];
    const float* gls   = (const float*)d_in[1];
    const float* W0    = (const float*)d_in[2];
    const float* b0    = (const float*)d_in[3];
    const float* l0s   = (const float*)d_in[4];
    const float* l0b   = (const float*)d_in[5];
    const float* W1    = (const float*)d_in[6];
    const float* b1    = (const float*)d_in[7];
    const float* l1s   = (const float*)d_in[8];
    const float* l1b   = (const float*)d_in[9];
    const float* W2    = (const float*)d_in[10];
    const float* b2    = (const float*)d_in[11];
    const float* l2s   = (const float*)d_in[12];
    const float* l2b   = (const float*)d_in[13];
    const float* W3    = (const float*)d_in[14];
    const float* b3    = (const float*)d_in[15];
    const float* alpha = (const float*)d_in[16];

    __half *a0, *actA, *actB, *wt;
    float *f32, *uvec, *cvec;
    float4 *stA, *stB;
    cudaGetSymbolAddress((void**)&a0,   g_a0);
    cudaGetSymbolAddress((void**)&actA, g_actA);
    cudaGetSymbolAddress((void**)&actB, g_actB);
    cudaGetSymbolAddress((void**)&wt,   g_wt);
    cudaGetSymbolAddress((void**)&f32,  g_f32);
    cudaGetSymbolAddress((void**)&uvec, g_uvec);
    cudaGetSymbolAddress((void**)&cvec, g_cvec);
    cudaGetSymbolAddress((void**)&stA,  g_statA);
    cudaGetSymbolAddress((void**)&stB,  g_statB);

    cudaFuncSetAttribute(gemm_kernel<64,  true,  false>, cudaFuncAttributeMaxDynamicSharedMemorySize, SMEM_BYTES);
    cudaFuncSetAttribute(gemm_kernel<512, true,  true >, cudaFuncAttributeMaxDynamicSharedMemorySize, SMEM_BYTES);
    cudaFuncSetAttribute(gemm_kernel<512, false, true >, cudaFuncAttributeMaxDynamicSharedMemorySize, SMEM_BYTES);

    dim3 blk(256);
    dim3 grid((TOT_ROWS / 128) * 4);

    conv_in<<<(TOT_ROWS * 64 + 255) / 256, 256>>>(obs, gls, a0);

    // L0: y = x@W0 + b0 (no fold), gelu + stats -> statA
    wprep<<<(512 * 64 + 255) / 256, 256>>>(W0, 64, nullptr, wt);
    gemm_kernel<64, true, false><<<grid, blk, SMEM_BYTES>>>(
        a0, wt, nullptr, b0, nullptr, (float2*)stA, actA, nullptr);

    // L1: fold ln0 into W1
    ucprep<<<512, 128>>>(W1, l0s, l0b, b1, uvec, cvec);
    wprep<<<(512 * 512 + 255) / 256, 256>>>(W1, 512, l0s, wt);
    gemm_kernel<512, true, true><<<grid, blk, SMEM_BYTES>>>(
        actA, wt, uvec, cvec, stA, (float2*)stB, actB, nullptr);

    // L2: fold ln1 into W2
    ucprep<<<512, 128>>>(W2, l1s, l1b, b2, uvec, cvec);
    wprep<<<(512 * 512 + 255) / 256, 256>>>(W2, 512, l1s, wt);
    gemm_kernel<512, true, true><<<grid, blk, SMEM_BYTES>>>(
        actB, wt, uvec, cvec, stB, (float2*)stA, actA, nullptr);

    // L3: fold ln2 into W3, no activation, f32 out
    ucprep<<<512, 128>>>(W3, l2s, l2b, b3, uvec, cvec);
    wprep<<<(512 * 512 + 255) / 256, 256>>>(W3, 512, l2s, wt);
    gemm_kernel<512, false, true><<<grid, blk, SMEM_BYTES>>>(
        actA, wt, uvec, cvec, stA, nullptr, nullptr, f32);

    iqe_kernel<<<(B_ROWS * 16) / 256, 256>>>(f32, alpha, (float*)d_out);
}

// round 8
// speedup vs baseline: 5.0403x; 1.0040x over previous
#include <cuda_runtime.h>
#include <cuda_fp16.h>
#include <cstdint>

#define B_ROWS   131072
#define TOT_ROWS 262144

// ---------------- scratch (device globals; no allocations) ----------------
__device__ __half  g_a0[(size_t)TOT_ROWS * 64];
__device__ __half  g_actA[(size_t)TOT_ROWS * 512];
__device__ __half  g_actB[(size_t)TOT_ROWS * 512];
__device__ __half  g_wt[512 * 512];
__device__ float4  g_statA[(size_t)TOT_ROWS * 8];   // 16 float2 partials per row
__device__ float4  g_statB[(size_t)TOT_ROWS * 8];
__device__ float   g_uvec[512];
__device__ float   g_cvec[512];
__device__ float2  g_iqePart[(size_t)B_ROWS * 4];   // (sum4, max4) per (row, colcta)

// ---------------- PTX helpers ----------------
static __device__ __forceinline__ uint32_t smem_u32(const void* p) {
    uint32_t a;
    asm("{ .reg .u64 t; cvta.to.shared.u64 t, %1; cvt.u32.u64 %0, t; }" : "=r"(a) : "l"(p));
    return a;
}
static __device__ __forceinline__ void cp16(uint32_t dst, const void* src) {
    asm volatile("cp.async.cg.shared.global [%0], [%1], 16;" :: "r"(dst), "l"(src));
}
static __device__ __forceinline__ void ldm_x4(uint32_t (&r)[4], uint32_t addr) {
    asm volatile("ldmatrix.sync.aligned.m8n8.x4.shared.b16 {%0,%1,%2,%3}, [%4];"
                 : "=r"(r[0]), "=r"(r[1]), "=r"(r[2]), "=r"(r[3]) : "r"(addr));
}
static __device__ __forceinline__ void mma_f16(float (&d)[4], const uint32_t (&a)[4],
                                               uint32_t b0, uint32_t b1) {
    asm volatile("mma.sync.aligned.m16n8k16.row.col.f32.f16.f16.f32 "
                 "{%0,%1,%2,%3}, {%4,%5,%6,%7}, {%8,%9}, {%0,%1,%2,%3};"
                 : "+f"(d[0]), "+f"(d[1]), "+f"(d[2]), "+f"(d[3])
                 : "r"(a[0]), "r"(a[1]), "r"(a[2]), "r"(a[3]), "r"(b0), "r"(b1));
}
// gelu(x) = x * sigmoid(2 * sqrt(2/pi) * (x + 0.044715 x^3))   (tanh form)
static __device__ __forceinline__ float gelu_f(float x) {
    float u = 0.7978845608028654f * x * (1.0f + 0.044715f * x * x);
    return x / (1.0f + __expf(-2.0f * u));
}
// swizzled byte offset within a [rows][32 f16 = 64B] tile (conflict-free ldmatrix)
static __device__ __forceinline__ uint32_t swz(int row, int seg) {
    return (uint32_t)(row * 64 + ((seg ^ ((row >> 1) & 3)) << 4));
}

// ---------------- smem layout ----------------
// mainloop: 4-stage ring, stage st (16KB): A @ st*16384 (8KB), W @ +8192 (8KB)
// paired epilogue: phi tile [128][132] f32 (67584B) + fold arrays (2KB)
#define STAGE_BYTES 16384
#define SMEM_BYTES  (67584 + 2048 + 128)

template<int KDIM, bool PAIRED>
static __device__ __forceinline__ void load_stage(
    int s, int row0, int col0, uint32_t sb, int tid,
    const __half* __restrict__ Aact, const __half* __restrict__ Wt)
{
    const uint32_t stb = sb + (uint32_t)(s & 3) * STAGE_BYTES;
    // A: 128 rows x 4 segs = 512 chunks of 16B
#pragma unroll
    for (int i = 0; i < 2; i++) {
        int idx = i * 256 + tid;
        int r   = idx >> 2;
        int sg  = idx & 3;
        size_t grow;
        if constexpr (PAIRED)
            grow = (r < 64) ? (size_t)(row0 + r)
                            : (size_t)B_ROWS + row0 + (r - 64);
        else
            grow = (size_t)(row0 + r);
        cp16(stb + swz(r, sg), Aact + grow * KDIM + s * 32 + sg * 8);
    }
    // W: 128 n-rows x 4 segs = 512 chunks
#pragma unroll
    for (int i = 0; i < 2; i++) {
        int idx = i * 256 + tid;
        int n   = idx >> 2;
        int sg  = idx & 3;
        cp16(stb + 8192u + swz(n, sg), Wt + (size_t)(col0 + n) * KDIM + s * 32 + sg * 8);
    }
    asm volatile("cp.async.commit_group;");
}

// ---------------- fp16 single-MMA GEMM with folded LayerNorm ----------------
// CTA: 128 rows x 128 cols, 256 threads, warp grid 2(m) x 4(n), warp tile 64x32.
// 2 CTAs/SM. FOLD: output = inv*(g@W'') - (m*inv)*u + c.
// ACT: gelu, fp16 activation out + per-row partial stats.
// PAIRED (final layer): local rows 0-63 = phi_s, 64-127 = phi_g of the SAME
// batch rows; epilogue computes IQE per (pair, component) in-CTA and emits
// one (sum4, max4) partial per (row, colcta). No phi ever touches DRAM.
template<int KDIM, bool ACT, bool FOLD, bool PAIRED>
__global__ __launch_bounds__(256, 2)
void gemm_kernel(const __half* __restrict__ Aact, const __half* __restrict__ Wt,
                 const float* __restrict__ uvec, const float* __restrict__ cvec,
                 const float4* __restrict__ statsIn, float2* __restrict__ statsOut,
                 __half* __restrict__ Oact, float2* __restrict__ iqePart)
{
    extern __shared__ char smraw[];
    char* smal = (char*)(((uintptr_t)smraw + 127) & ~(uintptr_t)127);
    const uint32_t sb = smem_u32(smal);

    const int tid  = threadIdx.x;
    const int lane = tid & 31;
    const int wid  = tid >> 5;
    const int wm   = wid >> 2;                 // 0..1 -> rows wm*64
    const int wn   = wid & 3;                  // 0..3 -> cols wn*32
    const int rowTile = blockIdx.x >> 2;
    const int colcta  = blockIdx.x & 3;
    const int row0 = PAIRED ? rowTile * 64 : rowTile * 128;
    const int col0 = colcta * 128;

    constexpr int NS = KDIM / 32;
    constexpr int PF = NS < 3 ? NS : 3;

    float acc[4][4][4];
#pragma unroll
    for (int mt = 0; mt < 4; mt++)
#pragma unroll
        for (int nt = 0; nt < 4; nt++)
#pragma unroll
            for (int j = 0; j < 4; j++) acc[mt][nt][j] = 0.f;

#pragma unroll
    for (int s = 0; s < PF; s++)
        load_stage<KDIM, PAIRED>(s, row0, col0, sb, tid, Aact, Wt);

    const int ar   = lane & 15;
    const int aseg = lane >> 4;
    const int br   = (lane & 7) + ((lane >> 4) << 3);
    const int bseg = (lane >> 3) & 1;

#pragma unroll 1
    for (int s = 0; s < NS; s++) {
        if constexpr (PF - 1 == 2) asm volatile("cp.async.wait_group 2;");
        else                       asm volatile("cp.async.wait_group 1;");
        __syncthreads();

        if (s + PF < NS) load_stage<KDIM, PAIRED>(s + PF, row0, col0, sb, tid, Aact, Wt);
        else             asm volatile("cp.async.commit_group;");

        const uint32_t stb = sb + (uint32_t)(s & 3) * STAGE_BYTES;
#pragma unroll
        for (int h = 0; h < 2; h++) {
            uint32_t a[4][4];
#pragma unroll
            for (int mt = 0; mt < 4; mt++)
                ldm_x4(a[mt], stb + swz(wm * 64 + mt * 16 + ar, 2 * h + aseg));
#pragma unroll
            for (int p = 0; p < 2; p++) {
                uint32_t bh[4];
                ldm_x4(bh, stb + 8192u + swz(wn * 32 + p * 16 + br, 2 * h + bseg));
#pragma unroll
                for (int q = 0; q < 2; q++) {
#pragma unroll
                    for (int mt = 0; mt < 4; mt++)
                        mma_f16(acc[mt][2 * p + q], a[mt], bh[2 * q], bh[2 * q + 1]);
                }
            }
        }
    }
    __syncthreads();   // release stage smem for epilogue

    // ---------------- epilogue ----------------
    // fold arrays live above the phi staging region (PAIRED) / at base (else)
    float* base = (float*)smal;
    float* sInv = PAIRED ? (float*)(smal + 67584) : base;
    float* sMi  = sInv + 128;
    float* sU   = sMi + 128;
    float* sC   = sU + 128;

    if constexpr (FOLD) {
        if (tid < 128) {
            size_t grow;
            if constexpr (PAIRED)
                grow = (tid < 64) ? (size_t)(row0 + tid)
                                  : (size_t)B_ROWS + row0 + (tid - 64);
            else
                grow = (size_t)(row0 + tid);
            const float4* sp = statsIn + grow * 8;
            float ss = 0.f, sq = 0.f;
#pragma unroll
            for (int i = 0; i < 8; i++) {
                float4 v = sp[i];
                ss += v.x + v.z;
                sq += v.y + v.w;
            }
            float m   = ss * (1.0f / 512.0f);
            float var = fmaxf(sq * (1.0f / 512.0f) - m * m, 0.0f);
            float inv = rsqrtf(var + 1e-6f);
            sInv[tid] = inv;
            sMi[tid]  = m * inv;
        }
    }
    if (tid >= 128) {
        sU[tid - 128] = FOLD ? uvec[col0 + tid - 128] : 0.0f;
        sC[tid - 128] = cvec[col0 + tid - 128];
    }
    __syncthreads();

#pragma unroll
    for (int mt = 0; mt < 4; mt++) {
#pragma unroll
        for (int dp = 0; dp < 2; dp++) {
            const int rl   = wm * 64 + mt * 16 + dp * 8 + (lane >> 2);
            const float inv = FOLD ? sInv[rl] : 1.0f;
            const float mi  = FOLD ? sMi[rl]  : 0.0f;
            float gs = 0.f, gq = 0.f;
            size_t grow = (size_t)(row0 + rl);   // used by ACT path only
#pragma unroll
            for (int nt = 0; nt < 4; nt++) {
                const int cl = wn * 32 + nt * 8 + 2 * (lane & 3);
                float z0 = inv * acc[mt][nt][2 * dp + 0] - mi * sU[cl]     + sC[cl];
                float z1 = inv * acc[mt][nt][2 * dp + 1] - mi * sU[cl + 1] + sC[cl + 1];
                if constexpr (PAIRED) {
                    // stage phi in [row][i][comp] layout: conflict-free comp gathers
                    base[rl * 132 + (cl & 31) * 4 + (cl >> 5)]       = z0;
                    base[rl * 132 + ((cl & 31) + 1) * 4 + (cl >> 5)] = z1;
                } else if constexpr (ACT) {
                    float g0 = gelu_f(z0), g1 = gelu_f(z1);
                    gs += g0 + g1;
                    gq += g0 * g0 + g1 * g1;
                    __half2 hv = __floats2half2_rn(g0, g1);
                    *(__half2*)(Oact + grow * 512 + col0 + cl) = hv;
                }
            }
            if constexpr (ACT && !PAIRED) {
                gs += __shfl_xor_sync(0xffffffffu, gs, 1);
                gs += __shfl_xor_sync(0xffffffffu, gs, 2);
                gq += __shfl_xor_sync(0xffffffffu, gq, 1);
                gq += __shfl_xor_sync(0xffffffffu, gq, 2);
                if ((lane & 3) == 0)
                    statsOut[grow * 16 + (size_t)(colcta * 4 + wn)] = make_float2(gs, gq);
            }
        }
    }

    if constexpr (PAIRED) {
        __syncthreads();
        // one thread per (pair row r, component comp); 4 comps = lanes sharing r
        const int r    = tid >> 2;
        const int comp = tid & 3;
        const float* xs = base + r * 132 + comp;
        const float* gs_ = base + (64 + r) * 132 + comp;
        float X[32], Y[32];
#pragma unroll
        for (int i = 0; i < 32; i++) {
            float xv = xs[i * 4];
            X[i] = xv;
            Y[i] = fmaxf(xv, gs_[i * 4]);
        }
        // bitonic sorts (defined below via forward decls)
        {
            // sort32 inlined through helper
            extern __device__ void __iqe_never_called__();  // (no-op anchor)
        }
        // sort X asc
        {
#define BSTEP(KK, J)                                                      \
            _Pragma("unroll")                                             \
            for (int i = 0; i < 32; i++) {                                \
                int l = i ^ (J);                                          \
                if (l > i) {                                              \
                    bool up = ((i & (KK)) == 0);                          \
                    float a_ = X[i], b_ = X[l];                           \
                    float lo = fminf(a_, b_), hi = fmaxf(a_, b_);         \
                    X[i] = up ? lo : hi;  X[l] = up ? hi : lo;            \
                }                                                         \
            }
            BSTEP(2,1) BSTEP(4,2) BSTEP(4,1) BSTEP(8,4) BSTEP(8,2) BSTEP(8,1)
            BSTEP(16,8) BSTEP(16,4) BSTEP(16,2) BSTEP(16,1)
            BSTEP(32,16) BSTEP(32,8) BSTEP(32,4) BSTEP(32,2) BSTEP(32,1)
#undef BSTEP
#define BSTEP(KK, J)                                                      \
            _Pragma("unroll")                                             \
            for (int i = 0; i < 32; i++) {                                \
                int l = i ^ (J);                                          \
                if (l > i) {                                              \
                    bool up = ((i & (KK)) == 0);                          \
                    float a_ = Y[i], b_ = Y[l];                           \
                    float lo = fminf(a_, b_), hi = fmaxf(a_, b_);         \
                    Y[i] = up ? lo : hi;  Y[l] = up ? hi : lo;            \
                }                                                         \
            }
            BSTEP(2,1) BSTEP(4,2) BSTEP(4,1) BSTEP(8,4) BSTEP(8,2) BSTEP(8,1)
            BSTEP(16,8) BSTEP(16,4) BSTEP(16,2) BSTEP(16,1)
            BSTEP(32,16) BSTEP(32,8) BSTEP(32,4) BSTEP(32,2) BSTEP(32,1)
#undef BSTEP
        }
        float s = Y[0] - X[0];
        float prev = Y[0];
#pragma unroll
        for (int j = 1; j < 32; j++) {
            s += Y[j] - fmaxf(X[j], prev);
            prev = Y[j];
        }
        // reduce the 4 components (lanes comp=0..3 share row r)
        float ssum = s, smax = s;
        ssum += __shfl_xor_sync(0xffffffffu, ssum, 1);
        smax  = fmaxf(smax, __shfl_xor_sync(0xffffffffu, smax, 1));
        ssum += __shfl_xor_sync(0xffffffffu, ssum, 2);
        smax  = fmaxf(smax, __shfl_xor_sync(0xffffffffu, smax, 2));
        if (comp == 0)
            iqePart[(size_t)(row0 + r) * 4 + colcta] = make_float2(ssum, smax);
    }
}

// ---------------- input conversion / weight & fold-vector prep ----------------
__global__ void conv_in(const float* __restrict__ obs, const float* __restrict__ gls,
                        __half* __restrict__ out)
{
    size_t i = (size_t)blockIdx.x * blockDim.x + threadIdx.x;
    size_t n = (size_t)TOT_ROWS * 64;
    if (i >= n) return;
    float v = (i < (size_t)B_ROWS * 64) ? obs[i] : gls[i - (size_t)B_ROWS * 64];
    out[i] = __float2half_rn(v);
}

// Wt''[n][k] = s[k] * W[k][n]  (s optional), fp16
__global__ void wprep(const float* __restrict__ W, int K, const float* __restrict__ s,
                      __half* __restrict__ wt)
{
    int i = blockIdx.x * blockDim.x + threadIdx.x;
    if (i >= 512 * K) return;
    int n = i / K, k = i % K;
    float v = W[(size_t)k * 512 + n];
    if (s) v *= s[k];
    wt[i] = __float2half_rn(v);
}

// u[n] = sum_k s[k]*W[k][n];  c[n] = sum_k t[k]*W[k][n] + beta[n]
__global__ void ucprep(const float* __restrict__ W, const float* __restrict__ s,
                       const float* __restrict__ t, const float* __restrict__ beta,
                       float* __restrict__ u, float* __restrict__ c)
{
    __shared__ float ru[128], rc[128];
    int n = blockIdx.x;
    float us = 0.f, cs = 0.f;
    for (int k = threadIdx.x; k < 512; k += 128) {
        float w = W[(size_t)k * 512 + n];
        us += s[k] * w;
        cs += t[k] * w;
    }
    ru[threadIdx.x] = us; rc[threadIdx.x] = cs;
    __syncthreads();
    for (int off = 64; off; off >>= 1) {
        if (threadIdx.x < off) {
            ru[threadIdx.x] += ru[threadIdx.x + off];
            rc[threadIdx.x] += rc[threadIdx.x + off];
        }
        __syncthreads();
    }
    if (threadIdx.x == 0) { u[n] = ru[0]; c[n] = rc[0] + beta[n]; }
}

// ---------------- final IQE combine ----------------
__global__ __launch_bounds__(256)
void iqe_combine(const float2* __restrict__ part, const float* __restrict__ alpha_p,
                 float* __restrict__ out)
{
    int r = blockIdx.x * 256 + threadIdx.x;
    if (r >= B_ROWS) return;
    float2 p0 = part[(size_t)r * 4 + 0];
    float2 p1 = part[(size_t)r * 4 + 1];
    float2 p2 = part[(size_t)r * 4 + 2];
    float2 p3 = part[(size_t)r * 4 + 3];
    float ssum = (p0.x + p1.x) + (p2.x + p3.x);
    float smax = fmaxf(fmaxf(p0.y, p1.y), fmaxf(p2.y, p3.y));
    float a = 1.0f / (1.0f + expf(-alpha_p[0]));
    out[r] = a * (ssum * (1.0f / 16.0f)) + (1.0f - a) * smax;
}

// ---------------- launch ----------------
extern "C" void kernel_launch(void* const* d_in, const int* in_sizes, int n_in,
                              void* d_out, int out_size)
{
    const float* obs   = (const float*)d_in[0];
    const float* gls   = (const float*)d_in[1];
    const float* W0    = (const float*)d_in[2];
    const float* b0    = (const float*)d_in[3];
    const float* l0s   = (const float*)d_in[4];
    const float* l0b   = (const float*)d_in[5];
    const float* W1    = (const float*)d_in[6];
    const float* b1    = (const float*)d_in[7];
    const float* l1s   = (const float*)d_in[8];
    const float* l1b   = (const float*)d_in[9];
    const float* W2    = (const float*)d_in[10];
    const float* b2    = (const float*)d_in[11];
    const float* l2s   = (const float*)d_in[12];
    const float* l2b   = (const float*)d_in[13];
    const float* W3    = (const float*)d_in[14];
    const float* b3    = (const float*)d_in[15];
    const float* alpha = (const float*)d_in[16];

    __half *a0, *actA, *actB, *wt;
    float *uvec, *cvec;
    float4 *stA, *stB;
    float2 *part;
    cudaGetSymbolAddress((void**)&a0,   g_a0);
    cudaGetSymbolAddress((void**)&actA, g_actA);
    cudaGetSymbolAddress((void**)&actB, g_actB);
    cudaGetSymbolAddress((void**)&wt,   g_wt);
    cudaGetSymbolAddress((void**)&uvec, g_uvec);
    cudaGetSymbolAddress((void**)&cvec, g_cvec);
    cudaGetSymbolAddress((void**)&stA,  g_statA);
    cudaGetSymbolAddress((void**)&stB,  g_statB);
    cudaGetSymbolAddress((void**)&part, g_iqePart);

    cudaFuncSetAttribute(gemm_kernel<64,  true,  false, false>, cudaFuncAttributeMaxDynamicSharedMemorySize, SMEM_BYTES);
    cudaFuncSetAttribute(gemm_kernel<512, true,  true,  false>, cudaFuncAttributeMaxDynamicSharedMemorySize, SMEM_BYTES);
    cudaFuncSetAttribute(gemm_kernel<512, false, true,  true >, cudaFuncAttributeMaxDynamicSharedMemorySize, SMEM_BYTES);

    dim3 blk(256);
    dim3 grid((TOT_ROWS / 128) * 4);

    conv_in<<<(TOT_ROWS * 64 + 255) / 256, 256>>>(obs, gls, a0);

    // L0: y = x@W0 + b0 (no fold), gelu + stats -> statA
    wprep<<<(512 * 64 + 255) / 256, 256>>>(W0, 64, nullptr, wt);
    gemm_kernel<64, true, false, false><<<grid, blk, SMEM_BYTES>>>(
        a0, wt, nullptr, b0, nullptr, (float2*)stA, actA, nullptr);

    // L1: fold ln0 into W1
    ucprep<<<512, 128>>>(W1, l0s, l0b, b1, uvec, cvec);
    wprep<<<(512 * 512 + 255) / 256, 256>>>(W1, 512, l0s, wt);
    gemm_kernel<512, true, true, false><<<grid, blk, SMEM_BYTES>>>(
        actA, wt, uvec, cvec, stA, (float2*)stB, actB, nullptr);

    // L2: fold ln1 into W2
    ucprep<<<512, 128>>>(W2, l1s, l1b, b2, uvec, cvec);
    wprep<<<(512 * 512 + 255) / 256, 256>>>(W2, 512, l1s, wt);
    gemm_kernel<512, true, true, false><<<grid, blk, SMEM_BYTES>>>(
        actB, wt, uvec, cvec, stB, (float2*)stA, actA, nullptr);

    // L3: fold ln2 into W3, paired rows, fused IQE -> partials
    ucprep<<<512, 128>>>(W3, l2s, l2b, b3, uvec, cvec);
    wprep<<<(512 * 512 + 255) / 256, 256>>>(W3, 512, l2s, wt);
    gemm_kernel<512, false, true, true><<<(B_ROWS / 64) * 4, blk, SMEM_BYTES>>>(
        actA, wt, uvec, cvec, stA, nullptr, nullptr, part);

    iqe_combine<<<(B_ROWS + 255) / 256, 256>>>(part, alpha, (float*)d_out);
}

// round 9
// speedup vs baseline: 5.0869x; 1.0093x over previous
#include <cuda_runtime.h>
#include <cuda_fp16.h>
#include <cstdint>

#define B_ROWS   131072
#define TOT_ROWS 262144

// ---------------- scratch (device globals; no allocations) ----------------
__device__ __half  g_a0[(size_t)TOT_ROWS * 64];
__device__ __half  g_actA[(size_t)TOT_ROWS * 512];
__device__ __half  g_actB[(size_t)TOT_ROWS * 512];
__device__ __half  g_wt0[512 * 64];
__device__ __half  g_wt1[512 * 512];
__device__ __half  g_wt2[512 * 512];
__device__ __half  g_wt3[512 * 512];
__device__ float4  g_statA[(size_t)TOT_ROWS * 8];   // 16 float2 partials per row
__device__ float4  g_statB[(size_t)TOT_ROWS * 8];
__device__ float   g_u1[512], g_c1[512];
__device__ float   g_u2[512], g_c2[512];
__device__ float   g_u3[512], g_c3[512];
__device__ float2  g_iqePart[(size_t)B_ROWS * 4];   // (sum4, max4) per (row, colcta)

// ---------------- PTX helpers ----------------
static __device__ __forceinline__ uint32_t smem_u32(const void* p) {
    uint32_t a;
    asm("{ .reg .u64 t; cvta.to.shared.u64 t, %1; cvt.u32.u64 %0, t; }" : "=r"(a) : "l"(p));
    return a;
}
static __device__ __forceinline__ void cp16(uint32_t dst, const void* src) {
    asm volatile("cp.async.cg.shared.global [%0], [%1], 16;" :: "r"(dst), "l"(src));
}
static __device__ __forceinline__ void ldm_x4(uint32_t (&r)[4], uint32_t addr) {
    asm volatile("ldmatrix.sync.aligned.m8n8.x4.shared.b16 {%0,%1,%2,%3}, [%4];"
                 : "=r"(r[0]), "=r"(r[1]), "=r"(r[2]), "=r"(r[3]) : "r"(addr));
}
static __device__ __forceinline__ void mma_f16(float (&d)[4], const uint32_t (&a)[4],
                                               uint32_t b0, uint32_t b1) {
    asm volatile("mma.sync.aligned.m16n8k16.row.col.f32.f16.f16.f32 "
                 "{%0,%1,%2,%3}, {%4,%5,%6,%7}, {%8,%9}, {%0,%1,%2,%3};"
                 : "+f"(d[0]), "+f"(d[1]), "+f"(d[2]), "+f"(d[3])
                 : "r"(a[0]), "r"(a[1]), "r"(a[2]), "r"(a[3]), "r"(b0), "r"(b1));
}
// gelu(x) = x * sigmoid(2 * sqrt(2/pi) * (x + 0.044715 x^3))   (tanh form)
static __device__ __forceinline__ float gelu_f(float x) {
    float u = 0.7978845608028654f * x * (1.0f + 0.044715f * x * x);
    return x / (1.0f + __expf(-2.0f * u));
}
// swizzled byte offset within a [rows][32 f16 = 64B] tile (conflict-free ldmatrix)
static __device__ __forceinline__ uint32_t swz(int row, int seg) {
    return (uint32_t)(row * 64 + ((seg ^ ((row >> 1) & 3)) << 4));
}

// ---------------- smem layout ----------------
// mainloop: 4-stage ring, stage st (16KB): A @ st*16384 (8KB), W @ +8192 (8KB)
// paired epilogue: phi tile [128][132] f32 (67584B) + fold arrays (2KB)
#define STAGE_BYTES 16384
#define SMEM_BYTES  (67584 + 2048 + 128)

template<int KDIM, bool PAIRED>
static __device__ __forceinline__ void load_stage(
    int s, int row0, int col0, uint32_t sb, int tid,
    const __half* __restrict__ Aact, const __half* __restrict__ Wt)
{
    const uint32_t stb = sb + (uint32_t)(s & 3) * STAGE_BYTES;
    // A: 128 rows x 4 segs = 512 chunks of 16B
#pragma unroll
    for (int i = 0; i < 2; i++) {
        int idx = i * 256 + tid;
        int r   = idx >> 2;
        int sg  = idx & 3;
        size_t grow;
        if constexpr (PAIRED)
            grow = (r < 64) ? (size_t)(row0 + r)
                            : (size_t)B_ROWS + row0 + (r - 64);
        else
            grow = (size_t)(row0 + r);
        cp16(stb + swz(r, sg), Aact + grow * KDIM + s * 32 + sg * 8);
    }
    // W: 128 n-rows x 4 segs = 512 chunks
#pragma unroll
    for (int i = 0; i < 2; i++) {
        int idx = i * 256 + tid;
        int n   = idx >> 2;
        int sg  = idx & 3;
        cp16(stb + 8192u + swz(n, sg), Wt + (size_t)(col0 + n) * KDIM + s * 32 + sg * 8);
    }
    asm volatile("cp.async.commit_group;");
}

// ---------------- fp16 single-MMA GEMM with folded LayerNorm ----------------
// CTA: 128 rows x 128 cols, 256 threads, warp grid 2(m) x 4(n), warp tile 64x32.
// 2 CTAs/SM. FOLD: output = inv*(g@W'') - (m*inv)*u + c.
// ACT: gelu, fp16 activation out + per-row partial stats.
// PAIRED (final layer): local rows 0-63 = phi_s, 64-127 = phi_g of the SAME
// batch rows; epilogue computes IQE per (pair, component) in-CTA and emits
// one (sum4, max4) partial per (row, colcta). No phi ever touches DRAM.
template<int KDIM, bool ACT, bool FOLD, bool PAIRED>
__global__ __launch_bounds__(256, 2)
void gemm_kernel(const __half* __restrict__ Aact, const __half* __restrict__ Wt,
                 const float* __restrict__ uvec, const float* __restrict__ cvec,
                 const float4* __restrict__ statsIn, float2* __restrict__ statsOut,
                 __half* __restrict__ Oact, float2* __restrict__ iqePart)
{
    extern __shared__ char smraw[];
    char* smal = (char*)(((uintptr_t)smraw + 127) & ~(uintptr_t)127);
    const uint32_t sb = smem_u32(smal);

    const int tid  = threadIdx.x;
    const int lane = tid & 31;
    const int wid  = tid >> 5;
    const int wm   = wid >> 2;                 // 0..1 -> rows wm*64
    const int wn   = wid & 3;                  // 0..3 -> cols wn*32
    const int rowTile = blockIdx.x >> 2;
    const int colcta  = blockIdx.x & 3;
    const int row0 = PAIRED ? rowTile * 64 : rowTile * 128;
    const int col0 = colcta * 128;

    constexpr int NS = KDIM / 32;
    constexpr int PF = NS < 3 ? NS : 3;

    float acc[4][4][4];
#pragma unroll
    for (int mt = 0; mt < 4; mt++)
#pragma unroll
        for (int nt = 0; nt < 4; nt++)
#pragma unroll
            for (int j = 0; j < 4; j++) acc[mt][nt][j] = 0.f;

#pragma unroll
    for (int s = 0; s < PF; s++)
        load_stage<KDIM, PAIRED>(s, row0, col0, sb, tid, Aact, Wt);

    const int ar   = lane & 15;
    const int aseg = lane >> 4;
    const int br   = (lane & 7) + ((lane >> 4) << 3);
    const int bseg = (lane >> 3) & 1;

#pragma unroll 1
    for (int s = 0; s < NS; s++) {
        if constexpr (PF - 1 == 2) asm volatile("cp.async.wait_group 2;");
        else                       asm volatile("cp.async.wait_group 1;");
        __syncthreads();

        if (s + PF < NS) load_stage<KDIM, PAIRED>(s + PF, row0, col0, sb, tid, Aact, Wt);
        else             asm volatile("cp.async.commit_group;");

        const uint32_t stb = sb + (uint32_t)(s & 3) * STAGE_BYTES;
#pragma unroll
        for (int h = 0; h < 2; h++) {
            uint32_t a[4][4];
#pragma unroll
            for (int mt = 0; mt < 4; mt++)
                ldm_x4(a[mt], stb + swz(wm * 64 + mt * 16 + ar, 2 * h + aseg));
#pragma unroll
            for (int p = 0; p < 2; p++) {
                uint32_t bh[4];
                ldm_x4(bh, stb + 8192u + swz(wn * 32 + p * 16 + br, 2 * h + bseg));
#pragma unroll
                for (int q = 0; q < 2; q++) {
#pragma unroll
                    for (int mt = 0; mt < 4; mt++)
                        mma_f16(acc[mt][2 * p + q], a[mt], bh[2 * q], bh[2 * q + 1]);
                }
            }
        }
    }
    __syncthreads();   // release stage smem for epilogue

    // ---------------- epilogue ----------------
    float* base = (float*)smal;
    float* sInv = PAIRED ? (float*)(smal + 67584) : base;
    float* sMi  = sInv + 128;
    float* sU   = sMi + 128;
    float* sC   = sU + 128;

    if constexpr (FOLD) {
        if (tid < 128) {
            size_t grow;
            if constexpr (PAIRED)
                grow = (tid < 64) ? (size_t)(row0 + tid)
                                  : (size_t)B_ROWS + row0 + (tid - 64);
            else
                grow = (size_t)(row0 + tid);
            const float4* sp = statsIn + grow * 8;
            float ss = 0.f, sq = 0.f;
#pragma unroll
            for (int i = 0; i < 8; i++) {
                float4 v = sp[i];
                ss += v.x + v.z;
                sq += v.y + v.w;
            }
            float m   = ss * (1.0f / 512.0f);
            float var = fmaxf(sq * (1.0f / 512.0f) - m * m, 0.0f);
            float inv = rsqrtf(var + 1e-6f);
            sInv[tid] = inv;
            sMi[tid]  = m * inv;
        }
    }
    if (tid >= 128) {
        sU[tid - 128] = FOLD ? uvec[col0 + tid - 128] : 0.0f;
        sC[tid - 128] = cvec[col0 + tid - 128];
    }
    __syncthreads();

#pragma unroll
    for (int mt = 0; mt < 4; mt++) {
#pragma unroll
        for (int dp = 0; dp < 2; dp++) {
            const int rl   = wm * 64 + mt * 16 + dp * 8 + (lane >> 2);
            const float inv = FOLD ? sInv[rl] : 1.0f;
            const float mi  = FOLD ? sMi[rl]  : 0.0f;
            float gs = 0.f, gq = 0.f;
            size_t grow = (size_t)(row0 + rl);   // used by ACT path only
#pragma unroll
            for (int nt = 0; nt < 4; nt++) {
                const int cl = wn * 32 + nt * 8 + 2 * (lane & 3);
                float z0 = inv * acc[mt][nt][2 * dp + 0] - mi * sU[cl]     + sC[cl];
                float z1 = inv * acc[mt][nt][2 * dp + 1] - mi * sU[cl + 1] + sC[cl + 1];
                if constexpr (PAIRED) {
                    // stage phi in [row][i][comp] layout: conflict-free comp gathers
                    base[rl * 132 + (cl & 31) * 4 + (cl >> 5)]       = z0;
                    base[rl * 132 + ((cl & 31) + 1) * 4 + (cl >> 5)] = z1;
                } else if constexpr (ACT) {
                    float g0 = gelu_f(z0), g1 = gelu_f(z1);
                    gs += g0 + g1;
                    gq += g0 * g0 + g1 * g1;
                    __half2 hv = __floats2half2_rn(g0, g1);
                    *(__half2*)(Oact + grow * 512 + col0 + cl) = hv;
                }
            }
            if constexpr (ACT && !PAIRED) {
                gs += __shfl_xor_sync(0xffffffffu, gs, 1);
                gs += __shfl_xor_sync(0xffffffffu, gs, 2);
                gq += __shfl_xor_sync(0xffffffffu, gq, 1);
                gq += __shfl_xor_sync(0xffffffffu, gq, 2);
                if ((lane & 3) == 0)
                    statsOut[grow * 16 + (size_t)(colcta * 4 + wn)] = make_float2(gs, gq);
            }
        }
    }

    if constexpr (PAIRED) {
        __syncthreads();
        // one thread per (pair row r, component comp); 4 comps = lanes sharing r
        const int r    = tid >> 2;
        const int comp = tid & 3;
        const float* xs  = base + r * 132 + comp;
        const float* gs_ = base + (64 + r) * 132 + comp;
        float X[32], Y[32];
#pragma unroll
        for (int i = 0; i < 32; i++) {
            float xv = xs[i * 4];
            X[i] = xv;
            Y[i] = fmaxf(xv, gs_[i * 4]);
        }
#define BSTEP(V, KK, J)                                                   \
        _Pragma("unroll")                                                 \
        for (int i = 0; i < 32; i++) {                                    \
            int l = i ^ (J);                                              \
            if (l > i) {                                                  \
                bool up = ((i & (KK)) == 0);                              \
                float a_ = V[i], b_ = V[l];                               \
                float lo = fminf(a_, b_), hi = fmaxf(a_, b_);             \
                V[i] = up ? lo : hi;  V[l] = up ? hi : lo;                \
            }                                                             \
        }
        BSTEP(X,2,1) BSTEP(X,4,2) BSTEP(X,4,1) BSTEP(X,8,4) BSTEP(X,8,2) BSTEP(X,8,1)
        BSTEP(X,16,8) BSTEP(X,16,4) BSTEP(X,16,2) BSTEP(X,16,1)
        BSTEP(X,32,16) BSTEP(X,32,8) BSTEP(X,32,4) BSTEP(X,32,2) BSTEP(X,32,1)
        BSTEP(Y,2,1) BSTEP(Y,4,2) BSTEP(Y,4,1) BSTEP(Y,8,4) BSTEP(Y,8,2) BSTEP(Y,8,1)
        BSTEP(Y,16,8) BSTEP(Y,16,4) BSTEP(Y,16,2) BSTEP(Y,16,1)
        BSTEP(Y,32,16) BSTEP(Y,32,8) BSTEP(Y,32,4) BSTEP(Y,32,2) BSTEP(Y,32,1)
#undef BSTEP
        float s = Y[0] - X[0];
        float prev = Y[0];
#pragma unroll
        for (int j = 1; j < 32; j++) {
            s += Y[j] - fmaxf(X[j], prev);
            prev = Y[j];
        }
        float ssum = s, smax = s;
        ssum += __shfl_xor_sync(0xffffffffu, ssum, 1);
        smax  = fmaxf(smax, __shfl_xor_sync(0xffffffffu, smax, 1));
        ssum += __shfl_xor_sync(0xffffffffu, ssum, 2);
        smax  = fmaxf(smax, __shfl_xor_sync(0xffffffffu, smax, 2));
        if (comp == 0)
            iqePart[(size_t)(row0 + r) * 4 + colcta] = make_float2(ssum, smax);
    }
}

// ---------------- input conversion ----------------
__global__ void conv_in(const float* __restrict__ obs, const float* __restrict__ gls,
                        __half* __restrict__ out)
{
    size_t i = (size_t)blockIdx.x * blockDim.x + threadIdx.x;
    size_t n = (size_t)TOT_ROWS * 64;
    if (i >= n) return;
    float v = (i < (size_t)B_ROWS * 64) ? obs[i] : gls[i - (size_t)B_ROWS * 64];
    out[i] = __float2half_rn(v);
}

// ---------------- merged prep: all weight transposes + fold vectors ----------
// block ranges:
//   [0,128)       wprep W0 (512*64, no scale)      -> wt0
//   [128,1152)    wprep W1 scaled by l0s           -> wt1
//   [1152,2176)   wprep W2 scaled by l1s           -> wt2
//   [2176,3200)   wprep W3 scaled by l2s           -> wt3
//   [3200,3456)   ucprep layer1 (2 n per block)    -> u1,c1
//   [3456,3712)   ucprep layer2                    -> u2,c2
//   [3712,3968)   ucprep layer3                    -> u3,c3
#define PREP_BLOCKS 3968

static __device__ __forceinline__ void wprep_body(
    int i, const float* __restrict__ W, int K, const float* __restrict__ s,
    __half* __restrict__ wt)
{
    int n = i / K, k = i % K;
    float v = W[(size_t)k * 512 + n];
    if (s) v *= s[k];
    wt[i] = __float2half_rn(v);
}

static __device__ __forceinline__ void ucprep_body(
    int blk, int tid, const float* __restrict__ W, const float* __restrict__ s,
    const float* __restrict__ t, const float* __restrict__ beta,
    float* __restrict__ u, float* __restrict__ c,
    float* __restrict__ ru, float* __restrict__ rc)
{
    const int half = tid >> 7;      // two independent 128-thread halves
    const int tt   = tid & 127;
    const int n    = blk * 2 + half;
    float us = 0.f, cs = 0.f;
    for (int k = tt; k < 512; k += 128) {
        float w = W[(size_t)k * 512 + n];
        us += s[k] * w;
        cs += t[k] * w;
    }
    ru[tid] = us; rc[tid] = cs;
    __syncthreads();
    for (int off = 64; off; off >>= 1) {
        if (tt < off) {
            ru[tid] += ru[tid + off];
            rc[tid] += rc[tid + off];
        }
        __syncthreads();
    }
    if (tt == 0) { u[n] = ru[tid]; c[n] = rc[tid] + beta[n]; }
}

__global__ __launch_bounds__(256)
void prep_all(const float* __restrict__ W0, const float* __restrict__ W1,
              const float* __restrict__ W2, const float* __restrict__ W3,
              const float* __restrict__ l0s, const float* __restrict__ l0b,
              const float* __restrict__ b1,
              const float* __restrict__ l1s, const float* __restrict__ l1b,
              const float* __restrict__ b2,
              const float* __restrict__ l2s, const float* __restrict__ l2b,
              const float* __restrict__ b3,
              __half* __restrict__ wt0, __half* __restrict__ wt1,
              __half* __restrict__ wt2, __half* __restrict__ wt3,
              float* __restrict__ u1, float* __restrict__ c1,
              float* __restrict__ u2, float* __restrict__ c2,
              float* __restrict__ u3, float* __restrict__ c3)
{
    __shared__ float ru[256], rc[256];
    const int b   = blockIdx.x;
    const int tid = threadIdx.x;
    if (b < 128) {
        wprep_body(b * 256 + tid, W0, 64, nullptr, wt0);
    } else if (b < 1152) {
        wprep_body((b - 128) * 256 + tid, W1, 512, l0s, wt1);
    } else if (b < 2176) {
        wprep_body((b - 1152) * 256 + tid, W2, 512, l1s, wt2);
    } else if (b < 3200) {
        wprep_body((b - 2176) * 256 + tid, W3, 512, l2s, wt3);
    } else if (b < 3456) {
        ucprep_body(b - 3200, tid, W1, l0s, l0b, b1, u1, c1, ru, rc);
    } else if (b < 3712) {
        ucprep_body(b - 3456, tid, W2, l1s, l1b, b2, u2, c2, ru, rc);
    } else {
        ucprep_body(b - 3712, tid, W3, l2s, l2b, b3, u3, c3, ru, rc);
    }
}

// ---------------- final IQE combine ----------------
__global__ __launch_bounds__(256)
void iqe_combine(const float2* __restrict__ part, const float* __restrict__ alpha_p,
                 float* __restrict__ out)
{
    int r = blockIdx.x * 256 + threadIdx.x;
    if (r >= B_ROWS) return;
    float2 p0 = part[(size_t)r * 4 + 0];
    float2 p1 = part[(size_t)r * 4 + 1];
    float2 p2 = part[(size_t)r * 4 + 2];
    float2 p3 = part[(size_t)r * 4 + 3];
    float ssum = (p0.x + p1.x) + (p2.x + p3.x);
    float smax = fmaxf(fmaxf(p0.y, p1.y), fmaxf(p2.y, p3.y));
    float a = 1.0f / (1.0f + expf(-alpha_p[0]));
    out[r] = a * (ssum * (1.0f / 16.0f)) + (1.0f - a) * smax;
}

// ---------------- launch ----------------
extern "C" void kernel_launch(void* const* d_in, const int* in_sizes, int n_in,
                              void* d_out, int out_size)
{
    const float* obs   = (const float*)d_in[0];
    const float* gls   = (const float*)d_in[1];
    const float* W0    = (const float*)d_in[2];
    const float* b0    = (const float*)d_in[3];
    const float* l0s   = (const float*)d_in[4];
    const float* l0b   = (const float*)d_in[5];
    const float* W1    = (const float*)d_in[6];
    const float* b1    = (const float*)d_in[7];
    const float* l1s   = (const float*)d_in[8];
    const float* l1b   = (const float*)d_in[9];
    const float* W2    = (const float*)d_in[10];
    const float* b2    = (const float*)d_in[11];
    const float* l2s   = (const float*)d_in[12];
    const float* l2b   = (const float*)d_in[13];
    const float* W3    = (const float*)d_in[14];
    const float* b3    = (const float*)d_in[15];
    const float* alpha = (const float*)d_in[16];

    __half *a0, *actA, *actB, *wt0, *wt1, *wt2, *wt3;
    float *u1, *c1, *u2, *c2, *u3, *c3;
    float4 *stA, *stB;
    float2 *part;
    cudaGetSymbolAddress((void**)&a0,   g_a0);
    cudaGetSymbolAddress((void**)&actA, g_actA);
    cudaGetSymbolAddress((void**)&actB, g_actB);
    cudaGetSymbolAddress((void**)&wt0,  g_wt0);
    cudaGetSymbolAddress((void**)&wt1,  g_wt1);
    cudaGetSymbolAddress((void**)&wt2,  g_wt2);
    cudaGetSymbolAddress((void**)&wt3,  g_wt3);
    cudaGetSymbolAddress((void**)&u1,   g_u1);
    cudaGetSymbolAddress((void**)&c1,   g_c1);
    cudaGetSymbolAddress((void**)&u2,   g_u2);
    cudaGetSymbolAddress((void**)&c2,   g_c2);
    cudaGetSymbolAddress((void**)&u3,   g_u3);
    cudaGetSymbolAddress((void**)&c3,   g_c3);
    cudaGetSymbolAddress((void**)&stA,  g_statA);
    cudaGetSymbolAddress((void**)&stB,  g_statB);
    cudaGetSymbolAddress((void**)&part, g_iqePart);

    cudaFuncSetAttribute(gemm_kernel<64,  true,  false, false>, cudaFuncAttributeMaxDynamicSharedMemorySize, SMEM_BYTES);
    cudaFuncSetAttribute(gemm_kernel<512, true,  true,  false>, cudaFuncAttributeMaxDynamicSharedMemorySize, SMEM_BYTES);
    cudaFuncSetAttribute(gemm_kernel<512, false, true,  true >, cudaFuncAttributeMaxDynamicSharedMemorySize, SMEM_BYTES);

    dim3 blk(256);
    dim3 grid((TOT_ROWS / 128) * 4);

    // launch 0
    conv_in<<<(TOT_ROWS * 64 + 255) / 256, 256>>>(obs, gls, a0);

    // launch 1: ALL weight/fold prep in one kernel
    prep_all<<<PREP_BLOCKS, 256>>>(W0, W1, W2, W3,
                                   l0s, l0b, b1, l1s, l1b, b2, l2s, l2b, b3,
                                   wt0, wt1, wt2, wt3, u1, c1, u2, c2, u3, c3);

    // launch 2: L0 (no fold), gelu + stats -> statA
    gemm_kernel<64, true, false, false><<<grid, blk, SMEM_BYTES>>>(
        a0, wt0, nullptr, b0, nullptr, (float2*)stA, actA, nullptr);

    // launch 3 (ncu capture slot): L1, fold ln0
    gemm_kernel<512, true, true, false><<<grid, blk, SMEM_BYTES>>>(
        actA, wt1, u1, c1, stA, (float2*)stB, actB, nullptr);

    // launch 4: L2, fold ln1
    gemm_kernel<512, true, true, false><<<grid, blk, SMEM_BYTES>>>(
        actB, wt2, u2, c2, stB, (float2*)stA, actA, nullptr);

    // launch 5: L3, fold ln2, paired rows, fused IQE -> partials
    gemm_kernel<512, false, true, true><<<(B_ROWS / 64) * 4, blk, SMEM_BYTES>>>(
        actA, wt3, u3, c3, stA, nullptr, nullptr, part);

    // launch 6
    iqe_combine<<<(B_ROWS + 255) / 256, 256>>>(part, alpha, (float*)d_out);
}

// round 10
// speedup vs baseline: 5.0897x; 1.0006x over previous
#include <cuda_runtime.h>
#include <cuda_fp16.h>
#include <cstdint>

#define B_ROWS   131072
#define TOT_ROWS 262144

// ---------------- scratch (device globals; no allocations) ----------------
__device__ __half  g_a0[(size_t)TOT_ROWS * 64];
__device__ __half  g_actA[(size_t)TOT_ROWS * 512];
__device__ __half  g_actB[(size_t)TOT_ROWS * 512];
__device__ __half  g_wt0[512 * 64];
__device__ __half  g_wt1[512 * 512];
__device__ __half  g_wt2[512 * 512];
__device__ __half  g_wt3[512 * 512];
__device__ float4  g_statA[(size_t)TOT_ROWS * 8];   // 16 float2 partials per row
__device__ float4  g_statB[(size_t)TOT_ROWS * 8];
__device__ float   g_u1[512], g_c1[512];
__device__ float   g_u2[512], g_c2[512];
__device__ float   g_u3[512], g_c3[512];
__device__ float2  g_iqePart[(size_t)B_ROWS * 4];   // (sum4, max4) per (row, colcta)

// ---------------- PTX helpers ----------------
static __device__ __forceinline__ uint32_t smem_u32(const void* p) {
    uint32_t a;
    asm("{ .reg .u64 t; cvta.to.shared.u64 t, %1; cvt.u32.u64 %0, t; }" : "=r"(a) : "l"(p));
    return a;
}
static __device__ __forceinline__ void cp16(uint32_t dst, const void* src) {
    asm volatile("cp.async.cg.shared.global [%0], [%1], 16;" :: "r"(dst), "l"(src));
}
static __device__ __forceinline__ void ldm_x4(uint32_t (&r)[4], uint32_t addr) {
    asm volatile("ldmatrix.sync.aligned.m8n8.x4.shared.b16 {%0,%1,%2,%3}, [%4];"
                 : "=r"(r[0]), "=r"(r[1]), "=r"(r[2]), "=r"(r[3]) : "r"(addr));
}
static __device__ __forceinline__ void mma_f16(float (&d)[4], const uint32_t (&a)[4],
                                               uint32_t b0, uint32_t b1) {
    asm volatile("mma.sync.aligned.m16n8k16.row.col.f32.f16.f16.f32 "
                 "{%0,%1,%2,%3}, {%4,%5,%6,%7}, {%8,%9}, {%0,%1,%2,%3};"
                 : "+f"(d[0]), "+f"(d[1]), "+f"(d[2]), "+f"(d[3])
                 : "r"(a[0]), "r"(a[1]), "r"(a[2]), "r"(a[3]), "r"(b0), "r"(b1));
}
// gelu(x) = x * sigmoid(2 * sqrt(2/pi) * (x + 0.044715 x^3))   (tanh form)
static __device__ __forceinline__ float gelu_f(float x) {
    float u = 0.7978845608028654f * x * (1.0f + 0.044715f * x * x);
    return x / (1.0f + __expf(-2.0f * u));
}
// swizzled byte offset within a [rows][32 f16 = 64B] tile (conflict-free ldmatrix)
static __device__ __forceinline__ uint32_t swz(int row, int seg) {
    return (uint32_t)(row * 64 + ((seg ^ ((row >> 1) & 3)) << 4));
}

// ---------------- smem layout ----------------
// mainloop: 4-stage ring, stage st (12KB): A @ st*12288 (4KB: 64 rows x 64B),
// W @ +4096 (8KB). paired epilogue: phi tile [64][132] f32 (33792B) + folds.
#define STAGE_BYTES 12288
#define SMEM_BYTES  (4 * STAGE_BYTES + 2048 + 128)

template<int KDIM, bool PAIRED>
static __device__ __forceinline__ void load_stage(
    int s, int row0, int col0, uint32_t sb, int tid,
    const __half* __restrict__ Aact, const __half* __restrict__ Wt)
{
    const uint32_t stb = sb + (uint32_t)(s & 3) * STAGE_BYTES;
    // A: 64 rows x 4 segs = 256 chunks of 16B
    {
        int r  = tid >> 2;
        int sg = tid & 3;
        size_t grow;
        if constexpr (PAIRED)
            grow = (r < 32) ? (size_t)(row0 + r)
                            : (size_t)B_ROWS + row0 + (r - 32);
        else
            grow = (size_t)(row0 + r);
        cp16(stb + swz(r, sg), Aact + grow * KDIM + s * 32 + sg * 8);
    }
    // W: 128 n-rows x 4 segs = 512 chunks
#pragma unroll
    for (int i = 0; i < 2; i++) {
        int idx = i * 256 + tid;
        int n   = idx >> 2;
        int sg  = idx & 3;
        cp16(stb + 4096u + swz(n, sg), Wt + (size_t)(col0 + n) * KDIM + s * 32 + sg * 8);
    }
    asm volatile("cp.async.commit_group;");
}

// ---------------- fp16 single-MMA GEMM with folded LayerNorm ----------------
// CTA: 64 rows x 128 cols, 256 threads, warp grid 2(m) x 4(n), warp tile 32x32.
// 3 CTAs/SM (24 warps): hides HMMA/ldmatrix latency + barrier drains.
// FOLD: output = inv*(g@W'') - (m*inv)*u + c.
// ACT: gelu, fp16 activation out + per-row partial stats.
// PAIRED (final layer): local rows 0-31 = phi_s, 32-63 = phi_g of the SAME
// batch rows; epilogue computes IQE per (pair, component) in-CTA.
template<int KDIM, bool ACT, bool FOLD, bool PAIRED>
__global__ __launch_bounds__(256, 3)
void gemm_kernel(const __half* __restrict__ Aact, const __half* __restrict__ Wt,
                 const float* __restrict__ uvec, const float* __restrict__ cvec,
                 const float4* __restrict__ statsIn, float2* __restrict__ statsOut,
                 __half* __restrict__ Oact, float2* __restrict__ iqePart)
{
    extern __shared__ char smraw[];
    char* smal = (char*)(((uintptr_t)smraw + 127) & ~(uintptr_t)127);
    const uint32_t sb = smem_u32(smal);

    const int tid  = threadIdx.x;
    const int lane = tid & 31;
    const int wid  = tid >> 5;
    const int wm   = wid >> 2;                 // 0..1 -> rows wm*32
    const int wn   = wid & 3;                  // 0..3 -> cols wn*32
    const int rowTile = blockIdx.x >> 2;
    const int colcta  = blockIdx.x & 3;
    const int row0 = PAIRED ? rowTile * 32 : rowTile * 64;
    const int col0 = colcta * 128;

    constexpr int NS = KDIM / 32;
    constexpr int PF = NS < 3 ? NS : 3;

    float acc[2][4][4];
#pragma unroll
    for (int mt = 0; mt < 2; mt++)
#pragma unroll
        for (int nt = 0; nt < 4; nt++)
#pragma unroll
            for (int j = 0; j < 4; j++) acc[mt][nt][j] = 0.f;

#pragma unroll
    for (int s = 0; s < PF; s++)
        load_stage<KDIM, PAIRED>(s, row0, col0, sb, tid, Aact, Wt);

    const int ar   = lane & 15;
    const int aseg = lane >> 4;
    const int br   = (lane & 7) + ((lane >> 4) << 3);
    const int bseg = (lane >> 3) & 1;

#pragma unroll 1
    for (int s = 0; s < NS; s++) {
        if constexpr (PF - 1 == 2) asm volatile("cp.async.wait_group 2;");
        else                       asm volatile("cp.async.wait_group 1;");
        __syncthreads();

        if (s + PF < NS) load_stage<KDIM, PAIRED>(s + PF, row0, col0, sb, tid, Aact, Wt);
        else             asm volatile("cp.async.commit_group;");

        const uint32_t stb = sb + (uint32_t)(s & 3) * STAGE_BYTES;
#pragma unroll
        for (int h = 0; h < 2; h++) {
            uint32_t a[2][4];
#pragma unroll
            for (int mt = 0; mt < 2; mt++)
                ldm_x4(a[mt], stb + swz(wm * 32 + mt * 16 + ar, 2 * h + aseg));
#pragma unroll
            for (int p = 0; p < 2; p++) {
                uint32_t bh[4];
                ldm_x4(bh, stb + 4096u + swz(wn * 32 + p * 16 + br, 2 * h + bseg));
#pragma unroll
                for (int q = 0; q < 2; q++) {
#pragma unroll
                    for (int mt = 0; mt < 2; mt++)
                        mma_f16(acc[mt][2 * p + q], a[mt], bh[2 * q], bh[2 * q + 1]);
                }
            }
        }
    }
    __syncthreads();   // release stage smem for epilogue

    // ---------------- epilogue ----------------
    float* base = (float*)smal;
    float* sInv = PAIRED ? (float*)(smal + 33792) : base;   // [64]
    float* sMi  = sInv + 64;                                 // [64]
    float* sU   = sMi + 64;                                  // [128]
    float* sC   = sU + 128;                                  // [128]

    if constexpr (FOLD) {
        if (tid < 64) {
            size_t grow;
            if constexpr (PAIRED)
                grow = (tid < 32) ? (size_t)(row0 + tid)
                                  : (size_t)B_ROWS + row0 + (tid - 32);
            else
                grow = (size_t)(row0 + tid);
            const float4* sp = statsIn + grow * 8;
            float ss = 0.f, sq = 0.f;
#pragma unroll
            for (int i = 0; i < 8; i++) {
                float4 v = sp[i];
                ss += v.x + v.z;
                sq += v.y + v.w;
            }
            float m   = ss * (1.0f / 512.0f);
            float var = fmaxf(sq * (1.0f / 512.0f) - m * m, 0.0f);
            float inv = rsqrtf(var + 1e-6f);
            sInv[tid] = inv;
            sMi[tid]  = m * inv;
        }
    }
    if (tid >= 128) {
        sU[tid - 128] = FOLD ? uvec[col0 + tid - 128] : 0.0f;
        sC[tid - 128] = cvec[col0 + tid - 128];
    }
    __syncthreads();

#pragma unroll
    for (int mt = 0; mt < 2; mt++) {
#pragma unroll
        for (int dp = 0; dp < 2; dp++) {
            const int rl   = wm * 32 + mt * 16 + dp * 8 + (lane >> 2);
            const float inv = FOLD ? sInv[rl] : 1.0f;
            const float mi  = FOLD ? sMi[rl]  : 0.0f;
            float gs = 0.f, gq = 0.f;
            size_t grow = (size_t)(row0 + rl);   // used by ACT path only
#pragma unroll
            for (int nt = 0; nt < 4; nt++) {
                const int cl = wn * 32 + nt * 8 + 2 * (lane & 3);
                float z0 = inv * acc[mt][nt][2 * dp + 0] - mi * sU[cl]     + sC[cl];
                float z1 = inv * acc[mt][nt][2 * dp + 1] - mi * sU[cl + 1] + sC[cl + 1];
                if constexpr (PAIRED) {
                    // stage phi in [row][i][comp] layout: conflict-free comp gathers
                    base[rl * 132 + (cl & 31) * 4 + (cl >> 5)]       = z0;
                    base[rl * 132 + ((cl & 31) + 1) * 4 + (cl >> 5)] = z1;
                } else if constexpr (ACT) {
                    float g0 = gelu_f(z0), g1 = gelu_f(z1);
                    gs += g0 + g1;
                    gq += g0 * g0 + g1 * g1;
                    __half2 hv = __floats2half2_rn(g0, g1);
                    *(__half2*)(Oact + grow * 512 + col0 + cl) = hv;
                }
            }
            if constexpr (ACT && !PAIRED) {
                gs += __shfl_xor_sync(0xffffffffu, gs, 1);
                gs += __shfl_xor_sync(0xffffffffu, gs, 2);
                gq += __shfl_xor_sync(0xffffffffu, gq, 1);
                gq += __shfl_xor_sync(0xffffffffu, gq, 2);
                if ((lane & 3) == 0)
                    statsOut[grow * 16 + (size_t)(colcta * 4 + wn)] = make_float2(gs, gq);
            }
        }
    }

    if constexpr (PAIRED) {
        __syncthreads();
        if (tid < 128) {
            // one thread per (pair row r, component comp)
            const int r    = tid >> 2;       // 0..31
            const int comp = tid & 3;
            const float* xs  = base + r * 132 + comp;
            const float* gs_ = base + (32 + r) * 132 + comp;
            float X[32], Y[32];
#pragma unroll
            for (int i = 0; i < 32; i++) {
                float xv = xs[i * 4];
                X[i] = xv;
                Y[i] = fmaxf(xv, gs_[i * 4]);
            }
#define BSTEP(V, KK, J)                                                   \
            _Pragma("unroll")                                             \
            for (int i = 0; i < 32; i++) {                                \
                int l = i ^ (J);                                          \
                if (l > i) {                                              \
                    bool up = ((i & (KK)) == 0);                          \
                    float a_ = V[i], b_ = V[l];                           \
                    float lo = fminf(a_, b_), hi = fmaxf(a_, b_);         \
                    V[i] = up ? lo : hi;  V[l] = up ? hi : lo;            \
                }                                                         \
            }
            BSTEP(X,2,1) BSTEP(X,4,2) BSTEP(X,4,1) BSTEP(X,8,4) BSTEP(X,8,2) BSTEP(X,8,1)
            BSTEP(X,16,8) BSTEP(X,16,4) BSTEP(X,16,2) BSTEP(X,16,1)
            BSTEP(X,32,16) BSTEP(X,32,8) BSTEP(X,32,4) BSTEP(X,32,2) BSTEP(X,32,1)
            BSTEP(Y,2,1) BSTEP(Y,4,2) BSTEP(Y,4,1) BSTEP(Y,8,4) BSTEP(Y,8,2) BSTEP(Y,8,1)
            BSTEP(Y,16,8) BSTEP(Y,16,4) BSTEP(Y,16,2) BSTEP(Y,16,1)
            BSTEP(Y,32,16) BSTEP(Y,32,8) BSTEP(Y,32,4) BSTEP(Y,32,2) BSTEP(Y,32,1)
#undef BSTEP
            float s = Y[0] - X[0];
            float prev = Y[0];
#pragma unroll
            for (int j = 1; j < 32; j++) {
                s += Y[j] - fmaxf(X[j], prev);
                prev = Y[j];
            }
            float ssum = s, smax = s;
            ssum += __shfl_xor_sync(0xffffffffu, ssum, 1);
            smax  = fmaxf(smax, __shfl_xor_sync(0xffffffffu, smax, 1));
            ssum += __shfl_xor_sync(0xffffffffu, ssum, 2);
            smax  = fmaxf(smax, __shfl_xor_sync(0xffffffffu, smax, 2));
            if (comp == 0)
                iqePart[(size_t)(row0 + r) * 4 + colcta] = make_float2(ssum, smax);
        }
    }
}

// ---------------- input conversion ----------------
__global__ void conv_in(const float* __restrict__ obs, const float* __restrict__ gls,
                        __half* __restrict__ out)
{
    size_t i = (size_t)blockIdx.x * blockDim.x + threadIdx.x;
    size_t n = (size_t)TOT_ROWS * 64;
    if (i >= n) return;
    float v = (i < (size_t)B_ROWS * 64) ? obs[i] : gls[i - (size_t)B_ROWS * 64];
    out[i] = __float2half_rn(v);
}

// ---------------- merged prep: all weight transposes + fold vectors ----------
#define PREP_BLOCKS 3968

static __device__ __forceinline__ void wprep_body(
    int i, const float* __restrict__ W, int K, const float* __restrict__ s,
    __half* __restrict__ wt)
{
    int n = i / K, k = i % K;
    float v = W[(size_t)k * 512 + n];
    if (s) v *= s[k];
    wt[i] = __float2half_rn(v);
}

static __device__ __forceinline__ void ucprep_body(
    int blk, int tid, const float* __restrict__ W, const float* __restrict__ s,
    const float* __restrict__ t, const float* __restrict__ beta,
    float* __restrict__ u, float* __restrict__ c,
    float* __restrict__ ru, float* __restrict__ rc)
{
    const int half = tid >> 7;      // two independent 128-thread halves
    const int tt   = tid & 127;
    const int n    = blk * 2 + half;
    float us = 0.f, cs = 0.f;
    for (int k = tt; k < 512; k += 128) {
        float w = W[(size_t)k * 512 + n];
        us += s[k] * w;
        cs += t[k] * w;
    }
    ru[tid] = us; rc[tid] = cs;
    __syncthreads();
    for (int off = 64; off; off >>= 1) {
        if (tt < off) {
            ru[tid] += ru[tid + off];
            rc[tid] += rc[tid + off];
        }
        __syncthreads();
    }
    if (tt == 0) { u[n] = ru[tid]; c[n] = rc[tid] + beta[n]; }
}

__global__ __launch_bounds__(256)
void prep_all(const float* __restrict__ W0, const float* __restrict__ W1,
              const float* __restrict__ W2, const float* __restrict__ W3,
              const float* __restrict__ l0s, const float* __restrict__ l0b,
              const float* __restrict__ b1,
              const float* __restrict__ l1s, const float* __restrict__ l1b,
              const float* __restrict__ b2,
              const float* __restrict__ l2s, const float* __restrict__ l2b,
              const float* __restrict__ b3,
              __half* __restrict__ wt0, __half* __restrict__ wt1,
              __half* __restrict__ wt2, __half* __restrict__ wt3,
              float* __restrict__ u1, float* __restrict__ c1,
              float* __restrict__ u2, float* __restrict__ c2,
              float* __restrict__ u3, float* __restrict__ c3)
{
    __shared__ float ru[256], rc[256];
    const int b   = blockIdx.x;
    const int tid = threadIdx.x;
    if (b < 128) {
        wprep_body(b * 256 + tid, W0, 64, nullptr, wt0);
    } else if (b < 1152) {
        wprep_body((b - 128) * 256 + tid, W1, 512, l0s, wt1);
    } else if (b < 2176) {
        wprep_body((b - 1152) * 256 + tid, W2, 512, l1s, wt2);
    } else if (b < 3200) {
        wprep_body((b - 2176) * 256 + tid, W3, 512, l2s, wt3);
    } else if (b < 3456) {
        ucprep_body(b - 3200, tid, W1, l0s, l0b, b1, u1, c1, ru, rc);
    } else if (b < 3712) {
        ucprep_body(b - 3456, tid, W2, l1s, l1b, b2, u2, c2, ru, rc);
    } else {
        ucprep_body(b - 3712, tid, W3, l2s, l2b, b3, u3, c3, ru, rc);
    }
}

// ---------------- final IQE combine ----------------
__global__ __launch_bounds__(256)
void iqe_combine(const float2* __restrict__ part, const float* __restrict__ alpha_p,
                 float* __restrict__ out)
{
    int r = blockIdx.x * 256 + threadIdx.x;
    if (r >= B_ROWS) return;
    float2 p0 = part[(size_t)r * 4 + 0];
    float2 p1 = part[(size_t)r * 4 + 1];
    float2 p2 = part[(size_t)r * 4 + 2];
    float2 p3 = part[(size_t)r * 4 + 3];
    float ssum = (p0.x + p1.x) + (p2.x + p3.x);
    float smax = fmaxf(fmaxf(p0.y, p1.y), fmaxf(p2.y, p3.y));
    float a = 1.0f / (1.0f + expf(-alpha_p[0]));
    out[r] = a * (ssum * (1.0f / 16.0f)) + (1.0f - a) * smax;
}

// ---------------- launch ----------------
extern "C" void kernel_launch(void* const* d_in, const int* in_sizes, int n_in,
                              void* d_out, int out_size)
{
    const float* obs   = (const float*)d_in[0];
    const float* gls   = (const float*)d_in[1];
    const float* W0    = (const float*)d_in[2];
    const float* b0    = (const float*)d_in[3];
    const float* l0s   = (const float*)d_in[4];
    const float* l0b   = (const float*)d_in[5];
    const float* W1    = (const float*)d_in[6];
    const float* b1    = (const float*)d_in[7];
    const float* l1s   = (const float*)d_in[8];
    const float* l1b   = (const float*)d_in[9];
    const float* W2    = (const float*)d_in[10];
    const float* b2    = (const float*)d_in[11];
    const float* l2s   = (const float*)d_in[12];
    const float* l2b   = (const float*)d_in[13];
    const float* W3    = (const float*)d_in[14];
    const float* b3    = (const float*)d_in[15];
    const float* alpha = (const float*)d_in[16];

    __half *a0, *actA, *actB, *wt0, *wt1, *wt2, *wt3;
    float *u1, *c1, *u2, *c2, *u3, *c3;
    float4 *stA, *stB;
    float2 *part;
    cudaGetSymbolAddress((void**)&a0,   g_a0);
    cudaGetSymbolAddress((void**)&actA, g_actA);
    cudaGetSymbolAddress((void**)&actB, g_actB);
    cudaGetSymbolAddress((void**)&wt0,  g_wt0);
    cudaGetSymbolAddress((void**)&wt1,  g_wt1);
    cudaGetSymbolAddress((void**)&wt2,  g_wt2);
    cudaGetSymbolAddress((void**)&wt3,  g_wt3);
    cudaGetSymbolAddress((void**)&u1,   g_u1);
    cudaGetSymbolAddress((void**)&c1,   g_c1);
    cudaGetSymbolAddress((void**)&u2,   g_u2);
    cudaGetSymbolAddress((void**)&c2,   g_c2);
    cudaGetSymbolAddress((void**)&u3,   g_u3);
    cudaGetSymbolAddress((void**)&c3,   g_c3);
    cudaGetSymbolAddress((void**)&stA,  g_statA);
    cudaGetSymbolAddress((void**)&stB,  g_statB);
    cudaGetSymbolAddress((void**)&part, g_iqePart);

    cudaFuncSetAttribute(gemm_kernel<64,  true,  false, false>, cudaFuncAttributeMaxDynamicSharedMemorySize, SMEM_BYTES);
    cudaFuncSetAttribute(gemm_kernel<512, true,  true,  false>, cudaFuncAttributeMaxDynamicSharedMemorySize, SMEM_BYTES);
    cudaFuncSetAttribute(gemm_kernel<512, false, true,  true >, cudaFuncAttributeMaxDynamicSharedMemorySize, SMEM_BYTES);

    dim3 blk(256);
    dim3 grid((TOT_ROWS / 64) * 4);

    // launch 0
    conv_in<<<(TOT_ROWS * 64 + 255) / 256, 256>>>(obs, gls, a0);

    // launch 1: ALL weight/fold prep in one kernel
    prep_all<<<PREP_BLOCKS, 256>>>(W0, W1, W2, W3,
                                   l0s, l0b, b1, l1s, l1b, b2, l2s, l2b, b3,
                                   wt0, wt1, wt2, wt3, u1, c1, u2, c2, u3, c3);

    // launch 2: L0 (no fold), gelu + stats -> statA
    gemm_kernel<64, true, false, false><<<grid, blk, SMEM_BYTES>>>(
        a0, wt0, nullptr, b0, nullptr, (float2*)stA, actA, nullptr);

    // launch 3 (ncu capture slot): L1, fold ln0
    gemm_kernel<512, true, true, false><<<grid, blk, SMEM_BYTES>>>(
        actA, wt1, u1, c1, stA, (float2*)stB, actB, nullptr);

    // launch 4: L2, fold ln1
    gemm_kernel<512, true, true, false><<<grid, blk, SMEM_BYTES>>>(
        actB, wt2, u2, c2, stB, (float2*)stA, actA, nullptr);

    // launch 5: L3, fold ln2, paired rows, fused IQE -> partials
    gemm_kernel<512, false, true, true><<<(B_ROWS / 32) * 4, blk, SMEM_BYTES>>>(
        actA, wt3, u3, c3, stA, nullptr, nullptr, part);

    // launch 6
    iqe_combine<<<(B_ROWS + 255) / 256, 256>>>(part, alpha, (float*)d_out);
}

// round 11
// speedup vs baseline: 5.2251x; 1.0266x over previous
#include <cuda_runtime.h>
#include <cuda_fp16.h>
#include <cstdint>

#define B_ROWS   131072
#define TOT_ROWS 262144

// ---------------- scratch (device globals; no allocations) ----------------
__device__ __half  g_a0[(size_t)TOT_ROWS * 64];
__device__ __half  g_actA[(size_t)TOT_ROWS * 512];
__device__ __half  g_actB[(size_t)TOT_ROWS * 512];
__device__ __half  g_wt0[512 * 64];
__device__ __half  g_wt1[512 * 512];
__device__ __half  g_wt2[512 * 512];
__device__ __half  g_wt3[512 * 512];
__device__ float4  g_statA[(size_t)TOT_ROWS * 8];   // 16 float2 partials per row
__device__ float4  g_statB[(size_t)TOT_ROWS * 8];
__device__ float   g_u1[512], g_c1[512];
__device__ float   g_u2[512], g_c2[512];
__device__ float   g_u3[512], g_c3[512];
__device__ float2  g_iqePart[(size_t)B_ROWS * 4];   // (sum4, max4) per (row, colcta)

// ---------------- PTX helpers ----------------
static __device__ __forceinline__ uint32_t smem_u32(const void* p) {
    uint32_t a;
    asm("{ .reg .u64 t; cvta.to.shared.u64 t, %1; cvt.u32.u64 %0, t; }" : "=r"(a) : "l"(p));
    return a;
}
static __device__ __forceinline__ void cp16(uint32_t dst, const void* src) {
    asm volatile("cp.async.cg.shared.global [%0], [%1], 16;" :: "r"(dst), "l"(src));
}
static __device__ __forceinline__ void ldm_x4(uint32_t (&r)[4], uint32_t addr) {
    asm volatile("ldmatrix.sync.aligned.m8n8.x4.shared.b16 {%0,%1,%2,%3}, [%4];"
                 : "=r"(r[0]), "=r"(r[1]), "=r"(r[2]), "=r"(r[3]) : "r"(addr));
}
static __device__ __forceinline__ void mma_f16(float (&d)[4], const uint32_t (&a)[4],
                                               uint32_t b0, uint32_t b1) {
    asm volatile("mma.sync.aligned.m16n8k16.row.col.f32.f16.f16.f32 "
                 "{%0,%1,%2,%3}, {%4,%5,%6,%7}, {%8,%9}, {%0,%1,%2,%3};"
                 : "+f"(d[0]), "+f"(d[1]), "+f"(d[2]), "+f"(d[3])
                 : "r"(a[0]), "r"(a[1]), "r"(a[2]), "r"(a[3]), "r"(b0), "r"(b1));
}
// gelu(x) = x * sigmoid(2 * sqrt(2/pi) * (x + 0.044715 x^3))   (tanh form)
static __device__ __forceinline__ float gelu_f(float x) {
    float u = 0.7978845608028654f * x * (1.0f + 0.044715f * x * x);
    return x / (1.0f + __expf(-2.0f * u));
}
// swizzled byte offset within a [rows][32 f16 = 64B] tile (conflict-free ldmatrix)
static __device__ __forceinline__ uint32_t swz(int row, int seg) {
    return (uint32_t)(row * 64 + ((seg ^ ((row >> 1) & 3)) << 4));
}

// ---------------- smem layout ----------------
// mainloop: 6-slot ring, slot (16KB): A @ 0 (8KB: 128 rows x 64B), W @ +8192 (8KB)
// paired epilogue: phi tile [128][132] f32 (67584B) + fold arrays (reuses ring)
#define SLOT_BYTES 16384
#define SMEM_BYTES (6 * SLOT_BYTES + 128)

// ---------------- fp16 single-MMA GEMM with folded LayerNorm ----------------
// CTA: 128 rows x 128 cols, 256 threads, warp grid 2(m) x 4(n), warp tile 64x32.
// occ 2. Ring of 6 K=32 slots; ONE barrier per TWO slots (64 MMAs/warp between
// barriers). All ldmatrix/cp.async addresses precomputed; h=1 offsets = h0 ^ 32.
// FOLD: output = inv*(g@W'') - (m*inv)*u + c.
// ACT:  gelu, fp16 activation out + per-row partial stats.
// PAIRED (final layer): local rows 0-63 = phi_s, 64-127 = phi_g of the SAME 64
// batch rows; epilogue computes IQE per (pair, component) in-CTA.
template<int KDIM, bool ACT, bool FOLD, bool PAIRED>
__global__ __launch_bounds__(256, 2)
void gemm_kernel(const __half* __restrict__ Aact, const __half* __restrict__ Wt,
                 const float* __restrict__ uvec, const float* __restrict__ cvec,
                 const float4* __restrict__ statsIn, float2* __restrict__ statsOut,
                 __half* __restrict__ Oact, float2* __restrict__ iqePart)
{
    extern __shared__ char smraw[];
    char* smal = (char*)(((uintptr_t)smraw + 127) & ~(uintptr_t)127);
    const uint32_t sb = smem_u32(smal);

    const int tid  = threadIdx.x;
    const int lane = tid & 31;
    const int wid  = tid >> 5;
    const int wm   = wid >> 2;                 // 0..1 -> rows wm*64
    const int wn   = wid & 3;                  // 0..3 -> cols wn*32
    const int rowTile = blockIdx.x >> 2;
    const int colcta  = blockIdx.x & 3;
    const int row0 = PAIRED ? rowTile * 64 : rowTile * 128;
    const int col0 = colcta * 128;

    constexpr int NS = KDIM / 32;              // 2 or 16

    float acc[4][4][4];
#pragma unroll
    for (int mt = 0; mt < 4; mt++)
#pragma unroll
        for (int nt = 0; nt < 4; nt++)
#pragma unroll
            for (int j = 0; j < 4; j++) acc[mt][nt][j] = 0.f;

    // -------- precomputed loader state --------
    const int rA  = tid >> 2;
    const int sgA = tid & 3;
    const uint32_t dstA0 = swz(rA, sgA);
    const uint32_t dstA1 = swz(rA + 64, sgA);
    const uint32_t dstW0 = 8192u + dstA0;
    const uint32_t dstW1 = 8192u + dstA1;
    size_t growA0, growA1;
    if constexpr (PAIRED) {
        growA0 = (size_t)(row0 + rA);
        growA1 = (size_t)B_ROWS + row0 + rA;
    } else {
        growA0 = (size_t)(row0 + rA);
        growA1 = growA0 + 64;
    }
    const __half* gA0 = Aact + growA0 * KDIM + sgA * 8;
    const __half* gA1 = Aact + growA1 * KDIM + sgA * 8;
    const __half* gW0 = Wt + (size_t)(col0 + rA) * KDIM + sgA * 8;
    const __half* gW1 = gW0 + (size_t)64 * KDIM;

    // -------- precomputed ldmatrix offsets (h=1 = h0 ^ 32) --------
    const int ar   = lane & 15;
    const int aseg = lane >> 4;
    const int br   = (lane & 7) + ((lane >> 4) << 3);
    const int bseg = (lane >> 3) & 1;
    uint32_t offA[4], offB[2];
#pragma unroll
    for (int mt = 0; mt < 4; mt++) offA[mt] = swz(wm * 64 + mt * 16 + ar, aseg);
#pragma unroll
    for (int p = 0; p < 2; p++)    offB[p]  = 8192u + swz(wn * 32 + p * 16 + br, bseg);

#define LOAD_SLOT(slot)                                                     \
    do {                                                                    \
        uint32_t stb_ = sb + (uint32_t)(slot) * SLOT_BYTES;                 \
        cp16(stb_ + dstA0, gA0); cp16(stb_ + dstA1, gA1);                   \
        cp16(stb_ + dstW0, gW0); cp16(stb_ + dstW1, gW1);                   \
        asm volatile("cp.async.commit_group;");                             \
        gA0 += 32; gA1 += 32; gW0 += 32; gW1 += 32;                         \
    } while (0)

    // prologue: 4 groups (empty commits pad when NS < 4)
#pragma unroll
    for (int s = 0; s < 4; s++) {
        if (s < NS) LOAD_SLOT(s);
        else        asm volatile("cp.async.commit_group;");
    }

    int cslot = 0;
    int lslot = 4;
#pragma unroll 1
    for (int it = 0; it < NS / 2; it++) {
        asm volatile("cp.async.wait_group 2;");
        __syncthreads();

        const int s4 = 2 * it + 4;
        if (s4 < NS)     LOAD_SLOT(lslot);
        else             asm volatile("cp.async.commit_group;");
        lslot = (lslot + 1 == 6) ? 0 : lslot + 1;
        if (s4 + 1 < NS) LOAD_SLOT(lslot);
        else             asm volatile("cp.async.commit_group;");
        lslot = (lslot + 1 == 6) ? 0 : lslot + 1;

#pragma unroll
        for (int u = 0; u < 2; u++) {
            const uint32_t stb = sb + (uint32_t)cslot * SLOT_BYTES;
#pragma unroll
            for (int h = 0; h < 2; h++) {
                const uint32_t hb = (uint32_t)h << 5;
                uint32_t a[4][4], b[2][4];
#pragma unroll
                for (int mt = 0; mt < 4; mt++) ldm_x4(a[mt], stb + (offA[mt] ^ hb));
#pragma unroll
                for (int p = 0; p < 2; p++)    ldm_x4(b[p],  stb + (offB[p]  ^ hb));
#pragma unroll
                for (int p = 0; p < 2; p++)
#pragma unroll
                    for (int q = 0; q < 2; q++)
#pragma unroll
                        for (int mt = 0; mt < 4; mt++)
                            mma_f16(acc[mt][2 * p + q], a[mt], b[p][2 * q], b[p][2 * q + 1]);
            }
            cslot = (cslot + 1 == 6) ? 0 : cslot + 1;
        }
    }
#undef LOAD_SLOT
    __syncthreads();   // release ring smem for epilogue

    // ---------------- epilogue ----------------
    float* base = (float*)smal;
    float* sInv = PAIRED ? (float*)(smal + 67584) : base;   // [128]
    float* sMi  = sInv + 128;
    float* sU   = sMi + 128;
    float* sC   = sU + 128;

    if constexpr (FOLD) {
        if (tid < 128) {
            size_t grow;
            if constexpr (PAIRED)
                grow = (tid < 64) ? (size_t)(row0 + tid)
                                  : (size_t)B_ROWS + row0 + (tid - 64);
            else
                grow = (size_t)(row0 + tid);
            const float4* sp = statsIn + grow * 8;
            float ss = 0.f, sq = 0.f;
#pragma unroll
            for (int i = 0; i < 8; i++) {
                float4 v = sp[i];
                ss += v.x + v.z;
                sq += v.y + v.w;
            }
            float m   = ss * (1.0f / 512.0f);
            float var = fmaxf(sq * (1.0f / 512.0f) - m * m, 0.0f);
            float inv = rsqrtf(var + 1e-6f);
            sInv[tid] = inv;
            sMi[tid]  = m * inv;
        }
    }
    if (tid >= 128) {
        sU[tid - 128] = FOLD ? uvec[col0 + tid - 128] : 0.0f;
        sC[tid - 128] = cvec[col0 + tid - 128];
    }
    __syncthreads();

#pragma unroll
    for (int mt = 0; mt < 4; mt++) {
#pragma unroll
        for (int dp = 0; dp < 2; dp++) {
            const int rl   = wm * 64 + mt * 16 + dp * 8 + (lane >> 2);
            const float inv = FOLD ? sInv[rl] : 1.0f;
            const float mi  = FOLD ? sMi[rl]  : 0.0f;
            float gs = 0.f, gq = 0.f;
            size_t grow = (size_t)(row0 + rl);   // used by ACT path only
#pragma unroll
            for (int nt = 0; nt < 4; nt++) {
                const int cl = wn * 32 + nt * 8 + 2 * (lane & 3);
                float z0 = inv * acc[mt][nt][2 * dp + 0] - mi * sU[cl]     + sC[cl];
                float z1 = inv * acc[mt][nt][2 * dp + 1] - mi * sU[cl + 1] + sC[cl + 1];
                if constexpr (PAIRED) {
                    // stage phi in [row][i][comp] layout: conflict-free comp gathers
                    base[rl * 132 + (cl & 31) * 4 + (cl >> 5)]       = z0;
                    base[rl * 132 + ((cl & 31) + 1) * 4 + (cl >> 5)] = z1;
                } else if constexpr (ACT) {
                    float g0 = gelu_f(z0), g1 = gelu_f(z1);
                    gs += g0 + g1;
                    gq += g0 * g0 + g1 * g1;
                    __half2 hv = __floats2half2_rn(g0, g1);
                    *(__half2*)(Oact + grow * 512 + col0 + cl) = hv;
                }
            }
            if constexpr (ACT && !PAIRED) {
                gs += __shfl_xor_sync(0xffffffffu, gs, 1);
                gs += __shfl_xor_sync(0xffffffffu, gs, 2);
                gq += __shfl_xor_sync(0xffffffffu, gq, 1);
                gq += __shfl_xor_sync(0xffffffffu, gq, 2);
                if ((lane & 3) == 0)
                    statsOut[grow * 16 + (size_t)(colcta * 4 + wn)] = make_float2(gs, gq);
            }
        }
    }

    if constexpr (PAIRED) {
        __syncthreads();
        // one thread per (pair row r, component comp); 4 comps = lanes sharing r
        const int r    = tid >> 2;       // 0..63
        const int comp = tid & 3;
        const float* xs  = base + r * 132 + comp;
        const float* gs_ = base + (64 + r) * 132 + comp;
        float X[32], Y[32];
#pragma unroll
        for (int i = 0; i < 32; i++) {
            float xv = xs[i * 4];
            X[i] = xv;
            Y[i] = fmaxf(xv, gs_[i * 4]);
        }
#define BSTEP(V, KK, J)                                                   \
        _Pragma("unroll")                                                 \
        for (int i = 0; i < 32; i++) {                                    \
            int l = i ^ (J);                                              \
            if (l > i) {                                                  \
                bool up = ((i & (KK)) == 0);                              \
                float a_ = V[i], b_ = V[l];                               \
                float lo = fminf(a_, b_), hi = fmaxf(a_, b_);             \
                V[i] = up ? lo : hi;  V[l] = up ? hi : lo;                \
            }                                                             \
        }
        BSTEP(X,2,1) BSTEP(X,4,2) BSTEP(X,4,1) BSTEP(X,8,4) BSTEP(X,8,2) BSTEP(X,8,1)
        BSTEP(X,16,8) BSTEP(X,16,4) BSTEP(X,16,2) BSTEP(X,16,1)
        BSTEP(X,32,16) BSTEP(X,32,8) BSTEP(X,32,4) BSTEP(X,32,2) BSTEP(X,32,1)
        BSTEP(Y,2,1) BSTEP(Y,4,2) BSTEP(Y,4,1) BSTEP(Y,8,4) BSTEP(Y,8,2) BSTEP(Y,8,1)
        BSTEP(Y,16,8) BSTEP(Y,16,4) BSTEP(Y,16,2) BSTEP(Y,16,1)
        BSTEP(Y,32,16) BSTEP(Y,32,8) BSTEP(Y,32,4) BSTEP(Y,32,2) BSTEP(Y,32,1)
#undef BSTEP
        float s = Y[0] - X[0];
        float prev = Y[0];
#pragma unroll
        for (int j = 1; j < 32; j++) {
            s += Y[j] - fmaxf(X[j], prev);
            prev = Y[j];
        }
        float ssum = s, smax = s;
        ssum += __shfl_xor_sync(0xffffffffu, ssum, 1);
        smax  = fmaxf(smax, __shfl_xor_sync(0xffffffffu, smax, 1));
        ssum += __shfl_xor_sync(0xffffffffu, ssum, 2);
        smax  = fmaxf(smax, __shfl_xor_sync(0xffffffffu, smax, 2));
        if (comp == 0)
            iqePart[(size_t)(row0 + r) * 4 + colcta] = make_float2(ssum, smax);
    }
}

// ---------------- fused input conversion + all prep ----------------
#define CONV_BLOCKS 65536
#define PREP_BLOCKS 3968

static __device__ __forceinline__ void wprep_body(
    int i, const float* __restrict__ W, int K, const float* __restrict__ s,
    __half* __restrict__ wt)
{
    int n = i / K, k = i % K;
    float v = W[(size_t)k * 512 + n];
    if (s) v *= s[k];
    wt[i] = __float2half_rn(v);
}

static __device__ __forceinline__ void ucprep_body(
    int blk, int tid, const float* __restrict__ W, const float* __restrict__ s,
    const float* __restrict__ t, const float* __restrict__ beta,
    float* __restrict__ u, float* __restrict__ c,
    float* __restrict__ ru, float* __restrict__ rc)
{
    const int half = tid >> 7;
    const int tt   = tid & 127;
    const int n    = blk * 2 + half;
    float us = 0.f, cs = 0.f;
    for (int k = tt; k < 512; k += 128) {
        float w = W[(size_t)k * 512 + n];
        us += s[k] * w;
        cs += t[k] * w;
    }
    ru[tid] = us; rc[tid] = cs;
    __syncthreads();
    for (int off = 64; off; off >>= 1) {
        if (tt < off) {
            ru[tid] += ru[tid + off];
            rc[tid] += rc[tid + off];
        }
        __syncthreads();
    }
    if (tt == 0) { u[n] = ru[tid]; c[n] = rc[tid] + beta[n]; }
}

__global__ __launch_bounds__(256)
void conv_prep(const float* __restrict__ obs, const float* __restrict__ gls,
               __half* __restrict__ a0out,
               const float* __restrict__ W0, const float* __restrict__ W1,
               const float* __restrict__ W2, const float* __restrict__ W3,
               const float* __restrict__ l0s, const float* __restrict__ l0b,
               const float* __restrict__ b1,
               const float* __restrict__ l1s, const float* __restrict__ l1b,
               const float* __restrict__ b2,
               const float* __restrict__ l2s, const float* __restrict__ l2b,
               const float* __restrict__ b3,
               __half* __restrict__ wt0, __half* __restrict__ wt1,
               __half* __restrict__ wt2, __half* __restrict__ wt3,
               float* __restrict__ u1, float* __restrict__ c1,
               float* __restrict__ u2, float* __restrict__ c2,
               float* __restrict__ u3, float* __restrict__ c3)
{
    __shared__ float ru[256], rc[256];
    const int tid = threadIdx.x;
    if (blockIdx.x < CONV_BLOCKS) {
        size_t i = (size_t)blockIdx.x * 256 + tid;
        float v = (i < (size_t)B_ROWS * 64) ? obs[i] : gls[i - (size_t)B_ROWS * 64];
        a0out[i] = __float2half_rn(v);
        return;
    }
    const int b = blockIdx.x - CONV_BLOCKS;
    if (b < 128) {
        wprep_body(b * 256 + tid, W0, 64, nullptr, wt0);
    } else if (b < 1152) {
        wprep_body((b - 128) * 256 + tid, W1, 512, l0s, wt1);
    } else if (b < 2176) {
        wprep_body((b - 1152) * 256 + tid, W2, 512, l1s, wt2);
    } else if (b < 3200) {
        wprep_body((b - 2176) * 256 + tid, W3, 512, l2s, wt3);
    } else if (b < 3456) {
        ucprep_body(b - 3200, tid, W1, l0s, l0b, b1, u1, c1, ru, rc);
    } else if (b < 3712) {
        ucprep_body(b - 3456, tid, W2, l1s, l1b, b2, u2, c2, ru, rc);
    } else {
        ucprep_body(b - 3712, tid, W3, l2s, l2b, b3, u3, c3, ru, rc);
    }
}

// ---------------- final IQE combine ----------------
__global__ __launch_bounds__(256)
void iqe_combine(const float2* __restrict__ part, const float* __restrict__ alpha_p,
                 float* __restrict__ out)
{
    int r = blockIdx.x * 256 + threadIdx.x;
    if (r >= B_ROWS) return;
    float2 p0 = part[(size_t)r * 4 + 0];
    float2 p1 = part[(size_t)r * 4 + 1];
    float2 p2 = part[(size_t)r * 4 + 2];
    float2 p3 = part[(size_t)r * 4 + 3];
    float ssum = (p0.x + p1.x) + (p2.x + p3.x);
    float smax = fmaxf(fmaxf(p0.y, p1.y), fmaxf(p2.y, p3.y));
    float a = 1.0f / (1.0f + expf(-alpha_p[0]));
    out[r] = a * (ssum * (1.0f / 16.0f)) + (1.0f - a) * smax;
}

// ---------------- launch ----------------
extern "C" void kernel_launch(void* const* d_in, const int* in_sizes, int n_in,
                              void* d_out, int out_size)
{
    const float* obs   = (const float*)d_in[0];
    const float* gls   = (const float*)d_in[1];
    const float* W0    = (const float*)d_in[2];
    const float* b0    = (const float*)d_in[3];
    const float* l0s   = (const float*)d_in[4];
    const float* l0b   = (const float*)d_in[5];
    const float* W1    = (const float*)d_in[6];
    const float* b1    = (const float*)d_in[7];
    const float* l1s   = (const float*)d_in[8];
    const float* l1b   = (const float*)d_in[9];
    const float* W2    = (const float*)d_in[10];
    const float* b2    = (const float*)d_in[11];
    const float* l2s   = (const float*)d_in[12];
    const float* l2b   = (const float*)d_in[13];
    const float* W3    = (const float*)d_in[14];
    const float* b3    = (const float*)d_in[15];
    const float* alpha = (const float*)d_in[16];

    __half *a0, *actA, *actB, *wt0, *wt1, *wt2, *wt3;
    float *u1, *c1, *u2, *c2, *u3, *c3;
    float4 *stA, *stB;
    float2 *part;
    cudaGetSymbolAddress((void**)&a0,   g_a0);
    cudaGetSymbolAddress((void**)&actA, g_actA);
    cudaGetSymbolAddress((void**)&actB, g_actB);
    cudaGetSymbolAddress((void**)&wt0,  g_wt0);
    cudaGetSymbolAddress((void**)&wt1,  g_wt1);
    cudaGetSymbolAddress((void**)&wt2,  g_wt2);
    cudaGetSymbolAddress((void**)&wt3,  g_wt3);
    cudaGetSymbolAddress((void**)&u1,   g_u1);
    cudaGetSymbolAddress((void**)&c1,   g_c1);
    cudaGetSymbolAddress((void**)&u2,   g_u2);
    cudaGetSymbolAddress((void**)&c2,   g_c2);
    cudaGetSymbolAddress((void**)&u3,   g_u3);
    cudaGetSymbolAddress((void**)&c3,   g_c3);
    cudaGetSymbolAddress((void**)&stA,  g_statA);
    cudaGetSymbolAddress((void**)&stB,  g_statB);
    cudaGetSymbolAddress((void**)&part, g_iqePart);

    cudaFuncSetAttribute(gemm_kernel<64,  true,  false, false>, cudaFuncAttributeMaxDynamicSharedMemorySize, SMEM_BYTES);
    cudaFuncSetAttribute(gemm_kernel<512, true,  true,  false>, cudaFuncAttributeMaxDynamicSharedMemorySize, SMEM_BYTES);
    cudaFuncSetAttribute(gemm_kernel<512, false, true,  true >, cudaFuncAttributeMaxDynamicSharedMemorySize, SMEM_BYTES);

    dim3 blk(256);
    dim3 grid((TOT_ROWS / 128) * 4);           // 8192

    // launch 0: input conversion + ALL weight/fold prep
    conv_prep<<<CONV_BLOCKS + PREP_BLOCKS, 256>>>(
        obs, gls, a0, W0, W1, W2, W3,
        l0s, l0b, b1, l1s, l1b, b2, l2s, l2b, b3,
        wt0, wt1, wt2, wt3, u1, c1, u2, c2, u3, c3);

    // launch 1: L0 (no fold), gelu + stats -> statA
    gemm_kernel<64, true, false, false><<<grid, blk, SMEM_BYTES>>>(
        a0, wt0, nullptr, b0, nullptr, (float2*)stA, actA, nullptr);

    // launch 2: L1, fold ln0
    gemm_kernel<512, true, true, false><<<grid, blk, SMEM_BYTES>>>(
        actA, wt1, u1, c1, stA, (float2*)stB, actB, nullptr);

    // launch 3 (ncu capture slot): L2, fold ln1
    gemm_kernel<512, true, true, false><<<grid, blk, SMEM_BYTES>>>(
        actB, wt2, u2, c2, stB, (float2*)stA, actA, nullptr);

    // launch 4: L3, fold ln2, paired rows, fused IQE -> partials
    gemm_kernel<512, false, true, true><<<(B_ROWS / 64) * 4, blk, SMEM_BYTES>>>(
        actA, wt3, u3, c3, stA, nullptr, nullptr, part);

    // launch 5
    iqe_combine<<<(B_ROWS + 255) / 256, 256>>>(part, alpha, (float*)d_out);
}